// round 1
// baseline (speedup 1.0000x reference)
#include <cuda_runtime.h>
#include <math.h>

#define NN 50000
#define NE 100000
#define NRL 500
#define NB 64
#define FF 768
#define FV 2304
#define ENC_NEG_INF 0x007FFFFFu

// ---------------- scratch (static device memory; no allocations) ------------
__device__ float g_big0[NN * FF];   // hl, then gl
__device__ float g_big1[NN * FF];   // hs, then gr
__device__ float g_big2[NN * FF];   // inj_ent, then msg-accum / ent_emb
__device__ float g_hq[NB * FF];
__device__ float g_ge[NRL * FF];
__device__ float g_logit[NE];
__device__ unsigned g_nmax[NN];
__device__ float g_nsum[NN];
__device__ float g_gate[NN];
__device__ unsigned g_gmax[NB];
__device__ float g_gsum[NB];
__device__ float g_pool[NB * FF];

// ---------------- helpers ----------------------------------------------------
__device__ __forceinline__ float lrelu(float x) { return x > 0.f ? x : 0.2f * x; }

__device__ __forceinline__ unsigned f2ord(float f) {
    unsigned u = __float_as_uint(f);
    return (u & 0x80000000u) ? ~u : (u | 0x80000000u);
}
__device__ __forceinline__ float ord2f(unsigned u) {
    return (u & 0x80000000u) ? __uint_as_float(u & 0x7FFFFFFFu) : __uint_as_float(~u);
}

__device__ __forceinline__ void fma2(unsigned long long& d, unsigned long long a,
                                     unsigned long long b) {
    asm("fma.rn.f32x2 %0, %1, %2, %0;" : "+l"(d) : "l"(a), "l"(b));
}
__device__ __forceinline__ unsigned long long pack2(float x, float y) {
    unsigned long long r;
    asm("mov.b64 %0, {%1, %2};" : "=l"(r) : "f"(x), "f"(y));
    return r;
}

// ---------------- SGEMM: C[M,N] = A[M,K] * B[K,N], row-major, fp32 -----------
// BM=128, BN=128, BK=16, 256 threads, 8x8 microtile, packed f32x2 FMAs,
// double-buffered smem. N, K must be multiples of 128/16; M is guarded.
#define BM 128
#define BN 128
#define BK 16

__global__ __launch_bounds__(256, 2) void sgemm(const float* __restrict__ A,
                                                const float* __restrict__ B,
                                                float* __restrict__ C,
                                                int M, int N, int K) {
    __shared__ __align__(16) float As[2][BK][BM];
    __shared__ __align__(16) float Bs[2][BK][BN];

    const int tid = threadIdx.x;
    const int row0 = blockIdx.x * BM;
    const int col0 = blockIdx.y * BN;

    const int arow = tid >> 2;          // 0..63
    const int acol = (tid & 3) << 2;    // 0,4,8,12
    const int brow = tid >> 5;          // 0..7
    const int bcol = (tid & 31) << 2;   // 0..124

    const int tm = (tid >> 4) << 3;
    const int tn = (tid & 15) << 3;

    unsigned long long acc[8][4];
#pragma unroll
    for (int i = 0; i < 8; i++)
#pragma unroll
        for (int j = 0; j < 4; j++) acc[i][j] = 0ull;

    float4 ra0, ra1, rb0, rb1;

    auto ldg = [&](int kt) {
        const int k = kt * BK;
        const int r0 = row0 + arow;
        const int r1 = r0 + 64;
        const float4 z = make_float4(0.f, 0.f, 0.f, 0.f);
        ra0 = (r0 < M) ? *(const float4*)(A + (size_t)r0 * K + k + acol) : z;
        ra1 = (r1 < M) ? *(const float4*)(A + (size_t)r1 * K + k + acol) : z;
        rb0 = *(const float4*)(B + (size_t)(k + brow) * N + col0 + bcol);
        rb1 = *(const float4*)(B + (size_t)(k + brow + 8) * N + col0 + bcol);
    };
    auto sts = [&](int buf) {
        As[buf][acol + 0][arow] = ra0.x;
        As[buf][acol + 1][arow] = ra0.y;
        As[buf][acol + 2][arow] = ra0.z;
        As[buf][acol + 3][arow] = ra0.w;
        As[buf][acol + 0][arow + 64] = ra1.x;
        As[buf][acol + 1][arow + 64] = ra1.y;
        As[buf][acol + 2][arow + 64] = ra1.z;
        As[buf][acol + 3][arow + 64] = ra1.w;
        *(float4*)&Bs[buf][brow][bcol] = rb0;
        *(float4*)&Bs[buf][brow + 8][bcol] = rb1;
    };

    ldg(0);
    sts(0);
    __syncthreads();

    const int nk = K / BK;
    for (int kt = 0; kt < nk; kt++) {
        const int buf = kt & 1;
        if (kt + 1 < nk) ldg(kt + 1);
#pragma unroll
        for (int kk = 0; kk < BK; kk++) {
            float4 a0 = *(float4*)&As[buf][kk][tm];
            float4 a1 = *(float4*)&As[buf][kk][tm + 4];
            ulonglong2 b0 = *(ulonglong2*)&Bs[buf][kk][tn];
            ulonglong2 b1 = *(ulonglong2*)&Bs[buf][kk][tn + 4];
            float av[8] = {a0.x, a0.y, a0.z, a0.w, a1.x, a1.y, a1.z, a1.w};
#pragma unroll
            for (int i = 0; i < 8; i++) {
                unsigned long long ad = pack2(av[i], av[i]);
                fma2(acc[i][0], ad, b0.x);
                fma2(acc[i][1], ad, b0.y);
                fma2(acc[i][2], ad, b1.x);
                fma2(acc[i][3], ad, b1.y);
            }
        }
        if (kt + 1 < nk) sts(buf ^ 1);
        __syncthreads();
    }

#pragma unroll
    for (int i = 0; i < 8; i++) {
        const int r = row0 + tm + i;
        if (r < M) {
            float2 p0 = *(float2*)&acc[i][0];
            float2 p1 = *(float2*)&acc[i][1];
            float2 p2 = *(float2*)&acc[i][2];
            float2 p3 = *(float2*)&acc[i][3];
            float4 o0 = make_float4(p0.x, p0.y, p1.x, p1.y);
            float4 o1 = make_float4(p2.x, p2.y, p3.x, p3.y);
            *(float4*)(C + (size_t)r * N + col0 + tn) = o0;
            *(float4*)(C + (size_t)r * N + col0 + tn + 4) = o1;
        }
    }
}

// ---------------- per-node injection attention (one warp per node) -----------
__global__ void combine_kernel(const float* __restrict__ hl,
                               const float* __restrict__ hs,
                               const float* __restrict__ hqg,
                               const int* __restrict__ batch,
                               const float* __restrict__ att,
                               float* __restrict__ inj) {
    int warp = (blockIdx.x * blockDim.x + threadIdx.x) >> 5;
    int lane = threadIdx.x & 31;
    if (warp >= NN) return;
    const float4* phl = (const float4*)(hl + (size_t)warp * FF);
    const float4* phs = (const float4*)(hs + (size_t)warp * FF);
    const float4* phq = (const float4*)(hqg + (size_t)batch[warp] * FF);
    const float4* pat = (const float4*)att;

    float4 vq[6], vs[6];
    float sq = 0.f, ss = 0.f;
#pragma unroll
    for (int i = 0; i < 6; i++) {
        int j = lane + i * 32;
        float4 l = phl[j];
        vq[i] = phq[j];
        vs[i] = phs[j];
        float4 a = pat[j];
        sq += lrelu(l.x + vq[i].x) * a.x + lrelu(l.y + vq[i].y) * a.y +
              lrelu(l.z + vq[i].z) * a.z + lrelu(l.w + vq[i].w) * a.w;
        ss += lrelu(l.x + vs[i].x) * a.x + lrelu(l.y + vs[i].y) * a.y +
              lrelu(l.z + vs[i].z) * a.z + lrelu(l.w + vs[i].w) * a.w;
    }
#pragma unroll
    for (int o = 16; o > 0; o >>= 1) {
        sq += __shfl_xor_sync(0xFFFFFFFFu, sq, o);
        ss += __shfl_xor_sync(0xFFFFFFFFu, ss, o);
    }
    float m = fmaxf(sq, ss);
    float e0 = expf(sq - m), e1 = expf(ss - m);
    float inv = 1.f / (e0 + e1);
    float a0 = e0 * inv, a1 = e1 * inv;

    float4* pout = (float4*)(inj + (size_t)warp * FF);
#pragma unroll
    for (int i = 0; i < 6; i++) {
        int j = lane + i * 32;
        float4 o;
        o.x = a0 * vq[i].x + a1 * vs[i].x;
        o.y = a0 * vq[i].y + a1 * vs[i].y;
        o.z = a0 * vq[i].z + a1 * vs[i].z;
        o.w = a0 * vq[i].w + a1 * vs[i].w;
        pout[j] = o;
    }
}

// ---------------- edge logits (one warp per edge) -----------------------------
__global__ void edge_logit_kernel(const float* __restrict__ gl,
                                  const float* __restrict__ gr,
                                  const float* __restrict__ ge,
                                  const int* __restrict__ xcoo,
                                  const float* __restrict__ att,
                                  float* __restrict__ logit) {
    int warp = (blockIdx.x * blockDim.x + threadIdx.x) >> 5;
    int lane = threadIdx.x & 31;
    if (warp >= NE) return;
    int src = xcoo[warp * 3 + 0];
    int rel = xcoo[warp * 3 + 1];
    int tgt = xcoo[warp * 3 + 2];
    const float4* pt = (const float4*)(gl + (size_t)tgt * FF);
    const float4* ps = (const float4*)(gr + (size_t)src * FF);
    const float4* pe = (const float4*)(ge + (size_t)rel * FF);
    const float4* pa = (const float4*)att;
    float s = 0.f;
#pragma unroll
    for (int i = 0; i < 6; i++) {
        int j = lane + i * 32;
        float4 t = pt[j], r = ps[j], e = pe[j], a = pa[j];
        s += lrelu(t.x + r.x + e.x) * a.x + lrelu(t.y + r.y + e.y) * a.y +
             lrelu(t.z + r.z + e.z) * a.z + lrelu(t.w + r.w + e.w) * a.w;
    }
#pragma unroll
    for (int o = 16; o > 0; o >>= 1) s += __shfl_xor_sync(0xFFFFFFFFu, s, o);
    if (lane == 0) logit[warp] = s;
}

// ---------------- segment softmax over edges (tgt) ----------------------------
__global__ void edge_max_kernel(const int* __restrict__ xcoo,
                                const float* __restrict__ logit,
                                unsigned* __restrict__ nmax) {
    int e = blockIdx.x * blockDim.x + threadIdx.x;
    if (e < NE) atomicMax(&nmax[xcoo[e * 3 + 2]], f2ord(logit[e]));
}

__global__ void edge_sum_kernel(const int* __restrict__ xcoo,
                                const float* __restrict__ logit,
                                const unsigned* __restrict__ nmax,
                                float* __restrict__ nsum) {
    int e = blockIdx.x * blockDim.x + threadIdx.x;
    if (e < NE) {
        int t = xcoo[e * 3 + 2];
        atomicAdd(&nsum[t], expf(logit[e] - ord2f(nmax[t])));
    }
}

// ---------------- message scatter (one warp per edge) ------------------------
__global__ void message_kernel(const int* __restrict__ xcoo,
                               const float* __restrict__ logit,
                               const unsigned* __restrict__ nmax,
                               const float* __restrict__ nsum,
                               const float* __restrict__ gr,
                               float* __restrict__ acc) {
    int warp = (blockIdx.x * blockDim.x + threadIdx.x) >> 5;
    int lane = threadIdx.x & 31;
    if (warp >= NE) return;
    int src = xcoo[warp * 3 + 0];
    int tgt = xcoo[warp * 3 + 2];
    float alpha = expf(logit[warp] - ord2f(nmax[tgt])) / (nsum[tgt] + 1e-16f);
    const float4* ps = (const float4*)(gr + (size_t)src * FF);
    float* pd = acc + (size_t)tgt * FF;
#pragma unroll
    for (int i = 0; i < 6; i++) {
        int j = lane + i * 32;
        float4 v = ps[j];
        atomicAdd(pd + j * 4 + 0, alpha * v.x);
        atomicAdd(pd + j * 4 + 1, alpha * v.y);
        atomicAdd(pd + j * 4 + 2, alpha * v.z);
        atomicAdd(pd + j * 4 + 3, alpha * v.w);
    }
}

// ---------------- elu + gate dot (one warp per node, in-place) ----------------
__global__ void node_post_kernel(float* __restrict__ emb,
                                 const float* __restrict__ gate_W,
                                 const float* __restrict__ gate_b,
                                 float* __restrict__ gate) {
    int warp = (blockIdx.x * blockDim.x + threadIdx.x) >> 5;
    int lane = threadIdx.x & 31;
    if (warp >= NN) return;
    float4* p = (float4*)(emb + (size_t)warp * FF);
    const float4* pw = (const float4*)gate_W;
    float s = 0.f;
#pragma unroll
    for (int i = 0; i < 6; i++) {
        int j = lane + i * 32;
        float4 v = p[j];
        v.x = v.x > 0.f ? v.x : expm1f(v.x);
        v.y = v.y > 0.f ? v.y : expm1f(v.y);
        v.z = v.z > 0.f ? v.z : expm1f(v.z);
        v.w = v.w > 0.f ? v.w : expm1f(v.w);
        p[j] = v;
        float4 w = pw[j];
        s += v.x * w.x + v.y * w.y + v.z * w.z + v.w * w.w;
    }
#pragma unroll
    for (int o = 16; o > 0; o >>= 1) s += __shfl_xor_sync(0xFFFFFFFFu, s, o);
    if (lane == 0) gate[warp] = s + gate_b[0];
}

// ---------------- graph softmax over nodes ------------------------------------
__global__ void graph_max_kernel(const float* __restrict__ gate,
                                 const int* __restrict__ batch,
                                 unsigned* __restrict__ gmax) {
    int n = blockIdx.x * blockDim.x + threadIdx.x;
    if (n < NN) atomicMax(&gmax[batch[n]], f2ord(gate[n]));
}

__global__ void graph_sum_kernel(float* __restrict__ gate,
                                 const int* __restrict__ batch,
                                 const unsigned* __restrict__ gmax,
                                 float* __restrict__ gsum) {
    int n = blockIdx.x * blockDim.x + threadIdx.x;
    if (n < NN) {
        float ex = expf(gate[n] - ord2f(gmax[batch[n]]));
        gate[n] = ex;
        atomicAdd(&gsum[batch[n]], ex);
    }
}

__global__ void gscale_kernel(float* __restrict__ gate,
                              const int* __restrict__ batch,
                              const float* __restrict__ gsum) {
    int n = blockIdx.x * blockDim.x + threadIdx.x;
    if (n < NN) gate[n] = gate[n] / (gsum[batch[n]] + 1e-16f);
}

// ---------------- pooled = segment_sum(g * emb, batch) (batch is sorted) ------
__global__ void pool_kernel(const float* __restrict__ emb,
                            const float* __restrict__ g,
                            const int* __restrict__ batch,
                            float* __restrict__ pool) {
    int f = blockIdx.y * 256 + threadIdx.x;  // 0..767
    int n0 = blockIdx.x * 1024;
    int n1 = min(n0 + 1024, NN);
    float acc = 0.f;
    int curb = batch[n0];
    for (int n = n0; n < n1; n++) {
        int b = batch[n];
        if (b != curb) {
            atomicAdd(&pool[(size_t)curb * FF + f], acc);
            acc = 0.f;
            curb = b;
        }
        acc += g[n] * emb[(size_t)n * FF + f];
    }
    atomicAdd(&pool[(size_t)curb * FF + f], acc);
}

// ---------------- init kernels ------------------------------------------------
__global__ void init_node_kernel(unsigned* nmax, float* nsum, unsigned* gmax,
                                 float* gsum, float* pool) {
    int i = blockIdx.x * blockDim.x + threadIdx.x;
    if (i < NN) {
        nmax[i] = ENC_NEG_INF;
        nsum[i] = 0.f;
    }
    if (i < NB) {
        gmax[i] = ENC_NEG_INF;
        gsum[i] = 0.f;
    }
    if (i < NB * FF) pool[i] = 0.f;
}

__global__ void zero_big_kernel(float4* p, int n4) {
    int i = blockIdx.x * blockDim.x + threadIdx.x;
    if (i < n4) p[i] = make_float4(0.f, 0.f, 0.f, 0.f);
}

// ---------------- launcher ------------------------------------------------------
extern "C" void kernel_launch(void* const* d_in, const int* in_sizes, int n_in,
                              void* d_out, int out_size) {
    const float* queries = (const float*)d_in[0];
    const float* entities = (const float*)d_in[1];
    const float* relations = (const float*)d_in[2];
    const int* xcoo = (const int*)d_in[3];
    const int* batch = (const int*)d_in[4];
    const float* inj_Wl = (const float*)d_in[5];
    const float* inj_Wr = (const float*)d_in[6];
    const float* inj_att = (const float*)d_in[7];
    const float* enc_Wl = (const float*)d_in[8];
    const float* enc_Wr = (const float*)d_in[9];
    const float* enc_We = (const float*)d_in[10];
    const float* enc_att = (const float*)d_in[11];
    /* d_in[12] enc_Wrel: dead code in reference */
    const float* gate_W = (const float*)d_in[13];
    const float* gate_b = (const float*)d_in[14];
    const float* vt_W = (const float*)d_in[15];
    float* out = (float*)d_out;

    float *big0, *big1, *big2, *hq, *ge, *logit, *nsum, *gate, *gsum, *pool;
    unsigned *nmax, *gmax;
    cudaGetSymbolAddress((void**)&big0, g_big0);
    cudaGetSymbolAddress((void**)&big1, g_big1);
    cudaGetSymbolAddress((void**)&big2, g_big2);
    cudaGetSymbolAddress((void**)&hq, g_hq);
    cudaGetSymbolAddress((void**)&ge, g_ge);
    cudaGetSymbolAddress((void**)&logit, g_logit);
    cudaGetSymbolAddress((void**)&nmax, g_nmax);
    cudaGetSymbolAddress((void**)&nsum, g_nsum);
    cudaGetSymbolAddress((void**)&gate, g_gate);
    cudaGetSymbolAddress((void**)&gmax, g_gmax);
    cudaGetSymbolAddress((void**)&gsum, g_gsum);
    cudaGetSymbolAddress((void**)&pool, g_pool);

    const dim3 gridEnt((NN + BM - 1) / BM, FF / BN);  // (391, 6)

    // injection layer GEMMs
    sgemm<<<gridEnt, 256>>>(entities, inj_Wl, big0, NN, FF, FF);   // hl
    sgemm<<<gridEnt, 256>>>(entities, inj_Wr, big1, NN, FF, FF);   // hs
    sgemm<<<dim3(1, FF / BN), 256>>>(queries, inj_Wr, hq, NB, FF, FF);

    combine_kernel<<<(NN * 32 + 255) / 256, 256>>>(big0, big1, hq, batch, inj_att, big2);

    // encoder GEMMs
    sgemm<<<gridEnt, 256>>>(big2, enc_Wl, big0, NN, FF, FF);       // gl
    sgemm<<<gridEnt, 256>>>(big2, enc_Wr, big1, NN, FF, FF);       // gr
    sgemm<<<dim3((NRL + BM - 1) / BM, FF / BN), 256>>>(relations, enc_We, ge, NRL, FF, FF);

    edge_logit_kernel<<<(NE * 32 + 255) / 256, 256>>>(big0, big1, ge, xcoo, enc_att, logit);

    // big2 (inj) no longer needed -> becomes the message accumulator
    init_node_kernel<<<(NN + 255) / 256, 256>>>(nmax, nsum, gmax, gsum, pool);
    zero_big_kernel<<<(NN * FF / 4 + 255) / 256, 256>>>((float4*)big2, NN * FF / 4);

    edge_max_kernel<<<(NE + 255) / 256, 256>>>(xcoo, logit, nmax);
    edge_sum_kernel<<<(NE + 255) / 256, 256>>>(xcoo, logit, nmax, nsum);
    message_kernel<<<(NE * 32 + 255) / 256, 256>>>(xcoo, logit, nmax, nsum, big1, big2);

    node_post_kernel<<<(NN * 32 + 255) / 256, 256>>>(big2, gate_W, gate_b, gate);

    graph_max_kernel<<<(NN + 255) / 256, 256>>>(gate, batch, gmax);
    graph_sum_kernel<<<(NN + 255) / 256, 256>>>(gate, batch, gmax, gsum);
    gscale_kernel<<<(NN + 255) / 256, 256>>>(gate, batch, gsum);

    pool_kernel<<<dim3((NN + 1023) / 1024, 3), 256>>>(big2, gate, batch, pool);

    // out = pooled @ vt_W  [64,768]x[768,2304]
    sgemm<<<dim3(1, FV / BN), 256>>>(pool, vt_W, out, NB, FV, FF);
}

// round 3
// speedup vs baseline: 1.8233x; 1.8233x over previous
#include <cuda_runtime.h>
#include <cuda_bf16.h>
#include <math.h>
#include <stdint.h>

#define NN 50000
#define NE 100000
#define NRL 500
#define NB 64
#define FF 768
#define FV 2304
#define ENC_NEG_INF 0x007FFFFFu

// ---------------- scratch (static device memory; no allocations) ------------
__device__ __align__(16) float g_big0[NN * FF];   // hl, then gl
__device__ __align__(16) float g_big1[NN * FF];   // hs, then gr
__device__ __align__(16) float g_big2[NN * FF];   // msg-accum / ent_emb
__device__ __align__(16) __nv_bfloat16 g_Ahb[NN * FF];   // bf16-hi plane of A
__device__ __align__(16) __nv_bfloat16 g_Alb[NN * FF];   // bf16-lo plane of A
__device__ __align__(16) __nv_bfloat16 g_Bth[2 * FF * FF];  // [1536,768] W^T hi
__device__ __align__(16) __nv_bfloat16 g_Btl[2 * FF * FF];  // [1536,768] W^T lo
__device__ float g_hq[NB * FF];
__device__ float g_ge[NRL * FF];
__device__ float g_logit[NE];
__device__ unsigned g_nmax[NN];
__device__ float g_nsum[NN];
__device__ float g_gate[NN];
__device__ unsigned g_gmax[NB];
__device__ float g_gsum[NB];
__device__ float g_pool[NB * FF];

// ---------------- helpers ----------------------------------------------------
__device__ __forceinline__ float lrelu(float x) { return x > 0.f ? x : 0.2f * x; }

__device__ __forceinline__ unsigned f2ord(float f) {
    unsigned u = __float_as_uint(f);
    return (u & 0x80000000u) ? ~u : (u | 0x80000000u);
}
__device__ __forceinline__ float ord2f(unsigned u) {
    return (u & 0x80000000u) ? __uint_as_float(u & 0x7FFFFFFFu) : __uint_as_float(~u);
}

__device__ __forceinline__ void fma2(unsigned long long& d, unsigned long long a,
                                     unsigned long long b) {
    asm("fma.rn.f32x2 %0, %1, %2, %0;" : "+l"(d) : "l"(a), "l"(b));
}
__device__ __forceinline__ unsigned long long pack2(float x, float y) {
    unsigned long long r;
    asm("mov.b64 %0, {%1, %2};" : "=l"(r) : "f"(x), "f"(y));
    return r;
}

__device__ __forceinline__ void split_bf(float v, __nv_bfloat16& h, __nv_bfloat16& l) {
    h = __float2bfloat16_rn(v);
    l = __float2bfloat16_rn(v - __bfloat162float(h));
}
__device__ __forceinline__ unsigned cat_bf(__nv_bfloat16 a, __nv_bfloat16 b) {
    return (unsigned)__bfloat16_as_ushort(a) | ((unsigned)__bfloat16_as_ushort(b) << 16);
}

__device__ __forceinline__ uint32_t smem_u32(const void* p) {
    uint32_t a;
    asm("{ .reg .u64 t; cvta.to.shared.u64 t, %1; cvt.u32.u64 %0, t; }" : "=r"(a) : "l"(p));
    return a;
}

__device__ __forceinline__ void ldsm4(unsigned* r, uint32_t addr) {
    asm volatile("ldmatrix.sync.aligned.m8n8.x4.shared.b16 {%0,%1,%2,%3}, [%4];"
                 : "=r"(r[0]), "=r"(r[1]), "=r"(r[2]), "=r"(r[3]) : "r"(addr));
}

__device__ __forceinline__ void mma_bf16(float* d, const unsigned* a, unsigned b0,
                                         unsigned b1) {
    asm volatile(
        "mma.sync.aligned.m16n8k16.row.col.f32.bf16.bf16.f32 "
        "{%0,%1,%2,%3}, {%4,%5,%6,%7}, {%8,%9}, {%0,%1,%2,%3};"
        : "+f"(d[0]), "+f"(d[1]), "+f"(d[2]), "+f"(d[3])
        : "r"(a[0]), "r"(a[1]), "r"(a[2]), "r"(a[3]), "r"(b0), "r"(b1));
}

// ---------------- bf16x3 MMA GEMM ----------------------------------------------
// C[M,1536] = A[M,768] * Bt^T, A/Bt given as bf16 (hi,lo) planes; fp32 accum.
// 3 products: Ah*Bh + Ah*Bl + Al*Bh. Block 128x128, BK=32, 256 thr, warps 2x4.
#define GSTG 40960  // bytes per stage (4 planes x 128 rows x 80B)
#define GPL 10240   // bytes per plane tile
#define GRS 80      // smem row stride (32 bf16 padded to 40)

__global__ __launch_bounds__(256, 1)
void gemm_bf16x3(const __nv_bfloat16* __restrict__ Ah, const __nv_bfloat16* __restrict__ Al,
                 const __nv_bfloat16* __restrict__ Bh, const __nv_bfloat16* __restrict__ Bl,
                 float* __restrict__ C0, float* __restrict__ C1, int M) {
    extern __shared__ char smem[];
    const uint32_t sbase = smem_u32(smem);
    const int tid = threadIdx.x;
    const int lane = tid & 31;
    const int wid = tid >> 5;
    const int wm = wid >> 2;   // 0..1
    const int wn = wid & 3;    // 0..3
    const int m0 = blockIdx.y * 128;
    const int n0 = blockIdx.x * 128;

    auto load_stage = [&](int stg, int k0) {
        uint32_t sb = sbase + stg * GSTG;
#pragma unroll
        for (int t = 0; t < 8; t++) {
            int idx = tid + t * 256;
            int plane = idx >> 9;        // 0:Ah 1:Al 2:Bh 3:Bl
            int r = (idx >> 2) & 127;
            int c = idx & 3;
            uint32_t dst = sb + plane * GPL + r * GRS + c * 16;
            const __nv_bfloat16* g;
            int sz = 16;
            if (plane < 2) {
                int row = m0 + r;
                if (row >= M) { row = 0; sz = 0; }
                g = (plane == 0 ? Ah : Al) + (size_t)row * FF + k0 + c * 8;
            } else {
                g = (plane == 2 ? Bh : Bl) + (size_t)(n0 + r) * FF + k0 + c * 8;
            }
            asm volatile("cp.async.cg.shared.global [%0], [%1], 16, %2;"
                         :: "r"(dst), "l"(g), "r"(sz));
        }
        asm volatile("cp.async.commit_group;" ::: "memory");
    };

    float acc[4][4][4];
#pragma unroll
    for (int i = 0; i < 4; i++)
#pragma unroll
        for (int t = 0; t < 4; t++)
#pragma unroll
            for (int q = 0; q < 4; q++) acc[i][t][q] = 0.f;

    const int fr = lane & 15;           // fragment row within 16
    const int fko = (lane >> 4) * 16;   // k byte offset within k16 (0 or 16)

    load_stage(0, 0);
    load_stage(1, 32);

#pragma unroll 1
    for (int ch = 0; ch < 24; ch++) {
        if (ch < 23)
            asm volatile("cp.async.wait_group 1;" ::: "memory");
        else
            asm volatile("cp.async.wait_group 0;" ::: "memory");
        __syncthreads();
        const uint32_t sb = sbase + (ch & 1) * GSTG;

#pragma unroll
        for (int ks = 0; ks < 2; ks++) {
            unsigned ah[4][4], al[4][4], bh[2][4], bl[2][4];
            const uint32_t ko = (uint32_t)(ks * 32 + fko);
#pragma unroll
            for (int i = 0; i < 4; i++) {
                uint32_t ra = sb + (uint32_t)((wm * 64 + i * 16 + fr) * GRS) + ko;
                ldsm4(ah[i], ra + 0 * GPL);
                ldsm4(al[i], ra + 1 * GPL);
            }
#pragma unroll
            for (int j = 0; j < 2; j++) {
                uint32_t rb = sb + (uint32_t)((wn * 32 + j * 16 + fr) * GRS) + ko;
                ldsm4(bh[j], rb + 2 * GPL);
                ldsm4(bl[j], rb + 3 * GPL);
            }
#pragma unroll
            for (int i = 0; i < 4; i++) {
#pragma unroll
                for (int t = 0; t < 4; t++) {
                    const int j = t >> 1, s = t & 1;
                    mma_bf16(acc[i][t], ah[i], bh[j][s], bh[j][s + 2]);
                    mma_bf16(acc[i][t], ah[i], bl[j][s], bl[j][s + 2]);
                    mma_bf16(acc[i][t], al[i], bh[j][s], bh[j][s + 2]);
                }
            }
        }
        __syncthreads();
        if (ch + 2 < 24) load_stage(ch & 1, (ch + 2) * 32);
    }

    // epilogue
    float* Cb;
    int nbase;
    if (n0 < FF) {
        Cb = C0;
        nbase = n0 + wn * 32;
    } else {
        Cb = C1;
        nbase = n0 - FF + wn * 32;
    }
#pragma unroll
    for (int i = 0; i < 4; i++) {
        const int r0 = m0 + wm * 64 + i * 16 + (lane >> 2);
#pragma unroll
        for (int t = 0; t < 4; t++) {
            const int col = nbase + t * 8 + (lane & 3) * 2;
            if (r0 < M)
                *(float2*)(Cb + (size_t)r0 * FF + col) =
                    make_float2(acc[i][t][0], acc[i][t][1]);
            if (r0 + 8 < M)
                *(float2*)(Cb + (size_t)(r0 + 8) * FF + col) =
                    make_float2(acc[i][t][2], acc[i][t][3]);
        }
    }
}

// ---------------- prep: split A into bf16 planes -------------------------------
__global__ void splitA_kernel(const float4* __restrict__ in, uint2* __restrict__ hi,
                              uint2* __restrict__ lo, int n4) {
    int i = blockIdx.x * blockDim.x + threadIdx.x;
    if (i >= n4) return;
    float4 v = in[i];
    __nv_bfloat16 h0, h1, h2, h3, l0, l1, l2, l3;
    split_bf(v.x, h0, l0);
    split_bf(v.y, h1, l1);
    split_bf(v.z, h2, l2);
    split_bf(v.w, h3, l3);
    hi[i] = make_uint2(cat_bf(h0, h1), cat_bf(h2, h3));
    lo[i] = make_uint2(cat_bf(l0, l1), cat_bf(l2, l3));
}

// ---------------- prep: transpose + split fused weights ------------------------
// Bt[n][k] = (n<768 ? Wl : Wr)[k][n mod 768], grid (768/32, 1536/32), block (32,8)
__global__ void wsplitT_kernel(const float* __restrict__ Wl, const float* __restrict__ Wr,
                               __nv_bfloat16* __restrict__ Bh,
                               __nv_bfloat16* __restrict__ Bl) {
    __shared__ float t[32][33];
    const int k0 = blockIdx.x * 32;
    const int n0g = blockIdx.y * 32;
    const float* W = (n0g < FF) ? Wl : Wr;
    const int n0 = (n0g < FF) ? n0g : n0g - FF;
    const int tx = threadIdx.x, ty = threadIdx.y;
#pragma unroll
    for (int i = 0; i < 4; i++)
        t[ty + i * 8][tx] = W[(size_t)(k0 + ty + i * 8) * FF + n0 + tx];
    __syncthreads();
#pragma unroll
    for (int i = 0; i < 4; i++) {
        float v = t[tx][ty + i * 8];
        size_t o = (size_t)(n0g + ty + i * 8) * FF + k0 + tx;
        __nv_bfloat16 h, l;
        split_bf(v, h, l);
        Bh[o] = h;
        Bl[o] = l;
    }
}

// ---------------- SGEMM (fp32, FFMA2) for the small GEMMs ---------------------
#define BM 128
#define BN 128
#define BK 16

__global__ __launch_bounds__(256, 2) void sgemm(const float* __restrict__ A,
                                                const float* __restrict__ B,
                                                float* __restrict__ C,
                                                int M, int N, int K) {
    __shared__ __align__(16) float As[2][BK][BM];
    __shared__ __align__(16) float Bs[2][BK][BN];

    const int tid = threadIdx.x;
    const int row0 = blockIdx.x * BM;
    const int col0 = blockIdx.y * BN;

    const int arow = tid >> 2;
    const int acol = (tid & 3) << 2;
    const int brow = tid >> 5;
    const int bcol = (tid & 31) << 2;

    const int tm = (tid >> 4) << 3;
    const int tn = (tid & 15) << 3;

    unsigned long long acc[8][4];
#pragma unroll
    for (int i = 0; i < 8; i++)
#pragma unroll
        for (int j = 0; j < 4; j++) acc[i][j] = 0ull;

    float4 ra0, ra1, rb0, rb1;

    auto ldg = [&](int kt) {
        const int k = kt * BK;
        const int r0 = row0 + arow;
        const int r1 = r0 + 64;
        const float4 z = make_float4(0.f, 0.f, 0.f, 0.f);
        ra0 = (r0 < M) ? *(const float4*)(A + (size_t)r0 * K + k + acol) : z;
        ra1 = (r1 < M) ? *(const float4*)(A + (size_t)r1 * K + k + acol) : z;
        rb0 = *(const float4*)(B + (size_t)(k + brow) * N + col0 + bcol);
        rb1 = *(const float4*)(B + (size_t)(k + brow + 8) * N + col0 + bcol);
    };
    auto sts = [&](int buf) {
        As[buf][acol + 0][arow] = ra0.x;
        As[buf][acol + 1][arow] = ra0.y;
        As[buf][acol + 2][arow] = ra0.z;
        As[buf][acol + 3][arow] = ra0.w;
        As[buf][acol + 0][arow + 64] = ra1.x;
        As[buf][acol + 1][arow + 64] = ra1.y;
        As[buf][acol + 2][arow + 64] = ra1.z;
        As[buf][acol + 3][arow + 64] = ra1.w;
        *(float4*)&Bs[buf][brow][bcol] = rb0;
        *(float4*)&Bs[buf][brow + 8][bcol] = rb1;
    };

    ldg(0);
    sts(0);
    __syncthreads();

    const int nk = K / BK;
    for (int kt = 0; kt < nk; kt++) {
        const int buf = kt & 1;
        if (kt + 1 < nk) ldg(kt + 1);
#pragma unroll
        for (int kk = 0; kk < BK; kk++) {
            float4 a0 = *(float4*)&As[buf][kk][tm];
            float4 a1 = *(float4*)&As[buf][kk][tm + 4];
            ulonglong2 b0 = *(ulonglong2*)&Bs[buf][kk][tn];
            ulonglong2 b1 = *(ulonglong2*)&Bs[buf][kk][tn + 4];
            float av[8] = {a0.x, a0.y, a0.z, a0.w, a1.x, a1.y, a1.z, a1.w};
#pragma unroll
            for (int i = 0; i < 8; i++) {
                unsigned long long ad = pack2(av[i], av[i]);
                fma2(acc[i][0], ad, b0.x);
                fma2(acc[i][1], ad, b0.y);
                fma2(acc[i][2], ad, b1.x);
                fma2(acc[i][3], ad, b1.y);
            }
        }
        if (kt + 1 < nk) sts(buf ^ 1);
        __syncthreads();
    }

#pragma unroll
    for (int i = 0; i < 8; i++) {
        const int r = row0 + tm + i;
        if (r < M) {
            float2 p0 = *(float2*)&acc[i][0];
            float2 p1 = *(float2*)&acc[i][1];
            float2 p2 = *(float2*)&acc[i][2];
            float2 p3 = *(float2*)&acc[i][3];
            *(float4*)(C + (size_t)r * N + col0 + tn) = make_float4(p0.x, p0.y, p1.x, p1.y);
            *(float4*)(C + (size_t)r * N + col0 + tn + 4) = make_float4(p2.x, p2.y, p3.x, p3.y);
        }
    }
}

// ---------------- per-node injection attention (writes bf16 planes) -----------
__global__ void combine_kernel(const float* __restrict__ hl,
                               const float* __restrict__ hs,
                               const float* __restrict__ hqg,
                               const int* __restrict__ batch,
                               const float* __restrict__ att,
                               __nv_bfloat16* __restrict__ outHi,
                               __nv_bfloat16* __restrict__ outLo) {
    int warp = (blockIdx.x * blockDim.x + threadIdx.x) >> 5;
    int lane = threadIdx.x & 31;
    if (warp >= NN) return;
    const float4* phl = (const float4*)(hl + (size_t)warp * FF);
    const float4* phs = (const float4*)(hs + (size_t)warp * FF);
    const float4* phq = (const float4*)(hqg + (size_t)batch[warp] * FF);
    const float4* pat = (const float4*)att;

    float4 vq[6], vs[6];
    float sq = 0.f, ss = 0.f;
#pragma unroll
    for (int i = 0; i < 6; i++) {
        int j = lane + i * 32;
        float4 l = phl[j];
        vq[i] = phq[j];
        vs[i] = phs[j];
        float4 a = pat[j];
        sq += lrelu(l.x + vq[i].x) * a.x + lrelu(l.y + vq[i].y) * a.y +
              lrelu(l.z + vq[i].z) * a.z + lrelu(l.w + vq[i].w) * a.w;
        ss += lrelu(l.x + vs[i].x) * a.x + lrelu(l.y + vs[i].y) * a.y +
              lrelu(l.z + vs[i].z) * a.z + lrelu(l.w + vs[i].w) * a.w;
    }
#pragma unroll
    for (int o = 16; o > 0; o >>= 1) {
        sq += __shfl_xor_sync(0xFFFFFFFFu, sq, o);
        ss += __shfl_xor_sync(0xFFFFFFFFu, ss, o);
    }
    float m = fmaxf(sq, ss);
    float e0 = expf(sq - m), e1 = expf(ss - m);
    float inv = 1.f / (e0 + e1);
    float a0 = e0 * inv, a1 = e1 * inv;

    uint2* pHi = (uint2*)(outHi + (size_t)warp * FF);
    uint2* pLo = (uint2*)(outLo + (size_t)warp * FF);
#pragma unroll
    for (int i = 0; i < 6; i++) {
        int j = lane + i * 32;
        float4 o;
        o.x = a0 * vq[i].x + a1 * vs[i].x;
        o.y = a0 * vq[i].y + a1 * vs[i].y;
        o.z = a0 * vq[i].z + a1 * vs[i].z;
        o.w = a0 * vq[i].w + a1 * vs[i].w;
        __nv_bfloat16 h0, h1, h2, h3, l0, l1, l2, l3;
        split_bf(o.x, h0, l0);
        split_bf(o.y, h1, l1);
        split_bf(o.z, h2, l2);
        split_bf(o.w, h3, l3);
        pHi[j] = make_uint2(cat_bf(h0, h1), cat_bf(h2, h3));
        pLo[j] = make_uint2(cat_bf(l0, l1), cat_bf(l2, l3));
    }
}

// ---------------- edge logits (one warp per edge) -----------------------------
__global__ void edge_logit_kernel(const float* __restrict__ gl,
                                  const float* __restrict__ gr,
                                  const float* __restrict__ ge,
                                  const int* __restrict__ xcoo,
                                  const float* __restrict__ att,
                                  float* __restrict__ logit) {
    int warp = (blockIdx.x * blockDim.x + threadIdx.x) >> 5;
    int lane = threadIdx.x & 31;
    if (warp >= NE) return;
    int src = xcoo[warp * 3 + 0];
    int rel = xcoo[warp * 3 + 1];
    int tgt = xcoo[warp * 3 + 2];
    const float4* pt = (const float4*)(gl + (size_t)tgt * FF);
    const float4* ps = (const float4*)(gr + (size_t)src * FF);
    const float4* pe = (const float4*)(ge + (size_t)rel * FF);
    const float4* pa = (const float4*)att;
    float s = 0.f;
#pragma unroll
    for (int i = 0; i < 6; i++) {
        int j = lane + i * 32;
        float4 t = pt[j], r = ps[j], e = pe[j], a = pa[j];
        s += lrelu(t.x + r.x + e.x) * a.x + lrelu(t.y + r.y + e.y) * a.y +
             lrelu(t.z + r.z + e.z) * a.z + lrelu(t.w + r.w + e.w) * a.w;
    }
#pragma unroll
    for (int o = 16; o > 0; o >>= 1) s += __shfl_xor_sync(0xFFFFFFFFu, s, o);
    if (lane == 0) logit[warp] = s;
}

// ---------------- segment softmax over edges (tgt) ----------------------------
__global__ void edge_max_kernel(const int* __restrict__ xcoo,
                                const float* __restrict__ logit,
                                unsigned* __restrict__ nmax) {
    int e = blockIdx.x * blockDim.x + threadIdx.x;
    if (e < NE) atomicMax(&nmax[xcoo[e * 3 + 2]], f2ord(logit[e]));
}

__global__ void edge_sum_kernel(const int* __restrict__ xcoo,
                                const float* __restrict__ logit,
                                const unsigned* __restrict__ nmax,
                                float* __restrict__ nsum) {
    int e = blockIdx.x * blockDim.x + threadIdx.x;
    if (e < NE) {
        int t = xcoo[e * 3 + 2];
        atomicAdd(&nsum[t], expf(logit[e] - ord2f(nmax[t])));
    }
}

// ---------------- message scatter (one warp per edge) ------------------------
__global__ void message_kernel(const int* __restrict__ xcoo,
                               const float* __restrict__ logit,
                               const unsigned* __restrict__ nmax,
                               const float* __restrict__ nsum,
                               const float* __restrict__ gr,
                               float* __restrict__ acc) {
    int warp = (blockIdx.x * blockDim.x + threadIdx.x) >> 5;
    int lane = threadIdx.x & 31;
    if (warp >= NE) return;
    int src = xcoo[warp * 3 + 0];
    int tgt = xcoo[warp * 3 + 2];
    float alpha = expf(logit[warp] - ord2f(nmax[tgt])) / (nsum[tgt] + 1e-16f);
    const float4* ps = (const float4*)(gr + (size_t)src * FF);
    float* pd = acc + (size_t)tgt * FF;
#pragma unroll
    for (int i = 0; i < 6; i++) {
        int j = lane + i * 32;
        float4 v = ps[j];
        atomicAdd(pd + j * 4 + 0, alpha * v.x);
        atomicAdd(pd + j * 4 + 1, alpha * v.y);
        atomicAdd(pd + j * 4 + 2, alpha * v.z);
        atomicAdd(pd + j * 4 + 3, alpha * v.w);
    }
}

// ---------------- elu + gate dot (one warp per node, in-place) ----------------
__global__ void node_post_kernel(float* __restrict__ emb,
                                 const float* __restrict__ gate_W,
                                 const float* __restrict__ gate_b,
                                 float* __restrict__ gate) {
    int warp = (blockIdx.x * blockDim.x + threadIdx.x) >> 5;
    int lane = threadIdx.x & 31;
    if (warp >= NN) return;
    float4* p = (float4*)(emb + (size_t)warp * FF);
    const float4* pw = (const float4*)gate_W;
    float s = 0.f;
#pragma unroll
    for (int i = 0; i < 6; i++) {
        int j = lane + i * 32;
        float4 v = p[j];
        v.x = v.x > 0.f ? v.x : expm1f(v.x);
        v.y = v.y > 0.f ? v.y : expm1f(v.y);
        v.z = v.z > 0.f ? v.z : expm1f(v.z);
        v.w = v.w > 0.f ? v.w : expm1f(v.w);
        p[j] = v;
        float4 w = pw[j];
        s += v.x * w.x + v.y * w.y + v.z * w.z + v.w * w.w;
    }
#pragma unroll
    for (int o = 16; o > 0; o >>= 1) s += __shfl_xor_sync(0xFFFFFFFFu, s, o);
    if (lane == 0) gate[warp] = s + gate_b[0];
}

// ---------------- graph softmax over nodes ------------------------------------
__global__ void graph_max_kernel(const float* __restrict__ gate,
                                 const int* __restrict__ batch,
                                 unsigned* __restrict__ gmax) {
    int n = blockIdx.x * blockDim.x + threadIdx.x;
    if (n < NN) atomicMax(&gmax[batch[n]], f2ord(gate[n]));
}

__global__ void graph_sum_kernel(float* __restrict__ gate,
                                 const int* __restrict__ batch,
                                 const unsigned* __restrict__ gmax,
                                 float* __restrict__ gsum) {
    int n = blockIdx.x * blockDim.x + threadIdx.x;
    if (n < NN) {
        float ex = expf(gate[n] - ord2f(gmax[batch[n]]));
        gate[n] = ex;
        atomicAdd(&gsum[batch[n]], ex);
    }
}

__global__ void gscale_kernel(float* __restrict__ gate,
                              const int* __restrict__ batch,
                              const float* __restrict__ gsum) {
    int n = blockIdx.x * blockDim.x + threadIdx.x;
    if (n < NN) gate[n] = gate[n] / (gsum[batch[n]] + 1e-16f);
}

// ---------------- pooled = segment_sum(g * emb, batch) (batch is sorted) ------
__global__ void pool_kernel(const float* __restrict__ emb,
                            const float* __restrict__ g,
                            const int* __restrict__ batch,
                            float* __restrict__ pool) {
    int f = blockIdx.y * 256 + threadIdx.x;
    int n0 = blockIdx.x * 1024;
    int n1 = min(n0 + 1024, NN);
    float acc = 0.f;
    int curb = batch[n0];
    for (int n = n0; n < n1; n++) {
        int b = batch[n];
        if (b != curb) {
            atomicAdd(&pool[(size_t)curb * FF + f], acc);
            acc = 0.f;
            curb = b;
        }
        acc += g[n] * emb[(size_t)n * FF + f];
    }
    atomicAdd(&pool[(size_t)curb * FF + f], acc);
}

// ---------------- init kernels ------------------------------------------------
__global__ void init_node_kernel(unsigned* nmax, float* nsum, unsigned* gmax,
                                 float* gsum, float* pool) {
    int i = blockIdx.x * blockDim.x + threadIdx.x;
    if (i < NN) {
        nmax[i] = ENC_NEG_INF;
        nsum[i] = 0.f;
    }
    if (i < NB) {
        gmax[i] = ENC_NEG_INF;
        gsum[i] = 0.f;
    }
    if (i < NB * FF) pool[i] = 0.f;
}

__global__ void zero_big_kernel(float4* p, int n4) {
    int i = blockIdx.x * blockDim.x + threadIdx.x;
    if (i < n4) p[i] = make_float4(0.f, 0.f, 0.f, 0.f);
}

// ---------------- launcher ------------------------------------------------------
extern "C" void kernel_launch(void* const* d_in, const int* in_sizes, int n_in,
                              void* d_out, int out_size) {
    const float* queries = (const float*)d_in[0];
    const float* entities = (const float*)d_in[1];
    const float* relations = (const float*)d_in[2];
    const int* xcoo = (const int*)d_in[3];
    const int* batch = (const int*)d_in[4];
    const float* inj_Wl = (const float*)d_in[5];
    const float* inj_Wr = (const float*)d_in[6];
    const float* inj_att = (const float*)d_in[7];
    const float* enc_Wl = (const float*)d_in[8];
    const float* enc_Wr = (const float*)d_in[9];
    const float* enc_We = (const float*)d_in[10];
    const float* enc_att = (const float*)d_in[11];
    /* d_in[12] enc_Wrel: dead code in reference */
    const float* gate_W = (const float*)d_in[13];
    const float* gate_b = (const float*)d_in[14];
    const float* vt_W = (const float*)d_in[15];
    float* out = (float*)d_out;

    float *big0, *big1, *big2, *hq, *ge, *logit, *nsum, *gate, *gsum, *pool;
    __nv_bfloat16 *Ahb, *Alb, *Bth, *Btl;
    unsigned *nmax, *gmax;
    cudaGetSymbolAddress((void**)&big0, g_big0);
    cudaGetSymbolAddress((void**)&big1, g_big1);
    cudaGetSymbolAddress((void**)&big2, g_big2);
    cudaGetSymbolAddress((void**)&Ahb, g_Ahb);
    cudaGetSymbolAddress((void**)&Alb, g_Alb);
    cudaGetSymbolAddress((void**)&Bth, g_Bth);
    cudaGetSymbolAddress((void**)&Btl, g_Btl);
    cudaGetSymbolAddress((void**)&hq, g_hq);
    cudaGetSymbolAddress((void**)&ge, g_ge);
    cudaGetSymbolAddress((void**)&logit, g_logit);
    cudaGetSymbolAddress((void**)&nmax, g_nmax);
    cudaGetSymbolAddress((void**)&nsum, g_nsum);
    cudaGetSymbolAddress((void**)&gate, g_gate);
    cudaGetSymbolAddress((void**)&gmax, g_gmax);
    cudaGetSymbolAddress((void**)&gsum, g_gsum);
    cudaGetSymbolAddress((void**)&pool, g_pool);

    cudaFuncSetAttribute(gemm_bf16x3, cudaFuncAttributeMaxDynamicSharedMemorySize,
                         2 * GSTG);

    const dim3 gridW(FF / 32, 2 * FF / 32);            // (24, 48)
    const dim3 gridG(2 * FF / 128, (NN + 127) / 128);  // (12, 391)

    // ---- injection layer: hl = E@Wl, hs = E@Wr (fused N=1536, bf16x3) ----
    splitA_kernel<<<(NN * FF / 4 + 255) / 256, 256>>>((const float4*)entities,
                                                      (uint2*)Ahb, (uint2*)Alb,
                                                      NN * FF / 4);
    wsplitT_kernel<<<gridW, dim3(32, 8)>>>(inj_Wl, inj_Wr, Bth, Btl);
    gemm_bf16x3<<<gridG, 256, 2 * GSTG>>>(Ahb, Alb, Bth, Btl, big0, big1, NN);
    sgemm<<<dim3(1, FF / BN), 256>>>(queries, inj_Wr, hq, NB, FF, FF);

    // combine writes bf16-split inj directly into Ahb/Alb
    combine_kernel<<<(NN * 32 + 255) / 256, 256>>>(big0, big1, hq, batch, inj_att,
                                                   Ahb, Alb);

    // ---- encoder layer: gl = inj@enc_Wl, gr = inj@enc_Wr ----
    wsplitT_kernel<<<gridW, dim3(32, 8)>>>(enc_Wl, enc_Wr, Bth, Btl);
    gemm_bf16x3<<<gridG, 256, 2 * GSTG>>>(Ahb, Alb, Bth, Btl, big0, big1, NN);
    sgemm<<<dim3((NRL + BM - 1) / BM, FF / BN), 256>>>(relations, enc_We, ge, NRL, FF, FF);

    edge_logit_kernel<<<(NE * 32 + 255) / 256, 256>>>(big0, big1, ge, xcoo, enc_att,
                                                      logit);

    init_node_kernel<<<(NN + 255) / 256, 256>>>(nmax, nsum, gmax, gsum, pool);
    zero_big_kernel<<<(NN * FF / 4 + 255) / 256, 256>>>((float4*)big2, NN * FF / 4);

    edge_max_kernel<<<(NE + 255) / 256, 256>>>(xcoo, logit, nmax);
    edge_sum_kernel<<<(NE + 255) / 256, 256>>>(xcoo, logit, nmax, nsum);
    message_kernel<<<(NE * 32 + 255) / 256, 256>>>(xcoo, logit, nmax, nsum, big1, big2);

    node_post_kernel<<<(NN * 32 + 255) / 256, 256>>>(big2, gate_W, gate_b, gate);

    graph_max_kernel<<<(NN + 255) / 256, 256>>>(gate, batch, gmax);
    graph_sum_kernel<<<(NN + 255) / 256, 256>>>(gate, batch, gmax, gsum);
    gscale_kernel<<<(NN + 255) / 256, 256>>>(gate, batch, gsum);

    pool_kernel<<<dim3((NN + 1023) / 1024, 3), 256>>>(big2, gate, batch, pool);

    sgemm<<<dim3(1, FV / BN), 256>>>(pool, vt_W, out, NB, FV, FF);
}

// round 4
// speedup vs baseline: 2.0500x; 1.1243x over previous
#include <cuda_runtime.h>
#include <cuda_bf16.h>
#include <math.h>
#include <stdint.h>

#define NN 50000
#define NE 100000
#define NRL 500
#define NB 64
#define FF 768
#define FV 2304
#define ENC_NEG_INF 0x007FFFFFu

// ---------------- scratch (static device memory; no allocations) ------------
__device__ __align__(16) float g_big0[NN * FF];   // hl, then gl
__device__ __align__(16) float g_big1[NN * FF];   // hs, then gr
__device__ __align__(16) float g_big2[NN * FF];   // msg-accum / ent_emb
__device__ __align__(16) __nv_bfloat16 g_Ahb[NN * FF];
__device__ __align__(16) __nv_bfloat16 g_Alb[NN * FF];
__device__ __align__(16) __nv_bfloat16 g_Bth[2 * FF * FF];
__device__ __align__(16) __nv_bfloat16 g_Btl[2 * FF * FF];
__device__ __align__(16) float g_hq[NB * FF];
__device__ float g_ge[NRL * FF];
__device__ float g_logit[NE];
__device__ unsigned g_nmax[NN];
__device__ float g_nsum[NN];
__device__ float g_gate[NN];
__device__ unsigned g_gmax[NB];
__device__ float g_gsum[NB];
__device__ float g_pool[NB * FF];

// ---------------- helpers ----------------------------------------------------
__device__ __forceinline__ float lrelu(float x) { return x > 0.f ? x : 0.2f * x; }

__device__ __forceinline__ unsigned f2ord(float f) {
    unsigned u = __float_as_uint(f);
    return (u & 0x80000000u) ? ~u : (u | 0x80000000u);
}
__device__ __forceinline__ float ord2f(unsigned u) {
    return (u & 0x80000000u) ? __uint_as_float(u & 0x7FFFFFFFu) : __uint_as_float(~u);
}

__device__ __forceinline__ void fma2(unsigned long long& d, unsigned long long a,
                                     unsigned long long b) {
    asm("fma.rn.f32x2 %0, %1, %2, %0;" : "+l"(d) : "l"(a), "l"(b));
}
__device__ __forceinline__ unsigned long long pack2(float x, float y) {
    unsigned long long r;
    asm("mov.b64 %0, {%1, %2};" : "=l"(r) : "f"(x), "f"(y));
    return r;
}

__device__ __forceinline__ void split_bf(float v, __nv_bfloat16& h, __nv_bfloat16& l) {
    h = __float2bfloat16_rn(v);
    l = __float2bfloat16_rn(v - __bfloat162float(h));
}
__device__ __forceinline__ unsigned cat_bf(__nv_bfloat16 a, __nv_bfloat16 b) {
    return (unsigned)__bfloat16_as_ushort(a) | ((unsigned)__bfloat16_as_ushort(b) << 16);
}

__device__ __forceinline__ uint32_t smem_u32(const void* p) {
    uint32_t a;
    asm("{ .reg .u64 t; cvta.to.shared.u64 t, %1; cvt.u32.u64 %0, t; }" : "=r"(a) : "l"(p));
    return a;
}

__device__ __forceinline__ void ldsm4(unsigned* r, uint32_t addr) {
    asm volatile("ldmatrix.sync.aligned.m8n8.x4.shared.b16 {%0,%1,%2,%3}, [%4];"
                 : "=r"(r[0]), "=r"(r[1]), "=r"(r[2]), "=r"(r[3]) : "r"(addr));
}

__device__ __forceinline__ void mma_bf16(float* d, const unsigned* a, unsigned b0,
                                         unsigned b1) {
    asm volatile(
        "mma.sync.aligned.m16n8k16.row.col.f32.bf16.bf16.f32 "
        "{%0,%1,%2,%3}, {%4,%5,%6,%7}, {%8,%9}, {%0,%1,%2,%3};"
        : "+f"(d[0]), "+f"(d[1]), "+f"(d[2]), "+f"(d[3])
        : "r"(a[0]), "r"(a[1]), "r"(a[2]), "r"(a[3]), "r"(b0), "r"(b1));
}

__device__ __forceinline__ void red_v4(float* p, float a, float b, float c, float d) {
    asm volatile("red.global.add.v4.f32 [%0], {%1,%2,%3,%4};"
                 :: "l"(p), "f"(a), "f"(b), "f"(c), "f"(d) : "memory");
}

// ---------------- bf16x3 MMA GEMM ----------------------------------------------
// C[M,1536] = A[M,768] * Bt^T. Block 128x256, warp tile 64x64 (2x4 warps), BK=32.
// smem stage: Ah[0,10240) Al[10240,20480) Bh[20480,40960) Bl[40960,61440)
#define GRS 80
#define G_APL 10240
#define G_BPL 20480
#define GSTG 61440

__global__ __launch_bounds__(256)
void gemm_bf16x3(const __nv_bfloat16* __restrict__ Ah, const __nv_bfloat16* __restrict__ Al,
                 const __nv_bfloat16* __restrict__ Bh, const __nv_bfloat16* __restrict__ Bl,
                 float* __restrict__ C0, float* __restrict__ C1, int M) {
    extern __shared__ char smem[];
    const uint32_t sbase = smem_u32(smem);
    const int tid = threadIdx.x;
    const int lane = tid & 31;
    const int wid = tid >> 5;
    const int wm = wid >> 2;   // 0..1
    const int wn = wid & 3;    // 0..3
    const int m0 = blockIdx.y * 128;
    const int n0 = blockIdx.x * 256;

    auto load_stage = [&](int stg, int k0) {
        uint32_t sb = sbase + stg * GSTG;
#pragma unroll
        for (int t = 0; t < 12; t++) {
            int idx = tid + t * 256;
            uint32_t dst;
            const __nv_bfloat16* g;
            int sz = 16;
            if (idx < 1024) {  // A: plane, 128 rows, 4 cols of 16B
                int plane = idx >> 9;
                int r = (idx >> 2) & 127;
                int c = idx & 3;
                dst = sb + plane * G_APL + r * GRS + c * 16;
                int row = m0 + r;
                if (row >= M) { row = 0; sz = 0; }
                g = (plane ? Al : Ah) + (size_t)row * FF + k0 + c * 8;
            } else {           // B: plane, 256 rows, 4 cols of 16B
                int i2 = idx - 1024;
                int plane = i2 >> 10;
                int r = (i2 >> 2) & 255;
                int c = i2 & 3;
                dst = sb + 2 * G_APL + plane * G_BPL + r * GRS + c * 16;
                g = (plane ? Bl : Bh) + (size_t)(n0 + r) * FF + k0 + c * 8;
            }
            asm volatile("cp.async.cg.shared.global [%0], [%1], 16, %2;"
                         :: "r"(dst), "l"(g), "r"(sz));
        }
        asm volatile("cp.async.commit_group;" ::: "memory");
    };

    float acc[4][8][4];
#pragma unroll
    for (int i = 0; i < 4; i++)
#pragma unroll
        for (int t = 0; t < 8; t++)
#pragma unroll
            for (int q = 0; q < 4; q++) acc[i][t][q] = 0.f;

    const int fr = lane & 15;
    const int fko = (lane >> 4) * 16;

    load_stage(0, 0);
    load_stage(1, 32);

#pragma unroll 1
    for (int ch = 0; ch < 24; ch++) {
        if (ch < 23)
            asm volatile("cp.async.wait_group 1;" ::: "memory");
        else
            asm volatile("cp.async.wait_group 0;" ::: "memory");
        __syncthreads();
        const uint32_t sb = sbase + (ch & 1) * GSTG;

#pragma unroll
        for (int ks = 0; ks < 2; ks++) {
            unsigned ah[4][4], al[4][4], bh[4][4], bl[4][4];
            const uint32_t ko = (uint32_t)(ks * 32 + fko);
#pragma unroll
            for (int i = 0; i < 4; i++) {
                uint32_t ra = sb + (uint32_t)((wm * 64 + i * 16 + fr) * GRS) + ko;
                ldsm4(ah[i], ra);
                ldsm4(al[i], ra + G_APL);
            }
#pragma unroll
            for (int j = 0; j < 4; j++) {
                uint32_t rb = sb + 2 * G_APL + (uint32_t)((wn * 64 + j * 16 + fr) * GRS) + ko;
                ldsm4(bh[j], rb);
                ldsm4(bl[j], rb + G_BPL);
            }
#pragma unroll
            for (int i = 0; i < 4; i++) {
#pragma unroll
                for (int j = 0; j < 4; j++) {
#pragma unroll
                    for (int s = 0; s < 2; s++) {
                        float* a = acc[i][j * 2 + s];
                        mma_bf16(a, ah[i], bh[j][s], bh[j][s + 2]);
                        mma_bf16(a, ah[i], bl[j][s], bl[j][s + 2]);
                        mma_bf16(a, al[i], bh[j][s], bh[j][s + 2]);
                    }
                }
            }
        }
        __syncthreads();
        if (ch + 2 < 24) load_stage(ch & 1, (ch + 2) * 32);
    }

    // epilogue
    float* Cb;
    int nbase;
    if (n0 < FF) {
        Cb = C0;
        nbase = n0 + wn * 64;
    } else {
        Cb = C1;
        nbase = n0 - FF + wn * 64;
    }
#pragma unroll
    for (int i = 0; i < 4; i++) {
        const int r0 = m0 + wm * 64 + i * 16 + (lane >> 2);
#pragma unroll
        for (int t = 0; t < 8; t++) {
            const int col = nbase + t * 8 + (lane & 3) * 2;
            if (r0 < M)
                *(float2*)(Cb + (size_t)r0 * FF + col) =
                    make_float2(acc[i][t][0], acc[i][t][1]);
            if (r0 + 8 < M)
                *(float2*)(Cb + (size_t)(r0 + 8) * FF + col) =
                    make_float2(acc[i][t][2], acc[i][t][3]);
        }
    }
}

// ---------------- split-K small GEMM: C[64,N] += A[64,K] * B[K,N] ---------------
// grid (N/64, K/128), block 256, 4x4 micro per thread, red.v4 accumulate.
#define SGK 128
__global__ __launch_bounds__(256) void smallgemm64(const float* __restrict__ A,
                                                   const float* __restrict__ B,
                                                   float* __restrict__ C, int N, int K) {
    __shared__ float As[32][68];
    __shared__ float Bs[32][64];
    const int tid = threadIdx.x;
    const int n0 = blockIdx.x * 64;
    const int k0 = blockIdx.y * SGK;
    const int tx = tid & 15, ty = tid >> 4;
    float acc[4][4] = {};

    for (int kt = 0; kt < SGK; kt += 32) {
        __syncthreads();
#pragma unroll
        for (int i = 0; i < 2; i++) {
            int idx = tid + i * 256;
            int r = idx >> 3, c = (idx & 7) * 4;
            float4 v = *(const float4*)(A + (size_t)r * K + k0 + kt + c);
            As[c + 0][r] = v.x;
            As[c + 1][r] = v.y;
            As[c + 2][r] = v.z;
            As[c + 3][r] = v.w;
            int rb = idx >> 4, cb = (idx & 15) * 4;
            *(float4*)&Bs[rb][cb] =
                *(const float4*)(B + (size_t)(k0 + kt + rb) * N + n0 + cb);
        }
        __syncthreads();
#pragma unroll
        for (int kk = 0; kk < 32; kk++) {
            float a0 = As[kk][ty * 4 + 0], a1 = As[kk][ty * 4 + 1];
            float a2 = As[kk][ty * 4 + 2], a3 = As[kk][ty * 4 + 3];
            float4 b = *(float4*)&Bs[kk][tx * 4];
            acc[0][0] += a0 * b.x; acc[0][1] += a0 * b.y; acc[0][2] += a0 * b.z; acc[0][3] += a0 * b.w;
            acc[1][0] += a1 * b.x; acc[1][1] += a1 * b.y; acc[1][2] += a1 * b.z; acc[1][3] += a1 * b.w;
            acc[2][0] += a2 * b.x; acc[2][1] += a2 * b.y; acc[2][2] += a2 * b.z; acc[2][3] += a2 * b.w;
            acc[3][0] += a3 * b.x; acc[3][1] += a3 * b.y; acc[3][2] += a3 * b.z; acc[3][3] += a3 * b.w;
        }
    }
#pragma unroll
    for (int i = 0; i < 4; i++) {
        float* p = C + (size_t)(ty * 4 + i) * N + n0 + tx * 4;
        red_v4(p, acc[i][0], acc[i][1], acc[i][2], acc[i][3]);
    }
}

// ---------------- prep: split A into bf16 planes -------------------------------
__global__ void splitA_kernel(const float4* __restrict__ in, uint2* __restrict__ hi,
                              uint2* __restrict__ lo, int n4) {
    int i = blockIdx.x * blockDim.x + threadIdx.x;
    if (i >= n4) return;
    float4 v = in[i];
    __nv_bfloat16 h0, h1, h2, h3, l0, l1, l2, l3;
    split_bf(v.x, h0, l0);
    split_bf(v.y, h1, l1);
    split_bf(v.z, h2, l2);
    split_bf(v.w, h3, l3);
    hi[i] = make_uint2(cat_bf(h0, h1), cat_bf(h2, h3));
    lo[i] = make_uint2(cat_bf(l0, l1), cat_bf(l2, l3));
}

// ---------------- prep: transpose + split fused weights ------------------------
__global__ void wsplitT_kernel(const float* __restrict__ Wl, const float* __restrict__ Wr,
                               __nv_bfloat16* __restrict__ Bh,
                               __nv_bfloat16* __restrict__ Bl) {
    __shared__ float t[32][33];
    const int k0 = blockIdx.x * 32;
    const int n0g = blockIdx.y * 32;
    const float* W = (n0g < FF) ? Wl : Wr;
    const int n0 = (n0g < FF) ? n0g : n0g - FF;
    const int tx = threadIdx.x, ty = threadIdx.y;
#pragma unroll
    for (int i = 0; i < 4; i++)
        t[ty + i * 8][tx] = W[(size_t)(k0 + ty + i * 8) * FF + n0 + tx];
    __syncthreads();
#pragma unroll
    for (int i = 0; i < 4; i++) {
        float v = t[tx][ty + i * 8];
        size_t o = (size_t)(n0g + ty + i * 8) * FF + k0 + tx;
        __nv_bfloat16 h, l;
        split_bf(v, h, l);
        Bh[o] = h;
        Bl[o] = l;
    }
}

// ---------------- SGEMM (fp32, FFMA2) for the relations GEMM -------------------
#define BM 128
#define BN 128
#define BK 16

__global__ __launch_bounds__(256, 2) void sgemm(const float* __restrict__ A,
                                                const float* __restrict__ B,
                                                float* __restrict__ C,
                                                int M, int N, int K) {
    __shared__ __align__(16) float As[2][BK][BM];
    __shared__ __align__(16) float Bs[2][BK][BN];

    const int tid = threadIdx.x;
    const int row0 = blockIdx.x * BM;
    const int col0 = blockIdx.y * BN;

    const int arow = tid >> 2;
    const int acol = (tid & 3) << 2;
    const int brow = tid >> 5;
    const int bcol = (tid & 31) << 2;

    const int tm = (tid >> 4) << 3;
    const int tn = (tid & 15) << 3;

    unsigned long long acc[8][4];
#pragma unroll
    for (int i = 0; i < 8; i++)
#pragma unroll
        for (int j = 0; j < 4; j++) acc[i][j] = 0ull;

    float4 ra0, ra1, rb0, rb1;

    auto ldg = [&](int kt) {
        const int k = kt * BK;
        const int r0 = row0 + arow;
        const int r1 = r0 + 64;
        const float4 z = make_float4(0.f, 0.f, 0.f, 0.f);
        ra0 = (r0 < M) ? *(const float4*)(A + (size_t)r0 * K + k + acol) : z;
        ra1 = (r1 < M) ? *(const float4*)(A + (size_t)r1 * K + k + acol) : z;
        rb0 = *(const float4*)(B + (size_t)(k + brow) * N + col0 + bcol);
        rb1 = *(const float4*)(B + (size_t)(k + brow + 8) * N + col0 + bcol);
    };
    auto sts = [&](int buf) {
        As[buf][acol + 0][arow] = ra0.x;
        As[buf][acol + 1][arow] = ra0.y;
        As[buf][acol + 2][arow] = ra0.z;
        As[buf][acol + 3][arow] = ra0.w;
        As[buf][acol + 0][arow + 64] = ra1.x;
        As[buf][acol + 1][arow + 64] = ra1.y;
        As[buf][acol + 2][arow + 64] = ra1.z;
        As[buf][acol + 3][arow + 64] = ra1.w;
        *(float4*)&Bs[buf][brow][bcol] = rb0;
        *(float4*)&Bs[buf][brow + 8][bcol] = rb1;
    };

    ldg(0);
    sts(0);
    __syncthreads();

    const int nk = K / BK;
    for (int kt = 0; kt < nk; kt++) {
        const int buf = kt & 1;
        if (kt + 1 < nk) ldg(kt + 1);
#pragma unroll
        for (int kk = 0; kk < BK; kk++) {
            float4 a0 = *(float4*)&As[buf][kk][tm];
            float4 a1 = *(float4*)&As[buf][kk][tm + 4];
            ulonglong2 b0 = *(ulonglong2*)&Bs[buf][kk][tn];
            ulonglong2 b1 = *(ulonglong2*)&Bs[buf][kk][tn + 4];
            float av[8] = {a0.x, a0.y, a0.z, a0.w, a1.x, a1.y, a1.z, a1.w};
#pragma unroll
            for (int i = 0; i < 8; i++) {
                unsigned long long ad = pack2(av[i], av[i]);
                fma2(acc[i][0], ad, b0.x);
                fma2(acc[i][1], ad, b0.y);
                fma2(acc[i][2], ad, b1.x);
                fma2(acc[i][3], ad, b1.y);
            }
        }
        if (kt + 1 < nk) sts(buf ^ 1);
        __syncthreads();
    }

#pragma unroll
    for (int i = 0; i < 8; i++) {
        const int r = row0 + tm + i;
        if (r < M) {
            float2 p0 = *(float2*)&acc[i][0];
            float2 p1 = *(float2*)&acc[i][1];
            float2 p2 = *(float2*)&acc[i][2];
            float2 p3 = *(float2*)&acc[i][3];
            *(float4*)(C + (size_t)r * N + col0 + tn) = make_float4(p0.x, p0.y, p1.x, p1.y);
            *(float4*)(C + (size_t)r * N + col0 + tn + 4) = make_float4(p2.x, p2.y, p3.x, p3.y);
        }
    }
}

// ---------------- per-node injection attention (writes bf16 planes) -----------
__global__ void combine_kernel(const float* __restrict__ hl,
                               const float* __restrict__ hs,
                               const float* __restrict__ hqg,
                               const int* __restrict__ batch,
                               const float* __restrict__ att,
                               __nv_bfloat16* __restrict__ outHi,
                               __nv_bfloat16* __restrict__ outLo) {
    int warp = (blockIdx.x * blockDim.x + threadIdx.x) >> 5;
    int lane = threadIdx.x & 31;
    if (warp >= NN) return;
    const float4* phl = (const float4*)(hl + (size_t)warp * FF);
    const float4* phs = (const float4*)(hs + (size_t)warp * FF);
    const float4* phq = (const float4*)(hqg + (size_t)batch[warp] * FF);
    const float4* pat = (const float4*)att;

    float4 vq[6], vs[6];
    float sq = 0.f, ss = 0.f;
#pragma unroll
    for (int i = 0; i < 6; i++) {
        int j = lane + i * 32;
        float4 l = phl[j];
        vq[i] = phq[j];
        vs[i] = phs[j];
        float4 a = pat[j];
        sq += lrelu(l.x + vq[i].x) * a.x + lrelu(l.y + vq[i].y) * a.y +
              lrelu(l.z + vq[i].z) * a.z + lrelu(l.w + vq[i].w) * a.w;
        ss += lrelu(l.x + vs[i].x) * a.x + lrelu(l.y + vs[i].y) * a.y +
              lrelu(l.z + vs[i].z) * a.z + lrelu(l.w + vs[i].w) * a.w;
    }
#pragma unroll
    for (int o = 16; o > 0; o >>= 1) {
        sq += __shfl_xor_sync(0xFFFFFFFFu, sq, o);
        ss += __shfl_xor_sync(0xFFFFFFFFu, ss, o);
    }
    float m = fmaxf(sq, ss);
    float e0 = expf(sq - m), e1 = expf(ss - m);
    float inv = 1.f / (e0 + e1);
    float a0 = e0 * inv, a1 = e1 * inv;

    uint2* pHi = (uint2*)(outHi + (size_t)warp * FF);
    uint2* pLo = (uint2*)(outLo + (size_t)warp * FF);
#pragma unroll
    for (int i = 0; i < 6; i++) {
        int j = lane + i * 32;
        float4 o;
        o.x = a0 * vq[i].x + a1 * vs[i].x;
        o.y = a0 * vq[i].y + a1 * vs[i].y;
        o.z = a0 * vq[i].z + a1 * vs[i].z;
        o.w = a0 * vq[i].w + a1 * vs[i].w;
        __nv_bfloat16 h0, h1, h2, h3, l0, l1, l2, l3;
        split_bf(o.x, h0, l0);
        split_bf(o.y, h1, l1);
        split_bf(o.z, h2, l2);
        split_bf(o.w, h3, l3);
        pHi[j] = make_uint2(cat_bf(h0, h1), cat_bf(h2, h3));
        pLo[j] = make_uint2(cat_bf(l0, l1), cat_bf(l2, l3));
    }
}

// ---------------- edge logits (one warp per edge) -----------------------------
__global__ void edge_logit_kernel(const float* __restrict__ gl,
                                  const float* __restrict__ gr,
                                  const float* __restrict__ ge,
                                  const int* __restrict__ xcoo,
                                  const float* __restrict__ att,
                                  float* __restrict__ logit) {
    int warp = (blockIdx.x * blockDim.x + threadIdx.x) >> 5;
    int lane = threadIdx.x & 31;
    if (warp >= NE) return;
    int src = xcoo[warp * 3 + 0];
    int rel = xcoo[warp * 3 + 1];
    int tgt = xcoo[warp * 3 + 2];
    const float4* pt = (const float4*)(gl + (size_t)tgt * FF);
    const float4* ps = (const float4*)(gr + (size_t)src * FF);
    const float4* pe = (const float4*)(ge + (size_t)rel * FF);
    const float4* pa = (const float4*)att;
    float s = 0.f;
#pragma unroll
    for (int i = 0; i < 6; i++) {
        int j = lane + i * 32;
        float4 t = pt[j], r = ps[j], e = pe[j], a = pa[j];
        s += lrelu(t.x + r.x + e.x) * a.x + lrelu(t.y + r.y + e.y) * a.y +
             lrelu(t.z + r.z + e.z) * a.z + lrelu(t.w + r.w + e.w) * a.w;
    }
#pragma unroll
    for (int o = 16; o > 0; o >>= 1) s += __shfl_xor_sync(0xFFFFFFFFu, s, o);
    if (lane == 0) logit[warp] = s;
}

// ---------------- segment softmax over edges (tgt) ----------------------------
__global__ void edge_max_kernel(const int* __restrict__ xcoo,
                                const float* __restrict__ logit,
                                unsigned* __restrict__ nmax) {
    int e = blockIdx.x * blockDim.x + threadIdx.x;
    if (e < NE) atomicMax(&nmax[xcoo[e * 3 + 2]], f2ord(logit[e]));
}

__global__ void edge_sum_kernel(const int* __restrict__ xcoo,
                                const float* __restrict__ logit,
                                const unsigned* __restrict__ nmax,
                                float* __restrict__ nsum) {
    int e = blockIdx.x * blockDim.x + threadIdx.x;
    if (e < NE) {
        int t = xcoo[e * 3 + 2];
        atomicAdd(&nsum[t], expf(logit[e] - ord2f(nmax[t])));
    }
}

// ---------------- message scatter (one warp per edge, red.v4) -----------------
__global__ void message_kernel(const int* __restrict__ xcoo,
                               const float* __restrict__ logit,
                               const unsigned* __restrict__ nmax,
                               const float* __restrict__ nsum,
                               const float* __restrict__ gr,
                               float* __restrict__ acc) {
    int warp = (blockIdx.x * blockDim.x + threadIdx.x) >> 5;
    int lane = threadIdx.x & 31;
    if (warp >= NE) return;
    int src = xcoo[warp * 3 + 0];
    int tgt = xcoo[warp * 3 + 2];
    float alpha = expf(logit[warp] - ord2f(nmax[tgt])) / (nsum[tgt] + 1e-16f);
    const float4* ps = (const float4*)(gr + (size_t)src * FF);
    float* pd = acc + (size_t)tgt * FF;
#pragma unroll
    for (int i = 0; i < 6; i++) {
        int j = lane + i * 32;
        float4 v = ps[j];
        red_v4(pd + j * 4, alpha * v.x, alpha * v.y, alpha * v.z, alpha * v.w);
    }
}

// ---------------- elu + gate dot (one warp per node, in-place) ----------------
__global__ void node_post_kernel(float* __restrict__ emb,
                                 const float* __restrict__ gate_W,
                                 const float* __restrict__ gate_b,
                                 float* __restrict__ gate) {
    int warp = (blockIdx.x * blockDim.x + threadIdx.x) >> 5;
    int lane = threadIdx.x & 31;
    if (warp >= NN) return;
    float4* p = (float4*)(emb + (size_t)warp * FF);
    const float4* pw = (const float4*)gate_W;
    float s = 0.f;
#pragma unroll
    for (int i = 0; i < 6; i++) {
        int j = lane + i * 32;
        float4 v = p[j];
        v.x = v.x > 0.f ? v.x : expm1f(v.x);
        v.y = v.y > 0.f ? v.y : expm1f(v.y);
        v.z = v.z > 0.f ? v.z : expm1f(v.z);
        v.w = v.w > 0.f ? v.w : expm1f(v.w);
        p[j] = v;
        float4 w = pw[j];
        s += v.x * w.x + v.y * w.y + v.z * w.z + v.w * w.w;
    }
#pragma unroll
    for (int o = 16; o > 0; o >>= 1) s += __shfl_xor_sync(0xFFFFFFFFu, s, o);
    if (lane == 0) gate[warp] = s + gate_b[0];
}

// ---------------- graph softmax over nodes ------------------------------------
__global__ void graph_max_kernel(const float* __restrict__ gate,
                                 const int* __restrict__ batch,
                                 unsigned* __restrict__ gmax) {
    int n = blockIdx.x * blockDim.x + threadIdx.x;
    if (n < NN) atomicMax(&gmax[batch[n]], f2ord(gate[n]));
}

__global__ void graph_sum_kernel(float* __restrict__ gate,
                                 const int* __restrict__ batch,
                                 const unsigned* __restrict__ gmax,
                                 float* __restrict__ gsum) {
    int n = blockIdx.x * blockDim.x + threadIdx.x;
    if (n < NN) {
        float ex = expf(gate[n] - ord2f(gmax[batch[n]]));
        gate[n] = ex;
        atomicAdd(&gsum[batch[n]], ex);
    }
}

__global__ void gscale_kernel(float* __restrict__ gate,
                              const int* __restrict__ batch,
                              const float* __restrict__ gsum) {
    int n = blockIdx.x * blockDim.x + threadIdx.x;
    if (n < NN) gate[n] = gate[n] / (gsum[batch[n]] + 1e-16f);
}

// ---------------- pooled = segment_sum(g * emb, batch) (batch is sorted) ------
__global__ void pool_kernel(const float* __restrict__ emb,
                            const float* __restrict__ g,
                            const int* __restrict__ batch,
                            float* __restrict__ pool) {
    int f = blockIdx.y * 256 + threadIdx.x;
    int n0 = blockIdx.x * 1024;
    int n1 = min(n0 + 1024, NN);
    float acc = 0.f;
    int curb = batch[n0];
    for (int n = n0; n < n1; n++) {
        int b = batch[n];
        if (b != curb) {
            atomicAdd(&pool[(size_t)curb * FF + f], acc);
            acc = 0.f;
            curb = b;
        }
        acc += g[n] * emb[(size_t)n * FF + f];
    }
    atomicAdd(&pool[(size_t)curb * FF + f], acc);
}

// ---------------- init kernels ------------------------------------------------
__global__ void init_node_kernel(unsigned* nmax, float* nsum, unsigned* gmax,
                                 float* gsum, float* pool) {
    int i = blockIdx.x * blockDim.x + threadIdx.x;
    if (i < NN) {
        nmax[i] = ENC_NEG_INF;
        nsum[i] = 0.f;
    }
    if (i < NB) {
        gmax[i] = ENC_NEG_INF;
        gsum[i] = 0.f;
    }
    if (i < NB * FF) pool[i] = 0.f;
}

__global__ void zero_kernel(float4* p, int n4) {
    int i = blockIdx.x * blockDim.x + threadIdx.x;
    if (i < n4) p[i] = make_float4(0.f, 0.f, 0.f, 0.f);
}

// ---------------- launcher ------------------------------------------------------
extern "C" void kernel_launch(void* const* d_in, const int* in_sizes, int n_in,
                              void* d_out, int out_size) {
    const float* queries = (const float*)d_in[0];
    const float* entities = (const float*)d_in[1];
    const float* relations = (const float*)d_in[2];
    const int* xcoo = (const int*)d_in[3];
    const int* batch = (const int*)d_in[4];
    const float* inj_Wl = (const float*)d_in[5];
    const float* inj_Wr = (const float*)d_in[6];
    const float* inj_att = (const float*)d_in[7];
    const float* enc_Wl = (const float*)d_in[8];
    const float* enc_Wr = (const float*)d_in[9];
    const float* enc_We = (const float*)d_in[10];
    const float* enc_att = (const float*)d_in[11];
    /* d_in[12] enc_Wrel: dead code in reference */
    const float* gate_W = (const float*)d_in[13];
    const float* gate_b = (const float*)d_in[14];
    const float* vt_W = (const float*)d_in[15];
    float* out = (float*)d_out;

    float *big0, *big1, *big2, *hq, *ge, *logit, *nsum, *gate, *gsum, *pool;
    __nv_bfloat16 *Ahb, *Alb, *Bth, *Btl;
    unsigned *nmax, *gmax;
    cudaGetSymbolAddress((void**)&big0, g_big0);
    cudaGetSymbolAddress((void**)&big1, g_big1);
    cudaGetSymbolAddress((void**)&big2, g_big2);
    cudaGetSymbolAddress((void**)&Ahb, g_Ahb);
    cudaGetSymbolAddress((void**)&Alb, g_Alb);
    cudaGetSymbolAddress((void**)&Bth, g_Bth);
    cudaGetSymbolAddress((void**)&Btl, g_Btl);
    cudaGetSymbolAddress((void**)&hq, g_hq);
    cudaGetSymbolAddress((void**)&ge, g_ge);
    cudaGetSymbolAddress((void**)&logit, g_logit);
    cudaGetSymbolAddress((void**)&nmax, g_nmax);
    cudaGetSymbolAddress((void**)&nsum, g_nsum);
    cudaGetSymbolAddress((void**)&gate, g_gate);
    cudaGetSymbolAddress((void**)&gmax, g_gmax);
    cudaGetSymbolAddress((void**)&gsum, g_gsum);
    cudaGetSymbolAddress((void**)&pool, g_pool);

    cudaFuncSetAttribute(gemm_bf16x3, cudaFuncAttributeMaxDynamicSharedMemorySize,
                         2 * GSTG);

    const dim3 gridW(FF / 32, 2 * FF / 32);            // (24, 48)
    const dim3 gridG(2 * FF / 256, (NN + 127) / 128);  // (6, 391)

    // ---- injection layer: hl = E@Wl, hs = E@Wr (fused N=1536, bf16x3) ----
    splitA_kernel<<<(NN * FF / 4 + 255) / 256, 256>>>((const float4*)entities,
                                                      (uint2*)Ahb, (uint2*)Alb,
                                                      NN * FF / 4);
    wsplitT_kernel<<<gridW, dim3(32, 8)>>>(inj_Wl, inj_Wr, Bth, Btl);
    gemm_bf16x3<<<gridG, 256, 2 * GSTG>>>(Ahb, Alb, Bth, Btl, big0, big1, NN);

    // hq = queries @ inj_Wr (split-K, red accumulate)
    zero_kernel<<<(NB * FF / 4 + 255) / 256, 256>>>((float4*)hq, NB * FF / 4);
    smallgemm64<<<dim3(FF / 64, FF / SGK), 256>>>(queries, inj_Wr, hq, FF, FF);

    combine_kernel<<<(NN * 32 + 255) / 256, 256>>>(big0, big1, hq, batch, inj_att,
                                                   Ahb, Alb);

    // ---- encoder layer: gl = inj@enc_Wl, gr = inj@enc_Wr ----
    wsplitT_kernel<<<gridW, dim3(32, 8)>>>(enc_Wl, enc_Wr, Bth, Btl);
    gemm_bf16x3<<<gridG, 256, 2 * GSTG>>>(Ahb, Alb, Bth, Btl, big0, big1, NN);
    sgemm<<<dim3((NRL + BM - 1) / BM, FF / BN), 256>>>(relations, enc_We, ge, NRL, FF, FF);

    edge_logit_kernel<<<(NE * 32 + 255) / 256, 256>>>(big0, big1, ge, xcoo, enc_att,
                                                      logit);

    init_node_kernel<<<(NN + 255) / 256, 256>>>(nmax, nsum, gmax, gsum, pool);
    zero_kernel<<<(NN * FF / 4 + 255) / 256, 256>>>((float4*)big2, NN * FF / 4);

    edge_max_kernel<<<(NE + 255) / 256, 256>>>(xcoo, logit, nmax);
    edge_sum_kernel<<<(NE + 255) / 256, 256>>>(xcoo, logit, nmax, nsum);
    message_kernel<<<(NE * 32 + 255) / 256, 256>>>(xcoo, logit, nmax, nsum, big1, big2);

    node_post_kernel<<<(NN * 32 + 255) / 256, 256>>>(big2, gate_W, gate_b, gate);

    graph_max_kernel<<<(NN + 255) / 256, 256>>>(gate, batch, gmax);
    graph_sum_kernel<<<(NN + 255) / 256, 256>>>(gate, batch, gmax, gsum);
    gscale_kernel<<<(NN + 255) / 256, 256>>>(gate, batch, gsum);

    pool_kernel<<<dim3((NN + 1023) / 1024, 3), 256>>>(big2, gate, batch, pool);

    // out = pooled @ vt_W  [64,768]x[768,2304] (split-K, red accumulate)
    zero_kernel<<<(NB * FV / 4 + 255) / 256, 256>>>((float4*)out, NB * FV / 4);
    smallgemm64<<<dim3(FV / 64, FF / SGK), 256>>>(pool, vt_W, out, FV, FF);
}

// round 5
// speedup vs baseline: 2.1208x; 1.0345x over previous
#include <cuda_runtime.h>
#include <cuda_bf16.h>
#include <math.h>
#include <stdint.h>

#define NN 50000
#define NE 100000
#define NRL 500
#define NB 64
#define FF 768
#define FV 2304
#define ENC_NEG_INF 0x007FFFFFu

// ---------------- scratch (static device memory; no allocations) ------------
__device__ __align__(16) float g_big0[NN * FF];   // hl, then gl
__device__ __align__(16) float g_big1[NN * FF];   // hs, then gr
__device__ __align__(16) float g_big2[NN * FF];   // msg-accum / ent_emb
__device__ __align__(16) __nv_bfloat16 g_Ahb[NN * FF];
__device__ __align__(16) __nv_bfloat16 g_Alb[NN * FF];
__device__ __align__(16) __nv_bfloat16 g_Bth[2 * FF * FF];
__device__ __align__(16) __nv_bfloat16 g_Btl[2 * FF * FF];
__device__ __align__(16) float g_hq[NB * FF];
__device__ __align__(16) float g_ge[NRL * FF];
__device__ float g_logit[NE];
__device__ unsigned g_nmax[NN];
__device__ float g_nsum[NN];
__device__ float g_gate[NN];
__device__ unsigned g_gmax[NB];
__device__ float g_gsum[NB];
__device__ __align__(16) float g_pool[NB * FF];

// ---------------- helpers ----------------------------------------------------
__device__ __forceinline__ float lrelu(float x) { return x > 0.f ? x : 0.2f * x; }

__device__ __forceinline__ unsigned f2ord(float f) {
    unsigned u = __float_as_uint(f);
    return (u & 0x80000000u) ? ~u : (u | 0x80000000u);
}
__device__ __forceinline__ float ord2f(unsigned u) {
    return (u & 0x80000000u) ? __uint_as_float(u & 0x7FFFFFFFu) : __uint_as_float(~u);
}

__device__ __forceinline__ void split_bf(float v, __nv_bfloat16& h, __nv_bfloat16& l) {
    h = __float2bfloat16_rn(v);
    l = __float2bfloat16_rn(v - __bfloat162float(h));
}
__device__ __forceinline__ unsigned cat_bf(__nv_bfloat16 a, __nv_bfloat16 b) {
    return (unsigned)__bfloat16_as_ushort(a) | ((unsigned)__bfloat16_as_ushort(b) << 16);
}

__device__ __forceinline__ uint32_t smem_u32(const void* p) {
    uint32_t a;
    asm("{ .reg .u64 t; cvta.to.shared.u64 t, %1; cvt.u32.u64 %0, t; }" : "=r"(a) : "l"(p));
    return a;
}

__device__ __forceinline__ void ldsm4(unsigned* r, uint32_t addr) {
    asm volatile("ldmatrix.sync.aligned.m8n8.x4.shared.b16 {%0,%1,%2,%3}, [%4];"
                 : "=r"(r[0]), "=r"(r[1]), "=r"(r[2]), "=r"(r[3]) : "r"(addr));
}

__device__ __forceinline__ void mma_bf16(float* d, const unsigned* a, unsigned b0,
                                         unsigned b1) {
    asm volatile(
        "mma.sync.aligned.m16n8k16.row.col.f32.bf16.bf16.f32 "
        "{%0,%1,%2,%3}, {%4,%5,%6,%7}, {%8,%9}, {%0,%1,%2,%3};"
        : "+f"(d[0]), "+f"(d[1]), "+f"(d[2]), "+f"(d[3])
        : "r"(a[0]), "r"(a[1]), "r"(a[2]), "r"(a[3]), "r"(b0), "r"(b1));
}

__device__ __forceinline__ void red_v4(float* p, float a, float b, float c, float d) {
    asm volatile("red.global.add.v4.f32 [%0], {%1,%2,%3,%4};"
                 :: "l"(p), "f"(a), "f"(b), "f"(c), "f"(d) : "memory");
}

// ---------------- bf16x3 MMA GEMM (3-stage pipeline) ---------------------------
// C[M,1536] = A[M,768] * Bt^T. Block 128x256, warp tile 64x64 (2x4 warps), BK=32.
// smem stage: Ah[0,10240) Al[10240,20480) Bh[20480,40960) Bl[40960,61440)
#define GRS 80
#define G_APL 10240
#define G_BPL 20480
#define GSTG 61440
#define NSTAGE 3

__global__ __launch_bounds__(256)
void gemm_bf16x3(const __nv_bfloat16* __restrict__ Ah, const __nv_bfloat16* __restrict__ Al,
                 const __nv_bfloat16* __restrict__ Bh, const __nv_bfloat16* __restrict__ Bl,
                 float* __restrict__ C0, float* __restrict__ C1, int M) {
    extern __shared__ char smem[];
    const uint32_t sbase = smem_u32(smem);
    const int tid = threadIdx.x;
    const int lane = tid & 31;
    const int wid = tid >> 5;
    const int wm = wid >> 2;   // 0..1
    const int wn = wid & 3;    // 0..3
    const int m0 = blockIdx.y * 128;
    const int n0 = blockIdx.x * 256;

    auto load_stage = [&](int stg, int k0) {
        uint32_t sb = sbase + stg * GSTG;
#pragma unroll
        for (int t = 0; t < 12; t++) {
            int idx = tid + t * 256;
            uint32_t dst;
            const __nv_bfloat16* g;
            int sz = 16;
            if (idx < 1024) {  // A planes: 128 rows x 4 cols of 16B
                int plane = idx >> 9;
                int r = (idx >> 2) & 127;
                int c = idx & 3;
                dst = sb + plane * G_APL + r * GRS + c * 16;
                int row = m0 + r;
                if (row >= M) { row = 0; sz = 0; }
                g = (plane ? Al : Ah) + (size_t)row * FF + k0 + c * 8;
            } else {           // B planes: 256 rows x 4 cols of 16B
                int i2 = idx - 1024;
                int plane = i2 >> 10;
                int r = (i2 >> 2) & 255;
                int c = i2 & 3;
                dst = sb + 2 * G_APL + plane * G_BPL + r * GRS + c * 16;
                g = (plane ? Bl : Bh) + (size_t)(n0 + r) * FF + k0 + c * 8;
            }
            asm volatile("cp.async.cg.shared.global [%0], [%1], 16, %2;"
                         :: "r"(dst), "l"(g), "r"(sz));
        }
        asm volatile("cp.async.commit_group;" ::: "memory");
    };

    float acc[4][8][4];
#pragma unroll
    for (int i = 0; i < 4; i++)
#pragma unroll
        for (int t = 0; t < 8; t++)
#pragma unroll
            for (int q = 0; q < 4; q++) acc[i][t][q] = 0.f;

    const int fr = lane & 15;
    const int fko = (lane >> 4) * 16;

    load_stage(0, 0);
    load_stage(1, 32);

#pragma unroll 1
    for (int ch = 0; ch < 24; ch++) {
        if (ch < 23)
            asm volatile("cp.async.wait_group 1;" ::: "memory");
        else
            asm volatile("cp.async.wait_group 0;" ::: "memory");
        __syncthreads();
        // issue next loads EARLY (into the stage consumed 2 iterations ago)
        if (ch + 2 < 24) load_stage((ch + 2) % NSTAGE, (ch + 2) * 32);

        const uint32_t sb = sbase + (ch % NSTAGE) * GSTG;
#pragma unroll
        for (int ks = 0; ks < 2; ks++) {
            unsigned ah[4][4], al[4][4], bh[4][4], bl[4][4];
            const uint32_t ko = (uint32_t)(ks * 32 + fko);
#pragma unroll
            for (int i = 0; i < 4; i++) {
                uint32_t ra = sb + (uint32_t)((wm * 64 + i * 16 + fr) * GRS) + ko;
                ldsm4(ah[i], ra);
                ldsm4(al[i], ra + G_APL);
            }
#pragma unroll
            for (int j = 0; j < 4; j++) {
                uint32_t rb = sb + 2 * G_APL + (uint32_t)((wn * 64 + j * 16 + fr) * GRS) + ko;
                ldsm4(bh[j], rb);
                ldsm4(bl[j], rb + G_BPL);
            }
#pragma unroll
            for (int i = 0; i < 4; i++) {
#pragma unroll
                for (int j = 0; j < 4; j++) {
#pragma unroll
                    for (int s = 0; s < 2; s++) {
                        float* a = acc[i][j * 2 + s];
                        mma_bf16(a, ah[i], bh[j][s], bh[j][s + 2]);
                        mma_bf16(a, ah[i], bl[j][s], bl[j][s + 2]);
                        mma_bf16(a, al[i], bh[j][s], bh[j][s + 2]);
                    }
                }
            }
        }
    }

    // epilogue
    float* Cb;
    int nbase;
    if (n0 < FF) {
        Cb = C0;
        nbase = n0 + wn * 64;
    } else {
        Cb = C1;
        nbase = n0 - FF + wn * 64;
    }
#pragma unroll
    for (int i = 0; i < 4; i++) {
        const int r0 = m0 + wm * 64 + i * 16 + (lane >> 2);
#pragma unroll
        for (int t = 0; t < 8; t++) {
            const int col = nbase + t * 8 + (lane & 3) * 2;
            if (r0 < M)
                *(float2*)(Cb + (size_t)r0 * FF + col) =
                    make_float2(acc[i][t][0], acc[i][t][1]);
            if (r0 + 8 < M)
                *(float2*)(Cb + (size_t)(r0 + 8) * FF + col) =
                    make_float2(acc[i][t][2], acc[i][t][3]);
        }
    }
}

// ---------------- split-K small GEMM: C[M,N] += A[M,K] * B[K,N] -----------------
// grid (N/64, K/128, ceil(M/64)), block 256, 4x4 micro, red.v4 accumulate.
#define SGK 128
__global__ __launch_bounds__(256) void smallgemm(const float* __restrict__ A,
                                                 const float* __restrict__ B,
                                                 float* __restrict__ C,
                                                 int M, int N, int K) {
    __shared__ float As[32][68];
    __shared__ float Bs[32][64];
    const int tid = threadIdx.x;
    const int n0 = blockIdx.x * 64;
    const int k0 = blockIdx.y * SGK;
    const int m0 = blockIdx.z * 64;
    const int tx = tid & 15, ty = tid >> 4;
    float acc[4][4] = {};

    for (int kt = 0; kt < SGK; kt += 32) {
        __syncthreads();
#pragma unroll
        for (int i = 0; i < 2; i++) {
            int idx = tid + i * 256;
            int r = idx >> 3, c = (idx & 7) * 4;
            float4 v = (m0 + r < M)
                           ? *(const float4*)(A + (size_t)(m0 + r) * K + k0 + kt + c)
                           : make_float4(0.f, 0.f, 0.f, 0.f);
            As[c + 0][r] = v.x;
            As[c + 1][r] = v.y;
            As[c + 2][r] = v.z;
            As[c + 3][r] = v.w;
            int rb = idx >> 4, cb = (idx & 15) * 4;
            *(float4*)&Bs[rb][cb] =
                *(const float4*)(B + (size_t)(k0 + kt + rb) * N + n0 + cb);
        }
        __syncthreads();
#pragma unroll
        for (int kk = 0; kk < 32; kk++) {
            float a0 = As[kk][ty * 4 + 0], a1 = As[kk][ty * 4 + 1];
            float a2 = As[kk][ty * 4 + 2], a3 = As[kk][ty * 4 + 3];
            float4 b = *(float4*)&Bs[kk][tx * 4];
            acc[0][0] += a0 * b.x; acc[0][1] += a0 * b.y; acc[0][2] += a0 * b.z; acc[0][3] += a0 * b.w;
            acc[1][0] += a1 * b.x; acc[1][1] += a1 * b.y; acc[1][2] += a1 * b.z; acc[1][3] += a1 * b.w;
            acc[2][0] += a2 * b.x; acc[2][1] += a2 * b.y; acc[2][2] += a2 * b.z; acc[2][3] += a2 * b.w;
            acc[3][0] += a3 * b.x; acc[3][1] += a3 * b.y; acc[3][2] += a3 * b.z; acc[3][3] += a3 * b.w;
        }
    }
#pragma unroll
    for (int i = 0; i < 4; i++) {
        int r = m0 + ty * 4 + i;
        if (r < M)
            red_v4(C + (size_t)r * N + n0 + tx * 4, acc[i][0], acc[i][1], acc[i][2],
                   acc[i][3]);
    }
}

// ---------------- prep: split A into bf16 planes -------------------------------
__global__ void splitA_kernel(const float4* __restrict__ in, uint2* __restrict__ hi,
                              uint2* __restrict__ lo, int n4) {
    int i = blockIdx.x * blockDim.x + threadIdx.x;
    if (i >= n4) return;
    float4 v = in[i];
    __nv_bfloat16 h0, h1, h2, h3, l0, l1, l2, l3;
    split_bf(v.x, h0, l0);
    split_bf(v.y, h1, l1);
    split_bf(v.z, h2, l2);
    split_bf(v.w, h3, l3);
    hi[i] = make_uint2(cat_bf(h0, h1), cat_bf(h2, h3));
    lo[i] = make_uint2(cat_bf(l0, l1), cat_bf(l2, l3));
}

// ---------------- prep: transpose + split fused weights ------------------------
__global__ void wsplitT_kernel(const float* __restrict__ Wl, const float* __restrict__ Wr,
                               __nv_bfloat16* __restrict__ Bh,
                               __nv_bfloat16* __restrict__ Bl) {
    __shared__ float t[32][33];
    const int k0 = blockIdx.x * 32;
    const int n0g = blockIdx.y * 32;
    const float* W = (n0g < FF) ? Wl : Wr;
    const int n0 = (n0g < FF) ? n0g : n0g - FF;
    const int tx = threadIdx.x, ty = threadIdx.y;
#pragma unroll
    for (int i = 0; i < 4; i++)
        t[ty + i * 8][tx] = W[(size_t)(k0 + ty + i * 8) * FF + n0 + tx];
    __syncthreads();
#pragma unroll
    for (int i = 0; i < 4; i++) {
        float v = t[tx][ty + i * 8];
        size_t o = (size_t)(n0g + ty + i * 8) * FF + k0 + tx;
        __nv_bfloat16 h, l;
        split_bf(v, h, l);
        Bh[o] = h;
        Bl[o] = l;
    }
}

// ---------------- per-node injection attention (writes bf16 planes) -----------
__global__ void combine_kernel(const float* __restrict__ hl,
                               const float* __restrict__ hs,
                               const float* __restrict__ hqg,
                               const int* __restrict__ batch,
                               const float* __restrict__ att,
                               __nv_bfloat16* __restrict__ outHi,
                               __nv_bfloat16* __restrict__ outLo) {
    int warp = (blockIdx.x * blockDim.x + threadIdx.x) >> 5;
    int lane = threadIdx.x & 31;
    if (warp >= NN) return;
    const float4* phl = (const float4*)(hl + (size_t)warp * FF);
    const float4* phs = (const float4*)(hs + (size_t)warp * FF);
    const float4* phq = (const float4*)(hqg + (size_t)batch[warp] * FF);
    const float4* pat = (const float4*)att;

    float4 vq[6], vs[6];
    float sq = 0.f, ss = 0.f;
#pragma unroll
    for (int i = 0; i < 6; i++) {
        int j = lane + i * 32;
        float4 l = phl[j];
        vq[i] = phq[j];
        vs[i] = phs[j];
        float4 a = pat[j];
        sq += lrelu(l.x + vq[i].x) * a.x + lrelu(l.y + vq[i].y) * a.y +
              lrelu(l.z + vq[i].z) * a.z + lrelu(l.w + vq[i].w) * a.w;
        ss += lrelu(l.x + vs[i].x) * a.x + lrelu(l.y + vs[i].y) * a.y +
              lrelu(l.z + vs[i].z) * a.z + lrelu(l.w + vs[i].w) * a.w;
    }
#pragma unroll
    for (int o = 16; o > 0; o >>= 1) {
        sq += __shfl_xor_sync(0xFFFFFFFFu, sq, o);
        ss += __shfl_xor_sync(0xFFFFFFFFu, ss, o);
    }
    float m = fmaxf(sq, ss);
    float e0 = expf(sq - m), e1 = expf(ss - m);
    float inv = 1.f / (e0 + e1);
    float a0 = e0 * inv, a1 = e1 * inv;

    uint2* pHi = (uint2*)(outHi + (size_t)warp * FF);
    uint2* pLo = (uint2*)(outLo + (size_t)warp * FF);
#pragma unroll
    for (int i = 0; i < 6; i++) {
        int j = lane + i * 32;
        float4 o;
        o.x = a0 * vq[i].x + a1 * vs[i].x;
        o.y = a0 * vq[i].y + a1 * vs[i].y;
        o.z = a0 * vq[i].z + a1 * vs[i].z;
        o.w = a0 * vq[i].w + a1 * vs[i].w;
        __nv_bfloat16 h0, h1, h2, h3, l0, l1, l2, l3;
        split_bf(o.x, h0, l0);
        split_bf(o.y, h1, l1);
        split_bf(o.z, h2, l2);
        split_bf(o.w, h3, l3);
        pHi[j] = make_uint2(cat_bf(h0, h1), cat_bf(h2, h3));
        pLo[j] = make_uint2(cat_bf(l0, l1), cat_bf(l2, l3));
    }
}

// ---------------- edge logits (one warp per edge) -----------------------------
__global__ void edge_logit_kernel(const float* __restrict__ gl,
                                  const float* __restrict__ gr,
                                  const float* __restrict__ ge,
                                  const int* __restrict__ xcoo,
                                  const float* __restrict__ att,
                                  float* __restrict__ logit) {
    int warp = (blockIdx.x * blockDim.x + threadIdx.x) >> 5;
    int lane = threadIdx.x & 31;
    if (warp >= NE) return;
    int src = xcoo[warp * 3 + 0];
    int rel = xcoo[warp * 3 + 1];
    int tgt = xcoo[warp * 3 + 2];
    const float4* pt = (const float4*)(gl + (size_t)tgt * FF);
    const float4* ps = (const float4*)(gr + (size_t)src * FF);
    const float4* pe = (const float4*)(ge + (size_t)rel * FF);
    const float4* pa = (const float4*)att;
    float s = 0.f;
#pragma unroll
    for (int i = 0; i < 6; i++) {
        int j = lane + i * 32;
        float4 t = pt[j], r = ps[j], e = pe[j], a = pa[j];
        s += lrelu(t.x + r.x + e.x) * a.x + lrelu(t.y + r.y + e.y) * a.y +
             lrelu(t.z + r.z + e.z) * a.z + lrelu(t.w + r.w + e.w) * a.w;
    }
#pragma unroll
    for (int o = 16; o > 0; o >>= 1) s += __shfl_xor_sync(0xFFFFFFFFu, s, o);
    if (lane == 0) logit[warp] = s;
}

// ---------------- segment softmax over edges (tgt) ----------------------------
__global__ void edge_max_kernel(const int* __restrict__ xcoo,
                                const float* __restrict__ logit,
                                unsigned* __restrict__ nmax) {
    int e = blockIdx.x * blockDim.x + threadIdx.x;
    if (e < NE) atomicMax(&nmax[xcoo[e * 3 + 2]], f2ord(logit[e]));
}

__global__ void edge_sum_kernel(const int* __restrict__ xcoo,
                                const float* __restrict__ logit,
                                const unsigned* __restrict__ nmax,
                                float* __restrict__ nsum) {
    int e = blockIdx.x * blockDim.x + threadIdx.x;
    if (e < NE) {
        int t = xcoo[e * 3 + 2];
        atomicAdd(&nsum[t], expf(logit[e] - ord2f(nmax[t])));
    }
}

// ---------------- message scatter (one warp per edge, red.v4) -----------------
__global__ void message_kernel(const int* __restrict__ xcoo,
                               const float* __restrict__ logit,
                               const unsigned* __restrict__ nmax,
                               const float* __restrict__ nsum,
                               const float* __restrict__ gr,
                               float* __restrict__ acc) {
    int warp = (blockIdx.x * blockDim.x + threadIdx.x) >> 5;
    int lane = threadIdx.x & 31;
    if (warp >= NE) return;
    int src = xcoo[warp * 3 + 0];
    int tgt = xcoo[warp * 3 + 2];
    float alpha = expf(logit[warp] - ord2f(nmax[tgt])) / (nsum[tgt] + 1e-16f);
    const float4* ps = (const float4*)(gr + (size_t)src * FF);
    float* pd = acc + (size_t)tgt * FF;
#pragma unroll
    for (int i = 0; i < 6; i++) {
        int j = lane + i * 32;
        float4 v = ps[j];
        red_v4(pd + j * 4, alpha * v.x, alpha * v.y, alpha * v.z, alpha * v.w);
    }
}

// ---------------- elu + gate dot (one warp per node, in-place) ----------------
__global__ void node_post_kernel(float* __restrict__ emb,
                                 const float* __restrict__ gate_W,
                                 const float* __restrict__ gate_b,
                                 float* __restrict__ gate) {
    int warp = (blockIdx.x * blockDim.x + threadIdx.x) >> 5;
    int lane = threadIdx.x & 31;
    if (warp >= NN) return;
    float4* p = (float4*)(emb + (size_t)warp * FF);
    const float4* pw = (const float4*)gate_W;
    float s = 0.f;
#pragma unroll
    for (int i = 0; i < 6; i++) {
        int j = lane + i * 32;
        float4 v = p[j];
        v.x = v.x > 0.f ? v.x : expm1f(v.x);
        v.y = v.y > 0.f ? v.y : expm1f(v.y);
        v.z = v.z > 0.f ? v.z : expm1f(v.z);
        v.w = v.w > 0.f ? v.w : expm1f(v.w);
        p[j] = v;
        float4 w = pw[j];
        s += v.x * w.x + v.y * w.y + v.z * w.z + v.w * w.w;
    }
#pragma unroll
    for (int o = 16; o > 0; o >>= 1) s += __shfl_xor_sync(0xFFFFFFFFu, s, o);
    if (lane == 0) gate[warp] = s + gate_b[0];
}

// ---------------- graph softmax over nodes ------------------------------------
__global__ void graph_max_kernel(const float* __restrict__ gate,
                                 const int* __restrict__ batch,
                                 unsigned* __restrict__ gmax) {
    int n = blockIdx.x * blockDim.x + threadIdx.x;
    if (n < NN) atomicMax(&gmax[batch[n]], f2ord(gate[n]));
}

__global__ void graph_sum_kernel(float* __restrict__ gate,
                                 const int* __restrict__ batch,
                                 const unsigned* __restrict__ gmax,
                                 float* __restrict__ gsum) {
    int n = blockIdx.x * blockDim.x + threadIdx.x;
    if (n < NN) {
        float ex = expf(gate[n] - ord2f(gmax[batch[n]]));
        gate[n] = ex;
        atomicAdd(&gsum[batch[n]], ex);
    }
}

__global__ void gscale_kernel(float* __restrict__ gate,
                              const int* __restrict__ batch,
                              const float* __restrict__ gsum) {
    int n = blockIdx.x * blockDim.x + threadIdx.x;
    if (n < NN) gate[n] = gate[n] / (gsum[batch[n]] + 1e-16f);
}

// ---------------- pooled = segment_sum(g * emb, batch) (batch is sorted) ------
__global__ void pool_kernel(const float* __restrict__ emb,
                            const float* __restrict__ g,
                            const int* __restrict__ batch,
                            float* __restrict__ pool) {
    int f = blockIdx.y * 256 + threadIdx.x;
    int n0 = blockIdx.x * 1024;
    int n1 = min(n0 + 1024, NN);
    float acc = 0.f;
    int curb = batch[n0];
    for (int n = n0; n < n1; n++) {
        int b = batch[n];
        if (b != curb) {
            atomicAdd(&pool[(size_t)curb * FF + f], acc);
            acc = 0.f;
            curb = b;
        }
        acc += g[n] * emb[(size_t)n * FF + f];
    }
    atomicAdd(&pool[(size_t)curb * FF + f], acc);
}

// ---------------- init kernels ------------------------------------------------
__global__ void init_node_kernel(unsigned* nmax, float* nsum, unsigned* gmax,
                                 float* gsum, float* pool) {
    int i = blockIdx.x * blockDim.x + threadIdx.x;
    if (i < NN) {
        nmax[i] = ENC_NEG_INF;
        nsum[i] = 0.f;
    }
    if (i < NB) {
        gmax[i] = ENC_NEG_INF;
        gsum[i] = 0.f;
    }
    if (i < NB * FF) pool[i] = 0.f;
}

__global__ void zero_kernel(float4* p, int n4) {
    int i = blockIdx.x * blockDim.x + threadIdx.x;
    if (i < n4) p[i] = make_float4(0.f, 0.f, 0.f, 0.f);
}

// ---------------- launcher ------------------------------------------------------
extern "C" void kernel_launch(void* const* d_in, const int* in_sizes, int n_in,
                              void* d_out, int out_size) {
    const float* queries = (const float*)d_in[0];
    const float* entities = (const float*)d_in[1];
    const float* relations = (const float*)d_in[2];
    const int* xcoo = (const int*)d_in[3];
    const int* batch = (const int*)d_in[4];
    const float* inj_Wl = (const float*)d_in[5];
    const float* inj_Wr = (const float*)d_in[6];
    const float* inj_att = (const float*)d_in[7];
    const float* enc_Wl = (const float*)d_in[8];
    const float* enc_Wr = (const float*)d_in[9];
    const float* enc_We = (const float*)d_in[10];
    const float* enc_att = (const float*)d_in[11];
    /* d_in[12] enc_Wrel: dead code in reference */
    const float* gate_W = (const float*)d_in[13];
    const float* gate_b = (const float*)d_in[14];
    const float* vt_W = (const float*)d_in[15];
    float* out = (float*)d_out;

    float *big0, *big1, *big2, *hq, *ge, *logit, *nsum, *gate, *gsum, *pool;
    __nv_bfloat16 *Ahb, *Alb, *Bth, *Btl;
    unsigned *nmax, *gmax;
    cudaGetSymbolAddress((void**)&big0, g_big0);
    cudaGetSymbolAddress((void**)&big1, g_big1);
    cudaGetSymbolAddress((void**)&big2, g_big2);
    cudaGetSymbolAddress((void**)&Ahb, g_Ahb);
    cudaGetSymbolAddress((void**)&Alb, g_Alb);
    cudaGetSymbolAddress((void**)&Bth, g_Bth);
    cudaGetSymbolAddress((void**)&Btl, g_Btl);
    cudaGetSymbolAddress((void**)&hq, g_hq);
    cudaGetSymbolAddress((void**)&ge, g_ge);
    cudaGetSymbolAddress((void**)&logit, g_logit);
    cudaGetSymbolAddress((void**)&nmax, g_nmax);
    cudaGetSymbolAddress((void**)&nsum, g_nsum);
    cudaGetSymbolAddress((void**)&gate, g_gate);
    cudaGetSymbolAddress((void**)&gmax, g_gmax);
    cudaGetSymbolAddress((void**)&gsum, g_gsum);
    cudaGetSymbolAddress((void**)&pool, g_pool);

    cudaFuncSetAttribute(gemm_bf16x3, cudaFuncAttributeMaxDynamicSharedMemorySize,
                         NSTAGE * GSTG);

    const dim3 gridW(FF / 32, 2 * FF / 32);            // (24, 48)
    const dim3 gridG(2 * FF / 256, (NN + 127) / 128);  // (6, 391)

    // ---- injection layer: hl = E@Wl, hs = E@Wr (fused N=1536, bf16x3) ----
    splitA_kernel<<<(NN * FF / 4 + 255) / 256, 256>>>((const float4*)entities,
                                                      (uint2*)Ahb, (uint2*)Alb,
                                                      NN * FF / 4);
    wsplitT_kernel<<<gridW, dim3(32, 8)>>>(inj_Wl, inj_Wr, Bth, Btl);
    gemm_bf16x3<<<gridG, 256, NSTAGE * GSTG>>>(Ahb, Alb, Bth, Btl, big0, big1, NN);

    // hq = queries @ inj_Wr (split-K, red accumulate)
    zero_kernel<<<(NB * FF / 4 + 255) / 256, 256>>>((float4*)hq, NB * FF / 4);
    smallgemm<<<dim3(FF / 64, FF / SGK, 1), 256>>>(queries, inj_Wr, hq, NB, FF, FF);

    combine_kernel<<<(NN * 32 + 255) / 256, 256>>>(big0, big1, hq, batch, inj_att,
                                                   Ahb, Alb);

    // ---- encoder layer: gl = inj@enc_Wl, gr = inj@enc_Wr ----
    wsplitT_kernel<<<gridW, dim3(32, 8)>>>(enc_Wl, enc_Wr, Bth, Btl);
    gemm_bf16x3<<<gridG, 256, NSTAGE * GSTG>>>(Ahb, Alb, Bth, Btl, big0, big1, NN);

    // ge = relations @ enc_We (split-K, red accumulate)
    zero_kernel<<<(NRL * FF / 4 + 255) / 256, 256>>>((float4*)ge, NRL * FF / 4);
    smallgemm<<<dim3(FF / 64, FF / SGK, (NRL + 63) / 64), 256>>>(relations, enc_We, ge,
                                                                 NRL, FF, FF);

    edge_logit_kernel<<<(NE * 32 + 255) / 256, 256>>>(big0, big1, ge, xcoo, enc_att,
                                                      logit);

    init_node_kernel<<<(NN + 255) / 256, 256>>>(nmax, nsum, gmax, gsum, pool);
    zero_kernel<<<(NN * FF / 4 + 255) / 256, 256>>>((float4*)big2, NN * FF / 4);

    edge_max_kernel<<<(NE + 255) / 256, 256>>>(xcoo, logit, nmax);
    edge_sum_kernel<<<(NE + 255) / 256, 256>>>(xcoo, logit, nmax, nsum);
    message_kernel<<<(NE * 32 + 255) / 256, 256>>>(xcoo, logit, nmax, nsum, big1, big2);

    node_post_kernel<<<(NN * 32 + 255) / 256, 256>>>(big2, gate_W, gate_b, gate);

    graph_max_kernel<<<(NN + 255) / 256, 256>>>(gate, batch, gmax);
    graph_sum_kernel<<<(NN + 255) / 256, 256>>>(gate, batch, gmax, gsum);
    gscale_kernel<<<(NN + 255) / 256, 256>>>(gate, batch, gsum);

    pool_kernel<<<dim3((NN + 1023) / 1024, 3), 256>>>(big2, gate, batch, pool);

    // out = pooled @ vt_W  [64,768]x[768,2304] (split-K, red accumulate)
    zero_kernel<<<(NB * FV / 4 + 255) / 256, 256>>>((float4*)out, NB * FV / 4);
    smallgemm<<<dim3(FV / 64, FF / SGK, 1), 256>>>(pool, vt_W, out, NB, FV, FF);
}

// round 6
// speedup vs baseline: 2.6582x; 1.2534x over previous
#include <cuda_runtime.h>
#include <cuda_fp16.h>
#include <math.h>
#include <stdint.h>

#define NN 50000
#define NE 100000
#define NRL 500
#define NB 64
#define FF 768
#define FV 2304
#define NMEGA (4 * FF)  // 3072
#define ENC_NEG_INF 0x007FFFFFu

// ---------------- scratch (static device memory; no allocations) ------------
__device__ __align__(16) float g_big0[NN * FF];   // hl -> gl
__device__ __align__(16) float g_big1[NN * FF];   // hs -> gr
__device__ __align__(16) float g_big2[NN * FF];   // t1 -> msg accum / ent_emb
__device__ __align__(16) float g_big3[NN * FF];   // t2
__device__ __align__(16) __half g_Ahf[NN * FF];   // fp16 hi plane of entities
__device__ __align__(16) __half g_Alf[NN * FF];   // fp16 lo plane of entities
__device__ __align__(16) __half g_Bhf[NMEGA * FF];  // [3072,768] fused W^T fp16
__device__ __align__(16) float g_P1[FF * FF];
__device__ __align__(16) float g_P2[FF * FF];
__device__ __align__(16) float g_hq[NB * FF];
__device__ __align__(16) float g_Gql[NB * FF];
__device__ __align__(16) float g_Gqr[NB * FF];
__device__ __align__(16) float g_ge[NRL * FF];
__device__ float g_logit[NE];
__device__ unsigned g_nmax[NN];
__device__ float g_nsum[NN];
__device__ float g_gate[NN];
__device__ unsigned g_gmax[NB];
__device__ float g_gsum[NB];
__device__ __align__(16) float g_pool[NB * FF];

// ---------------- helpers ----------------------------------------------------
__device__ __forceinline__ float lrelu(float x) { return x > 0.f ? x : 0.2f * x; }

__device__ __forceinline__ unsigned f2ord(float f) {
    unsigned u = __float_as_uint(f);
    return (u & 0x80000000u) ? ~u : (u | 0x80000000u);
}
__device__ __forceinline__ float ord2f(unsigned u) {
    return (u & 0x80000000u) ? __uint_as_float(u & 0x7FFFFFFFu) : __uint_as_float(~u);
}

__device__ __forceinline__ void split_h(float v, __half& h, __half& l) {
    h = __float2half_rn(v);
    l = __float2half_rn(v - __half2float(h));
}
__device__ __forceinline__ unsigned cat_h(__half a, __half b) {
    return (unsigned)__half_as_ushort(a) | ((unsigned)__half_as_ushort(b) << 16);
}

__device__ __forceinline__ uint32_t smem_u32(const void* p) {
    uint32_t a;
    asm("{ .reg .u64 t; cvta.to.shared.u64 t, %1; cvt.u32.u64 %0, t; }" : "=r"(a) : "l"(p));
    return a;
}

__device__ __forceinline__ void ldsm4(unsigned* r, uint32_t addr) {
    asm volatile("ldmatrix.sync.aligned.m8n8.x4.shared.b16 {%0,%1,%2,%3}, [%4];"
                 : "=r"(r[0]), "=r"(r[1]), "=r"(r[2]), "=r"(r[3]) : "r"(addr));
}

__device__ __forceinline__ void mma_f16(float* d, const unsigned* a, unsigned b0,
                                        unsigned b1) {
    asm volatile(
        "mma.sync.aligned.m16n8k16.row.col.f32.f16.f16.f32 "
        "{%0,%1,%2,%3}, {%4,%5,%6,%7}, {%8,%9}, {%0,%1,%2,%3};"
        : "+f"(d[0]), "+f"(d[1]), "+f"(d[2]), "+f"(d[3])
        : "r"(a[0]), "r"(a[1]), "r"(a[2]), "r"(a[3]), "r"(b0), "r"(b1));
}

__device__ __forceinline__ void red_v4(float* p, float a, float b, float c, float d) {
    asm volatile("red.global.add.v4.f32 [%0], {%1,%2,%3,%4};"
                 :: "l"(p), "f"(a), "f"(b), "f"(c), "f"(d) : "memory");
}

// ---------------- fp16x2 mega GEMM ---------------------------------------------
// [hl|hs|t1|t2][M,768 each] = A[M,768] * Bt^T, Bt=[3072,768] fp16.
// Products: Ah*Bh + Al*Bh = A*fp16(B). Block 128x256, warp 64x64 (2x4), BK=32.
// smem stage: Ah[0,10240) Al[10240,20480) Bh[20480,40960)
#define GRS 80
#define G_APL 10240
#define GSTG 40960
#define NSTAGE 4

__global__ __launch_bounds__(256)
void gemm_mega(const __half* __restrict__ Ah, const __half* __restrict__ Al,
               const __half* __restrict__ Bh,
               float* __restrict__ o0, float* __restrict__ o1,
               float* __restrict__ o2, float* __restrict__ o3, int M) {
    extern __shared__ char smem[];
    const uint32_t sbase = smem_u32(smem);
    const int tid = threadIdx.x;
    const int lane = tid & 31;
    const int wid = tid >> 5;
    const int wm = wid >> 2;   // 0..1
    const int wn = wid & 3;    // 0..3
    const int m0 = blockIdx.y * 128;
    const int n0 = blockIdx.x * 256;

    auto load_stage = [&](int stg, int k0) {
        uint32_t sb = sbase + stg * GSTG;
#pragma unroll
        for (int t = 0; t < 8; t++) {
            int idx = tid + t * 256;
            uint32_t dst;
            const __half* g;
            int sz = 16;
            if (idx < 1024) {  // A planes: 2 x 128 rows x 4 cols of 16B
                int plane = idx >> 9;
                int r = (idx >> 2) & 127;
                int c = idx & 3;
                dst = sb + plane * G_APL + r * GRS + c * 16;
                int row = m0 + r;
                if (row >= M) { row = 0; sz = 0; }
                g = (plane ? Al : Ah) + (size_t)row * FF + k0 + c * 8;
            } else {           // B plane: 256 rows x 4 cols of 16B
                int i2 = idx - 1024;
                int r = i2 >> 2;
                int c = i2 & 3;
                dst = sb + 2 * G_APL + r * GRS + c * 16;
                g = Bh + (size_t)(n0 + r) * FF + k0 + c * 8;
            }
            asm volatile("cp.async.cg.shared.global [%0], [%1], 16, %2;"
                         :: "r"(dst), "l"(g), "r"(sz));
        }
        asm volatile("cp.async.commit_group;" ::: "memory");
    };

    float acc[4][8][4];
#pragma unroll
    for (int i = 0; i < 4; i++)
#pragma unroll
        for (int t = 0; t < 8; t++)
#pragma unroll
            for (int q = 0; q < 4; q++) acc[i][t][q] = 0.f;

    const int fr = lane & 15;
    const int fko = (lane >> 4) * 16;

    load_stage(0, 0);
    load_stage(1, 32);
    load_stage(2, 64);

#pragma unroll 1
    for (int ch = 0; ch < 24; ch++) {
        asm volatile("cp.async.wait_group 2;" ::: "memory");
        __syncthreads();
        if (ch + 3 < 24) load_stage((ch + 3) % NSTAGE, (ch + 3) * 32);

        const uint32_t sb = sbase + (ch % NSTAGE) * GSTG;
#pragma unroll
        for (int ks = 0; ks < 2; ks++) {
            unsigned ah[4][4], al[4][4], bh[4][4];
            const uint32_t ko = (uint32_t)(ks * 32 + fko);
#pragma unroll
            for (int i = 0; i < 4; i++) {
                uint32_t ra = sb + (uint32_t)((wm * 64 + i * 16 + fr) * GRS) + ko;
                ldsm4(ah[i], ra);
                ldsm4(al[i], ra + G_APL);
            }
#pragma unroll
            for (int j = 0; j < 4; j++) {
                uint32_t rb = sb + 2 * G_APL + (uint32_t)((wn * 64 + j * 16 + fr) * GRS) + ko;
                ldsm4(bh[j], rb);
            }
#pragma unroll
            for (int i = 0; i < 4; i++) {
#pragma unroll
                for (int j = 0; j < 4; j++) {
#pragma unroll
                    for (int s = 0; s < 2; s++) {
                        float* a = acc[i][j * 2 + s];
                        mma_f16(a, ah[i], bh[j][s], bh[j][s + 2]);
                        mma_f16(a, al[i], bh[j][s], bh[j][s + 2]);
                    }
                }
            }
        }
    }

    // epilogue: stream = n0/768 (3 column tiles per stream)
    const int str = blockIdx.x / 3;
    float* Cb = (str == 0) ? o0 : (str == 1) ? o1 : (str == 2) ? o2 : o3;
    const int nbase = (blockIdx.x % 3) * 256 + wn * 64;
#pragma unroll
    for (int i = 0; i < 4; i++) {
        const int r0 = m0 + wm * 64 + i * 16 + (lane >> 2);
#pragma unroll
        for (int t = 0; t < 8; t++) {
            const int col = nbase + t * 8 + (lane & 3) * 2;
            if (r0 < M)
                *(float2*)(Cb + (size_t)r0 * FF + col) =
                    make_float2(acc[i][t][0], acc[i][t][1]);
            if (r0 + 8 < M)
                *(float2*)(Cb + (size_t)(r0 + 8) * FF + col) =
                    make_float2(acc[i][t][2], acc[i][t][3]);
        }
    }
}

// ---------------- split-K small GEMM: C[M,N] += A[M,K] * B[K,N] -----------------
#define SGK 128
__global__ __launch_bounds__(256) void smallgemm(const float* __restrict__ A,
                                                 const float* __restrict__ B,
                                                 float* __restrict__ C,
                                                 int M, int N, int K) {
    __shared__ float As[32][68];
    __shared__ float Bs[32][64];
    const int tid = threadIdx.x;
    const int n0 = blockIdx.x * 64;
    const int k0 = blockIdx.y * SGK;
    const int m0 = blockIdx.z * 64;
    const int tx = tid & 15, ty = tid >> 4;
    float acc[4][4] = {};

    for (int kt = 0; kt < SGK; kt += 32) {
        __syncthreads();
#pragma unroll
        for (int i = 0; i < 2; i++) {
            int idx = tid + i * 256;
            int r = idx >> 3, c = (idx & 7) * 4;
            float4 v = (m0 + r < M)
                           ? *(const float4*)(A + (size_t)(m0 + r) * K + k0 + kt + c)
                           : make_float4(0.f, 0.f, 0.f, 0.f);
            As[c + 0][r] = v.x;
            As[c + 1][r] = v.y;
            As[c + 2][r] = v.z;
            As[c + 3][r] = v.w;
            int rb = idx >> 4, cb = (idx & 15) * 4;
            *(float4*)&Bs[rb][cb] =
                *(const float4*)(B + (size_t)(k0 + kt + rb) * N + n0 + cb);
        }
        __syncthreads();
#pragma unroll
        for (int kk = 0; kk < 32; kk++) {
            float a0 = As[kk][ty * 4 + 0], a1 = As[kk][ty * 4 + 1];
            float a2 = As[kk][ty * 4 + 2], a3 = As[kk][ty * 4 + 3];
            float4 b = *(float4*)&Bs[kk][tx * 4];
            acc[0][0] += a0 * b.x; acc[0][1] += a0 * b.y; acc[0][2] += a0 * b.z; acc[0][3] += a0 * b.w;
            acc[1][0] += a1 * b.x; acc[1][1] += a1 * b.y; acc[1][2] += a1 * b.z; acc[1][3] += a1 * b.w;
            acc[2][0] += a2 * b.x; acc[2][1] += a2 * b.y; acc[2][2] += a2 * b.z; acc[2][3] += a2 * b.w;
            acc[3][0] += a3 * b.x; acc[3][1] += a3 * b.y; acc[3][2] += a3 * b.z; acc[3][3] += a3 * b.w;
        }
    }
#pragma unroll
    for (int i = 0; i < 4; i++) {
        int r = m0 + ty * 4 + i;
        if (r < M)
            red_v4(C + (size_t)r * N + n0 + tx * 4, acc[i][0], acc[i][1], acc[i][2],
                   acc[i][3]);
    }
}

// ---------------- prep: split entities into fp16 planes ------------------------
__global__ void splitA_kernel(const float4* __restrict__ in, uint2* __restrict__ hi,
                              uint2* __restrict__ lo, int n4) {
    int i = blockIdx.x * blockDim.x + threadIdx.x;
    if (i >= n4) return;
    float4 v = in[i];
    __half h0, h1, h2, h3, l0, l1, l2, l3;
    split_h(v.x, h0, l0);
    split_h(v.y, h1, l1);
    split_h(v.z, h2, l2);
    split_h(v.w, h3, l3);
    hi[i] = make_uint2(cat_h(h0, h1), cat_h(h2, h3));
    lo[i] = make_uint2(cat_h(l0, l1), cat_h(l2, l3));
}

// ---------------- prep: transpose + fp16 of fused mega weights -----------------
// Bt[n][k] = S[k][n%768], S = {Wl, Wr, P1, P2} by n/768. grid (768/32, 3072/32)
__global__ void wmegaT_kernel(const float* __restrict__ Wl, const float* __restrict__ Wr,
                              const float* __restrict__ P1, const float* __restrict__ P2,
                              __half* __restrict__ Bh) {
    __shared__ float t[32][33];
    const int k0 = blockIdx.x * 32;
    const int n0g = blockIdx.y * 32;
    const int sel = n0g / FF;
    const float* W = (sel == 0) ? Wl : (sel == 1) ? Wr : (sel == 2) ? P1 : P2;
    const int n0 = n0g - sel * FF;
    const int tx = threadIdx.x, ty = threadIdx.y;
#pragma unroll
    for (int i = 0; i < 4; i++)
        t[ty + i * 8][tx] = W[(size_t)(k0 + ty + i * 8) * FF + n0 + tx];
    __syncthreads();
#pragma unroll
    for (int i = 0; i < 4; i++)
        Bh[(size_t)(n0g + ty + i * 8) * FF + k0 + tx] = __float2half_rn(t[tx][ty + i * 8]);
}

// ---------------- fused injection attention + encoder-input assembly ----------
// per node n (one warp): a = softmax(s_q, s_s);
// gl[n] = a0*Gql[b] + a1*t1[n]   (written over hl)
// gr[n] = a0*Gqr[b] + a1*t2[n]   (written over hs)
__global__ void combine2_kernel(float* __restrict__ hl,        // in: hl, out: gl
                                float* __restrict__ hs,        // in: hs, out: gr
                                const float* __restrict__ t1,
                                const float* __restrict__ t2,
                                const float* __restrict__ hqg,
                                const float* __restrict__ Gql,
                                const float* __restrict__ Gqr,
                                const int* __restrict__ batch,
                                const float* __restrict__ att) {
    int warp = (blockIdx.x * blockDim.x + threadIdx.x) >> 5;
    int lane = threadIdx.x & 31;
    if (warp >= NN) return;
    const int b = batch[warp];
    const float4* phl = (const float4*)(hl + (size_t)warp * FF);
    const float4* phs = (const float4*)(hs + (size_t)warp * FF);
    const float4* phq = (const float4*)(hqg + (size_t)b * FF);
    const float4* pat = (const float4*)att;

    float sq = 0.f, ss = 0.f;
#pragma unroll
    for (int i = 0; i < 6; i++) {
        int j = lane + i * 32;
        float4 l = phl[j], q = phq[j], s = phs[j], a = pat[j];
        sq += lrelu(l.x + q.x) * a.x + lrelu(l.y + q.y) * a.y +
              lrelu(l.z + q.z) * a.z + lrelu(l.w + q.w) * a.w;
        ss += lrelu(l.x + s.x) * a.x + lrelu(l.y + s.y) * a.y +
              lrelu(l.z + s.z) * a.z + lrelu(l.w + s.w) * a.w;
    }
#pragma unroll
    for (int o = 16; o > 0; o >>= 1) {
        sq += __shfl_xor_sync(0xFFFFFFFFu, sq, o);
        ss += __shfl_xor_sync(0xFFFFFFFFu, ss, o);
    }
    float m = fmaxf(sq, ss);
    float e0 = expf(sq - m), e1 = expf(ss - m);
    float inv = 1.f / (e0 + e1);
    float a0 = e0 * inv, a1 = e1 * inv;

    const float4* pt1 = (const float4*)(t1 + (size_t)warp * FF);
    const float4* pt2 = (const float4*)(t2 + (size_t)warp * FF);
    const float4* pgl = (const float4*)(Gql + (size_t)b * FF);
    const float4* pgr = (const float4*)(Gqr + (size_t)b * FF);
    float4* ogl = (float4*)(hl + (size_t)warp * FF);
    float4* ogr = (float4*)(hs + (size_t)warp * FF);
#pragma unroll
    for (int i = 0; i < 6; i++) {
        int j = lane + i * 32;
        float4 u = pt1[j], g = pgl[j];
        ogl[j] = make_float4(a0 * g.x + a1 * u.x, a0 * g.y + a1 * u.y,
                             a0 * g.z + a1 * u.z, a0 * g.w + a1 * u.w);
        float4 v = pt2[j], h = pgr[j];
        ogr[j] = make_float4(a0 * h.x + a1 * v.x, a0 * h.y + a1 * v.y,
                             a0 * h.z + a1 * v.z, a0 * h.w + a1 * v.w);
    }
}

// ---------------- edge logits (one warp per edge) -----------------------------
__global__ void edge_logit_kernel(const float* __restrict__ gl,
                                  const float* __restrict__ gr,
                                  const float* __restrict__ ge,
                                  const int* __restrict__ xcoo,
                                  const float* __restrict__ att,
                                  float* __restrict__ logit) {
    int warp = (blockIdx.x * blockDim.x + threadIdx.x) >> 5;
    int lane = threadIdx.x & 31;
    if (warp >= NE) return;
    int src = xcoo[warp * 3 + 0];
    int rel = xcoo[warp * 3 + 1];
    int tgt = xcoo[warp * 3 + 2];
    const float4* pt = (const float4*)(gl + (size_t)tgt * FF);
    const float4* ps = (const float4*)(gr + (size_t)src * FF);
    const float4* pe = (const float4*)(ge + (size_t)rel * FF);
    const float4* pa = (const float4*)att;
    float s = 0.f;
#pragma unroll
    for (int i = 0; i < 6; i++) {
        int j = lane + i * 32;
        float4 t = pt[j], r = ps[j], e = pe[j], a = pa[j];
        s += lrelu(t.x + r.x + e.x) * a.x + lrelu(t.y + r.y + e.y) * a.y +
             lrelu(t.z + r.z + e.z) * a.z + lrelu(t.w + r.w + e.w) * a.w;
    }
#pragma unroll
    for (int o = 16; o > 0; o >>= 1) s += __shfl_xor_sync(0xFFFFFFFFu, s, o);
    if (lane == 0) logit[warp] = s;
}

// ---------------- segment softmax over edges (tgt) ----------------------------
__global__ void edge_max_kernel(const int* __restrict__ xcoo,
                                const float* __restrict__ logit,
                                unsigned* __restrict__ nmax) {
    int e = blockIdx.x * blockDim.x + threadIdx.x;
    if (e < NE) atomicMax(&nmax[xcoo[e * 3 + 2]], f2ord(logit[e]));
}

__global__ void edge_sum_kernel(const int* __restrict__ xcoo,
                                const float* __restrict__ logit,
                                const unsigned* __restrict__ nmax,
                                float* __restrict__ nsum) {
    int e = blockIdx.x * blockDim.x + threadIdx.x;
    if (e < NE) {
        int t = xcoo[e * 3 + 2];
        atomicAdd(&nsum[t], expf(logit[e] - ord2f(nmax[t])));
    }
}

// ---------------- message scatter (one warp per edge, red.v4) -----------------
__global__ void message_kernel(const int* __restrict__ xcoo,
                               const float* __restrict__ logit,
                               const unsigned* __restrict__ nmax,
                               const float* __restrict__ nsum,
                               const float* __restrict__ gr,
                               float* __restrict__ acc) {
    int warp = (blockIdx.x * blockDim.x + threadIdx.x) >> 5;
    int lane = threadIdx.x & 31;
    if (warp >= NE) return;
    int src = xcoo[warp * 3 + 0];
    int tgt = xcoo[warp * 3 + 2];
    float alpha = expf(logit[warp] - ord2f(nmax[tgt])) / (nsum[tgt] + 1e-16f);
    const float4* ps = (const float4*)(gr + (size_t)src * FF);
    float* pd = acc + (size_t)tgt * FF;
#pragma unroll
    for (int i = 0; i < 6; i++) {
        int j = lane + i * 32;
        float4 v = ps[j];
        red_v4(pd + j * 4, alpha * v.x, alpha * v.y, alpha * v.z, alpha * v.w);
    }
}

// ---------------- elu + gate dot (one warp per node, in-place) ----------------
__global__ void node_post_kernel(float* __restrict__ emb,
                                 const float* __restrict__ gate_W,
                                 const float* __restrict__ gate_b,
                                 float* __restrict__ gate) {
    int warp = (blockIdx.x * blockDim.x + threadIdx.x) >> 5;
    int lane = threadIdx.x & 31;
    if (warp >= NN) return;
    float4* p = (float4*)(emb + (size_t)warp * FF);
    const float4* pw = (const float4*)gate_W;
    float s = 0.f;
#pragma unroll
    for (int i = 0; i < 6; i++) {
        int j = lane + i * 32;
        float4 v = p[j];
        v.x = v.x > 0.f ? v.x : expm1f(v.x);
        v.y = v.y > 0.f ? v.y : expm1f(v.y);
        v.z = v.z > 0.f ? v.z : expm1f(v.z);
        v.w = v.w > 0.f ? v.w : expm1f(v.w);
        p[j] = v;
        float4 w = pw[j];
        s += v.x * w.x + v.y * w.y + v.z * w.z + v.w * w.w;
    }
#pragma unroll
    for (int o = 16; o > 0; o >>= 1) s += __shfl_xor_sync(0xFFFFFFFFu, s, o);
    if (lane == 0) gate[warp] = s + gate_b[0];
}

// ---------------- graph softmax over nodes ------------------------------------
__global__ void graph_max_kernel(const float* __restrict__ gate,
                                 const int* __restrict__ batch,
                                 unsigned* __restrict__ gmax) {
    int n = blockIdx.x * blockDim.x + threadIdx.x;
    if (n < NN) atomicMax(&gmax[batch[n]], f2ord(gate[n]));
}

__global__ void graph_sum_kernel(float* __restrict__ gate,
                                 const int* __restrict__ batch,
                                 const unsigned* __restrict__ gmax,
                                 float* __restrict__ gsum) {
    int n = blockIdx.x * blockDim.x + threadIdx.x;
    if (n < NN) {
        float ex = expf(gate[n] - ord2f(gmax[batch[n]]));
        gate[n] = ex;
        atomicAdd(&gsum[batch[n]], ex);
    }
}

__global__ void gscale_kernel(float* __restrict__ gate,
                              const int* __restrict__ batch,
                              const float* __restrict__ gsum) {
    int n = blockIdx.x * blockDim.x + threadIdx.x;
    if (n < NN) gate[n] = gate[n] / (gsum[batch[n]] + 1e-16f);
}

// ---------------- pooled = segment_sum(g * emb, batch) (batch is sorted) ------
__global__ void pool_kernel(const float* __restrict__ emb,
                            const float* __restrict__ g,
                            const int* __restrict__ batch,
                            float* __restrict__ pool) {
    int f = blockIdx.y * 256 + threadIdx.x;
    int n0 = blockIdx.x * 1024;
    int n1 = min(n0 + 1024, NN);
    float acc = 0.f;
    int curb = batch[n0];
    for (int n = n0; n < n1; n++) {
        int b = batch[n];
        if (b != curb) {
            atomicAdd(&pool[(size_t)curb * FF + f], acc);
            acc = 0.f;
            curb = b;
        }
        acc += g[n] * emb[(size_t)n * FF + f];
    }
    atomicAdd(&pool[(size_t)curb * FF + f], acc);
}

// ---------------- init kernels ------------------------------------------------
__global__ void init_node_kernel(unsigned* nmax, float* nsum, unsigned* gmax,
                                 float* gsum, float* pool) {
    int i = blockIdx.x * blockDim.x + threadIdx.x;
    if (i < NN) {
        nmax[i] = ENC_NEG_INF;
        nsum[i] = 0.f;
    }
    if (i < NB) {
        gmax[i] = ENC_NEG_INF;
        gsum[i] = 0.f;
    }
    if (i < NB * FF) pool[i] = 0.f;
}

__global__ void zero_kernel(float4* p, int n4) {
    int i = blockIdx.x * blockDim.x + threadIdx.x;
    if (i < n4) p[i] = make_float4(0.f, 0.f, 0.f, 0.f);
}

// ---------------- launcher ------------------------------------------------------
extern "C" void kernel_launch(void* const* d_in, const int* in_sizes, int n_in,
                              void* d_out, int out_size) {
    const float* queries = (const float*)d_in[0];
    const float* entities = (const float*)d_in[1];
    const float* relations = (const float*)d_in[2];
    const int* xcoo = (const int*)d_in[3];
    const int* batch = (const int*)d_in[4];
    const float* inj_Wl = (const float*)d_in[5];
    const float* inj_Wr = (const float*)d_in[6];
    const float* inj_att = (const float*)d_in[7];
    const float* enc_Wl = (const float*)d_in[8];
    const float* enc_Wr = (const float*)d_in[9];
    const float* enc_We = (const float*)d_in[10];
    const float* enc_att = (const float*)d_in[11];
    /* d_in[12] enc_Wrel: dead code in reference */
    const float* gate_W = (const float*)d_in[13];
    const float* gate_b = (const float*)d_in[14];
    const float* vt_W = (const float*)d_in[15];
    float* out = (float*)d_out;

    float *big0, *big1, *big2, *big3, *P1, *P2, *hq, *Gql, *Gqr, *ge, *logit, *nsum,
        *gate, *gsum, *pool;
    __half *Ahf, *Alf, *Bhf;
    unsigned *nmax, *gmax;
    cudaGetSymbolAddress((void**)&big0, g_big0);
    cudaGetSymbolAddress((void**)&big1, g_big1);
    cudaGetSymbolAddress((void**)&big2, g_big2);
    cudaGetSymbolAddress((void**)&big3, g_big3);
    cudaGetSymbolAddress((void**)&Ahf, g_Ahf);
    cudaGetSymbolAddress((void**)&Alf, g_Alf);
    cudaGetSymbolAddress((void**)&Bhf, g_Bhf);
    cudaGetSymbolAddress((void**)&P1, g_P1);
    cudaGetSymbolAddress((void**)&P2, g_P2);
    cudaGetSymbolAddress((void**)&hq, g_hq);
    cudaGetSymbolAddress((void**)&Gql, g_Gql);
    cudaGetSymbolAddress((void**)&Gqr, g_Gqr);
    cudaGetSymbolAddress((void**)&ge, g_ge);
    cudaGetSymbolAddress((void**)&logit, g_logit);
    cudaGetSymbolAddress((void**)&nmax, g_nmax);
    cudaGetSymbolAddress((void**)&nsum, g_nsum);
    cudaGetSymbolAddress((void**)&gate, g_gate);
    cudaGetSymbolAddress((void**)&gmax, g_gmax);
    cudaGetSymbolAddress((void**)&gsum, g_gsum);
    cudaGetSymbolAddress((void**)&pool, g_pool);

    cudaFuncSetAttribute(gemm_mega, cudaFuncAttributeMaxDynamicSharedMemorySize,
                         NSTAGE * GSTG);

    // ---- prep: fp16 planes of entities ----
    splitA_kernel<<<(NN * FF / 4 + 255) / 256, 256>>>((const float4*)entities,
                                                      (uint2*)Ahf, (uint2*)Alf,
                                                      NN * FF / 4);

    // ---- P1 = inj_Wr @ enc_Wl, P2 = inj_Wr @ enc_Wr (fp32 split-K) ----
    zero_kernel<<<(FF * FF / 4 + 255) / 256, 256>>>((float4*)P1, FF * FF / 4);
    zero_kernel<<<(FF * FF / 4 + 255) / 256, 256>>>((float4*)P2, FF * FF / 4);
    smallgemm<<<dim3(FF / 64, FF / SGK, FF / 64), 256>>>(inj_Wr, enc_Wl, P1, FF, FF, FF);
    smallgemm<<<dim3(FF / 64, FF / SGK, FF / 64), 256>>>(inj_Wr, enc_Wr, P2, FF, FF, FF);

    // ---- hq = queries @ inj_Wr; Gql = hq @ enc_Wl; Gqr = hq @ enc_Wr ----
    zero_kernel<<<(NB * FF / 4 + 255) / 256, 256>>>((float4*)hq, NB * FF / 4);
    smallgemm<<<dim3(FF / 64, FF / SGK, 1), 256>>>(queries, inj_Wr, hq, NB, FF, FF);
    zero_kernel<<<(NB * FF / 4 + 255) / 256, 256>>>((float4*)Gql, NB * FF / 4);
    zero_kernel<<<(NB * FF / 4 + 255) / 256, 256>>>((float4*)Gqr, NB * FF / 4);
    smallgemm<<<dim3(FF / 64, FF / SGK, 1), 256>>>(hq, enc_Wl, Gql, NB, FF, FF);
    smallgemm<<<dim3(FF / 64, FF / SGK, 1), 256>>>(hq, enc_Wr, Gqr, NB, FF, FF);

    // ---- ge = relations @ enc_We ----
    zero_kernel<<<(NRL * FF / 4 + 255) / 256, 256>>>((float4*)ge, NRL * FF / 4);
    smallgemm<<<dim3(FF / 64, FF / SGK, (NRL + 63) / 64), 256>>>(relations, enc_We, ge,
                                                                 NRL, FF, FF);

    // ---- fused mega weights [Wl | Wr | P1 | P2] -> Bt fp16 ----
    wmegaT_kernel<<<dim3(FF / 32, NMEGA / 32), dim3(32, 8)>>>(inj_Wl, inj_Wr, P1, P2,
                                                              Bhf);

    // ---- mega GEMM: E @ Bt^T -> hl, hs, t1, t2 ----
    gemm_mega<<<dim3(NMEGA / 256, (NN + 127) / 128), 256, NSTAGE * GSTG>>>(
        Ahf, Alf, Bhf, big0, big1, big2, big3, NN);

    // ---- injection attention + encoder-input assembly ----
    combine2_kernel<<<(NN * 32 + 255) / 256, 256>>>(big0, big1, big2, big3, hq, Gql,
                                                    Gqr, batch, inj_att);

    edge_logit_kernel<<<(NE * 32 + 255) / 256, 256>>>(big0, big1, ge, xcoo, enc_att,
                                                      logit);

    init_node_kernel<<<(NN + 255) / 256, 256>>>(nmax, nsum, gmax, gsum, pool);
    zero_kernel<<<(NN * FF / 4 + 255) / 256, 256>>>((float4*)big2, NN * FF / 4);

    edge_max_kernel<<<(NE + 255) / 256, 256>>>(xcoo, logit, nmax);
    edge_sum_kernel<<<(NE + 255) / 256, 256>>>(xcoo, logit, nmax, nsum);
    message_kernel<<<(NE * 32 + 255) / 256, 256>>>(xcoo, logit, nmax, nsum, big1, big2);

    node_post_kernel<<<(NN * 32 + 255) / 256, 256>>>(big2, gate_W, gate_b, gate);

    graph_max_kernel<<<(NN + 255) / 256, 256>>>(gate, batch, gmax);
    graph_sum_kernel<<<(NN + 255) / 256, 256>>>(gate, batch, gmax, gsum);
    gscale_kernel<<<(NN + 255) / 256, 256>>>(gate, batch, gsum);

    pool_kernel<<<dim3((NN + 1023) / 1024, 3), 256>>>(big2, gate, batch, pool);

    // out = pooled @ vt_W  [64,768]x[768,2304]
    zero_kernel<<<(NB * FV / 4 + 255) / 256, 256>>>((float4*)out, NB * FV / 4);
    smallgemm<<<dim3(FV / 64, FF / SGK, 1), 256>>>(pool, vt_W, out, NB, FV, FF);
}

// round 7
// speedup vs baseline: 3.5469x; 1.3343x over previous
#include <cuda_runtime.h>
#include <cuda_fp16.h>
#include <math.h>
#include <stdint.h>

#define NN 50000
#define NE 100000
#define NRL 500
#define NB 64
#define FF 768
#define FV 2304
#define NMEGA (4 * FF)  // 3072
#define ENC_NEG_INF 0x007FFFFFu

// ---------------- scratch (static device memory; no allocations) ------------
__device__ __align__(16) float g_big0[NN * FF];   // hl -> gl
__device__ __align__(16) float g_big1[NN * FF];   // hs -> gr
__device__ __align__(16) float g_big2[NN * FF];   // t1 -> msg accum / ent_emb
__device__ __align__(16) float g_big3[NN * FF];   // t2
__device__ __align__(16) __half g_Ahf[NN * FF];   // fp16 entities
__device__ __align__(16) __half g_Bhf[NMEGA * FF];  // [3072,768] fused W^T fp16
__device__ __align__(16) float g_P1[FF * FF];
__device__ __align__(16) float g_P2[FF * FF];
__device__ __align__(16) float g_hq[NB * FF];
__device__ __align__(16) float g_Gql[NB * FF];
__device__ __align__(16) float g_Gqr[NB * FF];
__device__ __align__(16) float g_ge[NRL * FF];
__device__ float g_logit[NE];
__device__ unsigned g_nmax[NN];
__device__ float g_nsum[NN];
__device__ float g_gate[NN];
__device__ unsigned g_gmax[NB];
__device__ float g_gsum[NB];
__device__ __align__(16) float g_pool[NB * FF];

// ---------------- helpers ----------------------------------------------------
__device__ __forceinline__ float lrelu(float x) { return x > 0.f ? x : 0.2f * x; }

__device__ __forceinline__ unsigned f2ord(float f) {
    unsigned u = __float_as_uint(f);
    return (u & 0x80000000u) ? ~u : (u | 0x80000000u);
}
__device__ __forceinline__ float ord2f(unsigned u) {
    return (u & 0x80000000u) ? __uint_as_float(u & 0x7FFFFFFFu) : __uint_as_float(~u);
}

__device__ __forceinline__ unsigned cat_h(__half a, __half b) {
    return (unsigned)__half_as_ushort(a) | ((unsigned)__half_as_ushort(b) << 16);
}

__device__ __forceinline__ uint32_t smem_u32(const void* p) {
    uint32_t a;
    asm("{ .reg .u64 t; cvta.to.shared.u64 t, %1; cvt.u32.u64 %0, t; }" : "=r"(a) : "l"(p));
    return a;
}

__device__ __forceinline__ void ldsm4(unsigned* r, uint32_t addr) {
    asm volatile("ldmatrix.sync.aligned.m8n8.x4.shared.b16 {%0,%1,%2,%3}, [%4];"
                 : "=r"(r[0]), "=r"(r[1]), "=r"(r[2]), "=r"(r[3]) : "r"(addr));
}

__device__ __forceinline__ void mma_f16(float* d, const unsigned* a, unsigned b0,
                                        unsigned b1) {
    asm volatile(
        "mma.sync.aligned.m16n8k16.row.col.f32.f16.f16.f32 "
        "{%0,%1,%2,%3}, {%4,%5,%6,%7}, {%8,%9}, {%0,%1,%2,%3};"
        : "+f"(d[0]), "+f"(d[1]), "+f"(d[2]), "+f"(d[3])
        : "r"(a[0]), "r"(a[1]), "r"(a[2]), "r"(a[3]), "r"(b0), "r"(b1));
}

__device__ __forceinline__ void red_v4(float* p, float a, float b, float c, float d) {
    asm volatile("red.global.add.v4.f32 [%0], {%1,%2,%3,%4};"
                 :: "l"(p), "f"(a), "f"(b), "f"(c), "f"(d) : "memory");
}

// ---------------- fp16 mega GEMM -----------------------------------------------
// [hl|hs|t1|t2][M,768 each] = fp16(A)[M,768] * Bt^T, Bt=[3072,768] fp16.
// Block 128x256, warp 64x64 (2x4 warps), BK=32.
// smem stage: A[0,10240) B[10240,30720)
#define GRS 80
#define G_APL 10240
#define GSTG 30720
#define NSTAGE 4

__global__ __launch_bounds__(256)
void gemm_mega(const __half* __restrict__ Ah, const __half* __restrict__ Bh,
               float* __restrict__ o0, float* __restrict__ o1,
               float* __restrict__ o2, float* __restrict__ o3, int M) {
    extern __shared__ char smem[];
    const uint32_t sbase = smem_u32(smem);
    const int tid = threadIdx.x;
    const int lane = tid & 31;
    const int wid = tid >> 5;
    const int wm = wid >> 2;   // 0..1
    const int wn = wid & 3;    // 0..3
    const int m0 = blockIdx.y * 128;
    const int n0 = blockIdx.x * 256;

    auto load_stage = [&](int stg, int k0) {
        uint32_t sb = sbase + stg * GSTG;
#pragma unroll
        for (int t = 0; t < 6; t++) {
            int idx = tid + t * 256;
            uint32_t dst;
            const __half* g;
            int sz = 16;
            if (idx < 512) {  // A: 128 rows x 4 cols of 16B
                int r = idx >> 2;
                int c = idx & 3;
                dst = sb + r * GRS + c * 16;
                int row = m0 + r;
                if (row >= M) { row = 0; sz = 0; }
                g = Ah + (size_t)row * FF + k0 + c * 8;
            } else {          // B: 256 rows x 4 cols of 16B
                int i2 = idx - 512;
                int r = i2 >> 2;
                int c = i2 & 3;
                dst = sb + G_APL + r * GRS + c * 16;
                g = Bh + (size_t)(n0 + r) * FF + k0 + c * 8;
            }
            asm volatile("cp.async.cg.shared.global [%0], [%1], 16, %2;"
                         :: "r"(dst), "l"(g), "r"(sz));
        }
        asm volatile("cp.async.commit_group;" ::: "memory");
    };

    float acc[4][8][4];
#pragma unroll
    for (int i = 0; i < 4; i++)
#pragma unroll
        for (int t = 0; t < 8; t++)
#pragma unroll
            for (int q = 0; q < 4; q++) acc[i][t][q] = 0.f;

    const int fr = lane & 15;
    const int fko = (lane >> 4) * 16;

    load_stage(0, 0);
    load_stage(1, 32);
    load_stage(2, 64);

#pragma unroll 1
    for (int ch = 0; ch < 24; ch++) {
        asm volatile("cp.async.wait_group 2;" ::: "memory");
        __syncthreads();
        if (ch + 3 < 24) load_stage((ch + 3) % NSTAGE, (ch + 3) * 32);

        const uint32_t sb = sbase + (ch % NSTAGE) * GSTG;
#pragma unroll
        for (int ks = 0; ks < 2; ks++) {
            unsigned ah[4][4], bh[4][4];
            const uint32_t ko = (uint32_t)(ks * 32 + fko);
#pragma unroll
            for (int i = 0; i < 4; i++) {
                uint32_t ra = sb + (uint32_t)((wm * 64 + i * 16 + fr) * GRS) + ko;
                ldsm4(ah[i], ra);
            }
#pragma unroll
            for (int j = 0; j < 4; j++) {
                uint32_t rb = sb + G_APL + (uint32_t)((wn * 64 + j * 16 + fr) * GRS) + ko;
                ldsm4(bh[j], rb);
            }
#pragma unroll
            for (int i = 0; i < 4; i++) {
#pragma unroll
                for (int j = 0; j < 4; j++) {
#pragma unroll
                    for (int s = 0; s < 2; s++) {
                        mma_f16(acc[i][j * 2 + s], ah[i], bh[j][s], bh[j][s + 2]);
                    }
                }
            }
        }
    }

    // epilogue: stream = blockIdx.x / 3 (3 column tiles per 768-wide stream)
    const int str = blockIdx.x / 3;
    float* Cb = (str == 0) ? o0 : (str == 1) ? o1 : (str == 2) ? o2 : o3;
    const int nbase = (blockIdx.x % 3) * 256 + wn * 64;
#pragma unroll
    for (int i = 0; i < 4; i++) {
        const int r0 = m0 + wm * 64 + i * 16 + (lane >> 2);
#pragma unroll
        for (int t = 0; t < 8; t++) {
            const int col = nbase + t * 8 + (lane & 3) * 2;
            if (r0 < M)
                *(float2*)(Cb + (size_t)r0 * FF + col) =
                    make_float2(acc[i][t][0], acc[i][t][1]);
            if (r0 + 8 < M)
                *(float2*)(Cb + (size_t)(r0 + 8) * FF + col) =
                    make_float2(acc[i][t][2], acc[i][t][3]);
        }
    }
}

// ---------------- split-K small GEMM: C[M,N] += A[M,K] * B[K,N] -----------------
#define SGK 128
__global__ __launch_bounds__(256) void smallgemm(const float* __restrict__ A,
                                                 const float* __restrict__ B,
                                                 float* __restrict__ C,
                                                 int M, int N, int K) {
    __shared__ float As[32][68];
    __shared__ float Bs[32][64];
    const int tid = threadIdx.x;
    const int n0 = blockIdx.x * 64;
    const int k0 = blockIdx.y * SGK;
    const int m0 = blockIdx.z * 64;
    const int tx = tid & 15, ty = tid >> 4;
    float acc[4][4] = {};

    for (int kt = 0; kt < SGK; kt += 32) {
        __syncthreads();
#pragma unroll
        for (int i = 0; i < 2; i++) {
            int idx = tid + i * 256;
            int r = idx >> 3, c = (idx & 7) * 4;
            float4 v = (m0 + r < M)
                           ? *(const float4*)(A + (size_t)(m0 + r) * K + k0 + kt + c)
                           : make_float4(0.f, 0.f, 0.f, 0.f);
            As[c + 0][r] = v.x;
            As[c + 1][r] = v.y;
            As[c + 2][r] = v.z;
            As[c + 3][r] = v.w;
            int rb = idx >> 4, cb = (idx & 15) * 4;
            *(float4*)&Bs[rb][cb] =
                *(const float4*)(B + (size_t)(k0 + kt + rb) * N + n0 + cb);
        }
        __syncthreads();
#pragma unroll
        for (int kk = 0; kk < 32; kk++) {
            float a0 = As[kk][ty * 4 + 0], a1 = As[kk][ty * 4 + 1];
            float a2 = As[kk][ty * 4 + 2], a3 = As[kk][ty * 4 + 3];
            float4 b = *(float4*)&Bs[kk][tx * 4];
            acc[0][0] += a0 * b.x; acc[0][1] += a0 * b.y; acc[0][2] += a0 * b.z; acc[0][3] += a0 * b.w;
            acc[1][0] += a1 * b.x; acc[1][1] += a1 * b.y; acc[1][2] += a1 * b.z; acc[1][3] += a1 * b.w;
            acc[2][0] += a2 * b.x; acc[2][1] += a2 * b.y; acc[2][2] += a2 * b.z; acc[2][3] += a2 * b.w;
            acc[3][0] += a3 * b.x; acc[3][1] += a3 * b.y; acc[3][2] += a3 * b.z; acc[3][3] += a3 * b.w;
        }
    }
#pragma unroll
    for (int i = 0; i < 4; i++) {
        int r = m0 + ty * 4 + i;
        if (r < M)
            red_v4(C + (size_t)r * N + n0 + tx * 4, acc[i][0], acc[i][1], acc[i][2],
                   acc[i][3]);
    }
}

// ---------------- prep: convert entities to fp16 --------------------------------
__global__ void cvtA_kernel(const float4* __restrict__ in, uint2* __restrict__ hi,
                            int n4) {
    int i = blockIdx.x * blockDim.x + threadIdx.x;
    if (i >= n4) return;
    float4 v = in[i];
    hi[i] = make_uint2(cat_h(__float2half_rn(v.x), __float2half_rn(v.y)),
                       cat_h(__float2half_rn(v.z), __float2half_rn(v.w)));
}

// ---------------- prep: transpose + fp16 of fused mega weights -----------------
__global__ void wmegaT_kernel(const float* __restrict__ Wl, const float* __restrict__ Wr,
                              const float* __restrict__ P1, const float* __restrict__ P2,
                              __half* __restrict__ Bh) {
    __shared__ float t[32][33];
    const int k0 = blockIdx.x * 32;
    const int n0g = blockIdx.y * 32;
    const int sel = n0g / FF;
    const float* W = (sel == 0) ? Wl : (sel == 1) ? Wr : (sel == 2) ? P1 : P2;
    const int n0 = n0g - sel * FF;
    const int tx = threadIdx.x, ty = threadIdx.y;
#pragma unroll
    for (int i = 0; i < 4; i++)
        t[ty + i * 8][tx] = W[(size_t)(k0 + ty + i * 8) * FF + n0 + tx];
    __syncthreads();
#pragma unroll
    for (int i = 0; i < 4; i++)
        Bh[(size_t)(n0g + ty + i * 8) * FF + k0 + tx] = __float2half_rn(t[tx][ty + i * 8]);
}

// ---------------- fused injection attention + encoder-input assembly ----------
__global__ void combine2_kernel(float* __restrict__ hl,        // in: hl, out: gl
                                float* __restrict__ hs,        // in: hs, out: gr
                                const float* __restrict__ t1,
                                const float* __restrict__ t2,
                                const float* __restrict__ hqg,
                                const float* __restrict__ Gql,
                                const float* __restrict__ Gqr,
                                const int* __restrict__ batch,
                                const float* __restrict__ att) {
    int warp = (blockIdx.x * blockDim.x + threadIdx.x) >> 5;
    int lane = threadIdx.x & 31;
    if (warp >= NN) return;
    const int b = batch[warp];
    const float4* phl = (const float4*)(hl + (size_t)warp * FF);
    const float4* phs = (const float4*)(hs + (size_t)warp * FF);
    const float4* phq = (const float4*)(hqg + (size_t)b * FF);
    const float4* pat = (const float4*)att;

    float sq = 0.f, ss = 0.f;
#pragma unroll
    for (int i = 0; i < 6; i++) {
        int j = lane + i * 32;
        float4 l = phl[j], q = phq[j], s = phs[j], a = pat[j];
        sq += lrelu(l.x + q.x) * a.x + lrelu(l.y + q.y) * a.y +
              lrelu(l.z + q.z) * a.z + lrelu(l.w + q.w) * a.w;
        ss += lrelu(l.x + s.x) * a.x + lrelu(l.y + s.y) * a.y +
              lrelu(l.z + s.z) * a.z + lrelu(l.w + s.w) * a.w;
    }
#pragma unroll
    for (int o = 16; o > 0; o >>= 1) {
        sq += __shfl_xor_sync(0xFFFFFFFFu, sq, o);
        ss += __shfl_xor_sync(0xFFFFFFFFu, ss, o);
    }
    float m = fmaxf(sq, ss);
    float e0 = expf(sq - m), e1 = expf(ss - m);
    float inv = 1.f / (e0 + e1);
    float a0 = e0 * inv, a1 = e1 * inv;

    const float4* pt1 = (const float4*)(t1 + (size_t)warp * FF);
    const float4* pt2 = (const float4*)(t2 + (size_t)warp * FF);
    const float4* pgl = (const float4*)(Gql + (size_t)b * FF);
    const float4* pgr = (const float4*)(Gqr + (size_t)b * FF);
    float4* ogl = (float4*)(hl + (size_t)warp * FF);
    float4* ogr = (float4*)(hs + (size_t)warp * FF);
#pragma unroll
    for (int i = 0; i < 6; i++) {
        int j = lane + i * 32;
        float4 u = pt1[j], g = pgl[j];
        ogl[j] = make_float4(a0 * g.x + a1 * u.x, a0 * g.y + a1 * u.y,
                             a0 * g.z + a1 * u.z, a0 * g.w + a1 * u.w);
        float4 v = pt2[j], h = pgr[j];
        ogr[j] = make_float4(a0 * h.x + a1 * v.x, a0 * h.y + a1 * v.y,
                             a0 * h.z + a1 * v.z, a0 * h.w + a1 * v.w);
    }
}

// ---------------- edge logits (one warp per edge) -----------------------------
__global__ void edge_logit_kernel(const float* __restrict__ gl,
                                  const float* __restrict__ gr,
                                  const float* __restrict__ ge,
                                  const int* __restrict__ xcoo,
                                  const float* __restrict__ att,
                                  float* __restrict__ logit) {
    int warp = (blockIdx.x * blockDim.x + threadIdx.x) >> 5;
    int lane = threadIdx.x & 31;
    if (warp >= NE) return;
    int src = xcoo[warp * 3 + 0];
    int rel = xcoo[warp * 3 + 1];
    int tgt = xcoo[warp * 3 + 2];
    const float4* pt = (const float4*)(gl + (size_t)tgt * FF);
    const float4* ps = (const float4*)(gr + (size_t)src * FF);
    const float4* pe = (const float4*)(ge + (size_t)rel * FF);
    const float4* pa = (const float4*)att;
    float s = 0.f;
#pragma unroll
    for (int i = 0; i < 6; i++) {
        int j = lane + i * 32;
        float4 t = pt[j], r = ps[j], e = pe[j], a = pa[j];
        s += lrelu(t.x + r.x + e.x) * a.x + lrelu(t.y + r.y + e.y) * a.y +
             lrelu(t.z + r.z + e.z) * a.z + lrelu(t.w + r.w + e.w) * a.w;
    }
#pragma unroll
    for (int o = 16; o > 0; o >>= 1) s += __shfl_xor_sync(0xFFFFFFFFu, s, o);
    if (lane == 0) logit[warp] = s;
}

// ---------------- segment softmax over edges (tgt) ----------------------------
__global__ void edge_max_kernel(const int* __restrict__ xcoo,
                                const float* __restrict__ logit,
                                unsigned* __restrict__ nmax) {
    int e = blockIdx.x * blockDim.x + threadIdx.x;
    if (e < NE) atomicMax(&nmax[xcoo[e * 3 + 2]], f2ord(logit[e]));
}

__global__ void edge_sum_kernel(const int* __restrict__ xcoo,
                                const float* __restrict__ logit,
                                const unsigned* __restrict__ nmax,
                                float* __restrict__ nsum) {
    int e = blockIdx.x * blockDim.x + threadIdx.x;
    if (e < NE) {
        int t = xcoo[e * 3 + 2];
        atomicAdd(&nsum[t], expf(logit[e] - ord2f(nmax[t])));
    }
}

// ---------------- message scatter (one warp per edge, red.v4) -----------------
__global__ void message_kernel(const int* __restrict__ xcoo,
                               const float* __restrict__ logit,
                               const unsigned* __restrict__ nmax,
                               const float* __restrict__ nsum,
                               const float* __restrict__ gr,
                               float* __restrict__ acc) {
    int warp = (blockIdx.x * blockDim.x + threadIdx.x) >> 5;
    int lane = threadIdx.x & 31;
    if (warp >= NE) return;
    int src = xcoo[warp * 3 + 0];
    int tgt = xcoo[warp * 3 + 2];
    float alpha = expf(logit[warp] - ord2f(nmax[tgt])) / (nsum[tgt] + 1e-16f);
    const float4* ps = (const float4*)(gr + (size_t)src * FF);
    float* pd = acc + (size_t)tgt * FF;
#pragma unroll
    for (int i = 0; i < 6; i++) {
        int j = lane + i * 32;
        float4 v = ps[j];
        red_v4(pd + j * 4, alpha * v.x, alpha * v.y, alpha * v.z, alpha * v.w);
    }
}

// ---------------- elu + gate dot (one warp per node, in-place) ----------------
__global__ void node_post_kernel(float* __restrict__ emb,
                                 const float* __restrict__ gate_W,
                                 const float* __restrict__ gate_b,
                                 float* __restrict__ gate) {
    int warp = (blockIdx.x * blockDim.x + threadIdx.x) >> 5;
    int lane = threadIdx.x & 31;
    if (warp >= NN) return;
    float4* p = (float4*)(emb + (size_t)warp * FF);
    const float4* pw = (const float4*)gate_W;
    float s = 0.f;
#pragma unroll
    for (int i = 0; i < 6; i++) {
        int j = lane + i * 32;
        float4 v = p[j];
        v.x = v.x > 0.f ? v.x : expm1f(v.x);
        v.y = v.y > 0.f ? v.y : expm1f(v.y);
        v.z = v.z > 0.f ? v.z : expm1f(v.z);
        v.w = v.w > 0.f ? v.w : expm1f(v.w);
        p[j] = v;
        float4 w = pw[j];
        s += v.x * w.x + v.y * w.y + v.z * w.z + v.w * w.w;
    }
#pragma unroll
    for (int o = 16; o > 0; o >>= 1) s += __shfl_xor_sync(0xFFFFFFFFu, s, o);
    if (lane == 0) gate[warp] = s + gate_b[0];
}

// ---------------- graph softmax over nodes ------------------------------------
__global__ void graph_max_kernel(const float* __restrict__ gate,
                                 const int* __restrict__ batch,
                                 unsigned* __restrict__ gmax) {
    int n = blockIdx.x * blockDim.x + threadIdx.x;
    if (n < NN) atomicMax(&gmax[batch[n]], f2ord(gate[n]));
}

__global__ void graph_sum_kernel(float* __restrict__ gate,
                                 const int* __restrict__ batch,
                                 const unsigned* __restrict__ gmax,
                                 float* __restrict__ gsum) {
    int n = blockIdx.x * blockDim.x + threadIdx.x;
    if (n < NN) {
        float ex = expf(gate[n] - ord2f(gmax[batch[n]]));
        gate[n] = ex;
        atomicAdd(&gsum[batch[n]], ex);
    }
}

__global__ void gscale_kernel(float* __restrict__ gate,
                              const int* __restrict__ batch,
                              const float* __restrict__ gsum) {
    int n = blockIdx.x * blockDim.x + threadIdx.x;
    if (n < NN) gate[n] = gate[n] / (gsum[batch[n]] + 1e-16f);
}

// ---------------- pooled = segment_sum(g * emb, batch) (batch is sorted) ------
__global__ void pool_kernel(const float* __restrict__ emb,
                            const float* __restrict__ g,
                            const int* __restrict__ batch,
                            float* __restrict__ pool) {
    int f = blockIdx.y * 256 + threadIdx.x;
    int n0 = blockIdx.x * 1024;
    int n1 = min(n0 + 1024, NN);
    float acc = 0.f;
    int curb = batch[n0];
    for (int n = n0; n < n1; n++) {
        int b = batch[n];
        if (b != curb) {
            atomicAdd(&pool[(size_t)curb * FF + f], acc);
            acc = 0.f;
            curb = b;
        }
        acc += g[n] * emb[(size_t)n * FF + f];
    }
    atomicAdd(&pool[(size_t)curb * FF + f], acc);
}

// ---------------- init kernels ------------------------------------------------
__global__ void init_node_kernel(unsigned* nmax, float* nsum, unsigned* gmax,
                                 float* gsum, float* pool) {
    int i = blockIdx.x * blockDim.x + threadIdx.x;
    if (i < NN) {
        nmax[i] = ENC_NEG_INF;
        nsum[i] = 0.f;
    }
    if (i < NB) {
        gmax[i] = ENC_NEG_INF;
        gsum[i] = 0.f;
    }
    if (i < NB * FF) pool[i] = 0.f;
}

__global__ void zero_kernel(float4* p, int n4) {
    int i = blockIdx.x * blockDim.x + threadIdx.x;
    if (i < n4) p[i] = make_float4(0.f, 0.f, 0.f, 0.f);
}

// ---------------- launcher ------------------------------------------------------
extern "C" void kernel_launch(void* const* d_in, const int* in_sizes, int n_in,
                              void* d_out, int out_size) {
    const float* queries = (const float*)d_in[0];
    const float* entities = (const float*)d_in[1];
    const float* relations = (const float*)d_in[2];
    const int* xcoo = (const int*)d_in[3];
    const int* batch = (const int*)d_in[4];
    const float* inj_Wl = (const float*)d_in[5];
    const float* inj_Wr = (const float*)d_in[6];
    const float* inj_att = (const float*)d_in[7];
    const float* enc_Wl = (const float*)d_in[8];
    const float* enc_Wr = (const float*)d_in[9];
    const float* enc_We = (const float*)d_in[10];
    const float* enc_att = (const float*)d_in[11];
    /* d_in[12] enc_Wrel: dead code in reference */
    const float* gate_W = (const float*)d_in[13];
    const float* gate_b = (const float*)d_in[14];
    const float* vt_W = (const float*)d_in[15];
    float* out = (float*)d_out;

    float *big0, *big1, *big2, *big3, *P1, *P2, *hq, *Gql, *Gqr, *ge, *logit, *nsum,
        *gate, *gsum, *pool;
    __half *Ahf, *Bhf;
    unsigned *nmax, *gmax;
    cudaGetSymbolAddress((void**)&big0, g_big0);
    cudaGetSymbolAddress((void**)&big1, g_big1);
    cudaGetSymbolAddress((void**)&big2, g_big2);
    cudaGetSymbolAddress((void**)&big3, g_big3);
    cudaGetSymbolAddress((void**)&Ahf, g_Ahf);
    cudaGetSymbolAddress((void**)&Bhf, g_Bhf);
    cudaGetSymbolAddress((void**)&P1, g_P1);
    cudaGetSymbolAddress((void**)&P2, g_P2);
    cudaGetSymbolAddress((void**)&hq, g_hq);
    cudaGetSymbolAddress((void**)&Gql, g_Gql);
    cudaGetSymbolAddress((void**)&Gqr, g_Gqr);
    cudaGetSymbolAddress((void**)&ge, g_ge);
    cudaGetSymbolAddress((void**)&logit, g_logit);
    cudaGetSymbolAddress((void**)&nmax, g_nmax);
    cudaGetSymbolAddress((void**)&nsum, g_nsum);
    cudaGetSymbolAddress((void**)&gate, g_gate);
    cudaGetSymbolAddress((void**)&gmax, g_gmax);
    cudaGetSymbolAddress((void**)&gsum, g_gsum);
    cudaGetSymbolAddress((void**)&pool, g_pool);

    cudaFuncSetAttribute(gemm_mega, cudaFuncAttributeMaxDynamicSharedMemorySize,
                         NSTAGE * GSTG);

    // ---- prep: fp16 entities ----
    cvtA_kernel<<<(NN * FF / 4 + 255) / 256, 256>>>((const float4*)entities,
                                                    (uint2*)Ahf, NN * FF / 4);

    // ---- P1 = inj_Wr @ enc_Wl, P2 = inj_Wr @ enc_Wr (fp32 split-K) ----
    zero_kernel<<<(FF * FF / 4 + 255) / 256, 256>>>((float4*)P1, FF * FF / 4);
    zero_kernel<<<(FF * FF / 4 + 255) / 256, 256>>>((float4*)P2, FF * FF / 4);
    smallgemm<<<dim3(FF / 64, FF / SGK, FF / 64), 256>>>(inj_Wr, enc_Wl, P1, FF, FF, FF);
    smallgemm<<<dim3(FF / 64, FF / SGK, FF / 64), 256>>>(inj_Wr, enc_Wr, P2, FF, FF, FF);

    // ---- hq = queries @ inj_Wr; Gql = hq @ enc_Wl; Gqr = hq @ enc_Wr ----
    zero_kernel<<<(NB * FF / 4 + 255) / 256, 256>>>((float4*)hq, NB * FF / 4);
    smallgemm<<<dim3(FF / 64, FF / SGK, 1), 256>>>(queries, inj_Wr, hq, NB, FF, FF);
    zero_kernel<<<(NB * FF / 4 + 255) / 256, 256>>>((float4*)Gql, NB * FF / 4);
    zero_kernel<<<(NB * FF / 4 + 255) / 256, 256>>>((float4*)Gqr, NB * FF / 4);
    smallgemm<<<dim3(FF / 64, FF / SGK, 1), 256>>>(hq, enc_Wl, Gql, NB, FF, FF);
    smallgemm<<<dim3(FF / 64, FF / SGK, 1), 256>>>(hq, enc_Wr, Gqr, NB, FF, FF);

    // ---- ge = relations @ enc_We ----
    zero_kernel<<<(NRL * FF / 4 + 255) / 256, 256>>>((float4*)ge, NRL * FF / 4);
    smallgemm<<<dim3(FF / 64, FF / SGK, (NRL + 63) / 64), 256>>>(relations, enc_We, ge,
                                                                 NRL, FF, FF);

    // ---- fused mega weights [Wl | Wr | P1 | P2] -> Bt fp16 ----
    wmegaT_kernel<<<dim3(FF / 32, NMEGA / 32), dim3(32, 8)>>>(inj_Wl, inj_Wr, P1, P2,
                                                              Bhf);

    // ---- mega GEMM: fp16(E) @ Bt^T -> hl, hs, t1, t2 ----
    gemm_mega<<<dim3(NMEGA / 256, (NN + 127) / 128), 256, NSTAGE * GSTG>>>(
        Ahf, Bhf, big0, big1, big2, big3, NN);

    // ---- injection attention + encoder-input assembly ----
    combine2_kernel<<<(NN * 32 + 255) / 256, 256>>>(big0, big1, big2, big3, hq, Gql,
                                                    Gqr, batch, inj_att);

    edge_logit_kernel<<<(NE * 32 + 255) / 256, 256>>>(big0, big1, ge, xcoo, enc_att,
                                                      logit);

    init_node_kernel<<<(NN + 255) / 256, 256>>>(nmax, nsum, gmax, gsum, pool);
    zero_kernel<<<(NN * FF / 4 + 255) / 256, 256>>>((float4*)big2, NN * FF / 4);

    edge_max_kernel<<<(NE + 255) / 256, 256>>>(xcoo, logit, nmax);
    edge_sum_kernel<<<(NE + 255) / 256, 256>>>(xcoo, logit, nmax, nsum);
    message_kernel<<<(NE * 32 + 255) / 256, 256>>>(xcoo, logit, nmax, nsum, big1, big2);

    node_post_kernel<<<(NN * 32 + 255) / 256, 256>>>(big2, gate_W, gate_b, gate);

    graph_max_kernel<<<(NN + 255) / 256, 256>>>(gate, batch, gmax);
    graph_sum_kernel<<<(NN + 255) / 256, 256>>>(gate, batch, gmax, gsum);
    gscale_kernel<<<(NN + 255) / 256, 256>>>(gate, batch, gsum);

    pool_kernel<<<dim3((NN + 1023) / 1024, 3), 256>>>(big2, gate, batch, pool);

    // out = pooled @ vt_W  [64,768]x[768,2304]
    zero_kernel<<<(NB * FV / 4 + 255) / 256, 256>>>((float4*)out, NB * FV / 4);
    smallgemm<<<dim3(FV / 64, FF / SGK, 1), 256>>>(pool, vt_W, out, NB, FV, FF);
}

// round 8
// speedup vs baseline: 3.8356x; 1.0814x over previous
#include <cuda_runtime.h>
#include <cuda_fp16.h>
#include <math.h>
#include <stdint.h>

#define NN 50000
#define NE 100000
#define NRL 500
#define NB 64
#define FF 768
#define FV 2304
#define NMEGA (4 * FF)  // 3072
#define ENC_NEG_INF 0x007FFFFFu

// ---------------- scratch (static device memory; no allocations) ------------
__device__ __align__(16) float g_big0[NN * FF];   // hl -> gl
__device__ __align__(16) float g_big1[NN * FF];   // hs -> gr
__device__ __align__(16) float g_big2[NN * FF];   // t1 -> msg accum / ent_emb
__device__ __align__(16) float g_big3[NN * FF];   // t2
__device__ __align__(16) __half g_Ahf[NN * FF];   // fp16 entities
__device__ __align__(16) __half g_Bhf[NMEGA * FF];  // [3072,768] fused W^T fp16
__device__ __align__(16) float g_P1[FF * FF];
__device__ __align__(16) float g_P2[FF * FF];
__device__ __align__(16) float g_hq[NB * FF];
__device__ __align__(16) float g_Gql[NB * FF];
__device__ __align__(16) float g_Gqr[NB * FF];
__device__ __align__(16) float g_ge[NRL * FF];
__device__ float g_logit[NE];
__device__ unsigned g_nmax[NN];
__device__ float g_nsum[NN];
__device__ float g_gate[NN];
__device__ unsigned g_gmax[NB];
__device__ float g_gsum[NB];
__device__ __align__(16) float g_pool[NB * FF];

// ---------------- helpers ----------------------------------------------------
__device__ __forceinline__ float lrelu(float x) { return x > 0.f ? x : 0.2f * x; }

__device__ __forceinline__ unsigned f2ord(float f) {
    unsigned u = __float_as_uint(f);
    return (u & 0x80000000u) ? ~u : (u | 0x80000000u);
}
__device__ __forceinline__ float ord2f(unsigned u) {
    return (u & 0x80000000u) ? __uint_as_float(u & 0x7FFFFFFFu) : __uint_as_float(~u);
}

__device__ __forceinline__ unsigned cat_h(__half a, __half b) {
    return (unsigned)__half_as_ushort(a) | ((unsigned)__half_as_ushort(b) << 16);
}

__device__ __forceinline__ uint32_t smem_u32(const void* p) {
    uint32_t a;
    asm("{ .reg .u64 t; cvta.to.shared.u64 t, %1; cvt.u32.u64 %0, t; }" : "=r"(a) : "l"(p));
    return a;
}

__device__ __forceinline__ void ldsm4(unsigned* r, uint32_t addr) {
    asm volatile("ldmatrix.sync.aligned.m8n8.x4.shared.b16 {%0,%1,%2,%3}, [%4];"
                 : "=r"(r[0]), "=r"(r[1]), "=r"(r[2]), "=r"(r[3]) : "r"(addr));
}

__device__ __forceinline__ void mma_f16(float* d, const unsigned* a, unsigned b0,
                                        unsigned b1) {
    asm volatile(
        "mma.sync.aligned.m16n8k16.row.col.f32.f16.f16.f32 "
        "{%0,%1,%2,%3}, {%4,%5,%6,%7}, {%8,%9}, {%0,%1,%2,%3};"
        : "+f"(d[0]), "+f"(d[1]), "+f"(d[2]), "+f"(d[3])
        : "r"(a[0]), "r"(a[1]), "r"(a[2]), "r"(a[3]), "r"(b0), "r"(b1));
}

__device__ __forceinline__ void red_v4(float* p, float a, float b, float c, float d) {
    asm volatile("red.global.add.v4.f32 [%0], {%1,%2,%3,%4};"
                 :: "l"(p), "f"(a), "f"(b), "f"(c), "f"(d) : "memory");
}

// ---------------- fp16 mega GEMM -----------------------------------------------
// [hl|hs|t1|t2][M,768 each] = fp16(A)[M,768] * Bt^T, Bt=[3072,768] fp16.
// Block 128x128, warp tile 64x32 (2x4 warps), BK=64, 3 stages, 2 CTAs/SM.
// smem stage: A[0,18432) B[18432,36864), row stride 144B (64 halves + pad)
#define GRS 144
#define G_ATILE 18432
#define GSTG 36864
#define NSTAGE 3
#define NCHUNK 12

__global__ __launch_bounds__(256, 2)
void gemm_mega(const __half* __restrict__ Ah, const __half* __restrict__ Bh,
               float* __restrict__ o0, float* __restrict__ o1,
               float* __restrict__ o2, float* __restrict__ o3, int M) {
    extern __shared__ char smem[];
    const uint32_t sbase = smem_u32(smem);
    const int tid = threadIdx.x;
    const int lane = tid & 31;
    const int wid = tid >> 5;
    const int wm = wid >> 2;   // 0..1
    const int wn = wid & 3;    // 0..3
    const int m0 = blockIdx.y * 128;
    const int n0 = blockIdx.x * 128;

    auto load_stage = [&](int stg, int k0) {
        uint32_t sb = sbase + stg * GSTG;
#pragma unroll
        for (int t = 0; t < 8; t++) {
            int idx = tid + t * 256;
            int r = (idx >> 3) & 127;
            int c = idx & 7;
            uint32_t dst;
            const __half* g;
            int sz = 16;
            if (idx < 1024) {  // A: 128 rows x 8 cols of 16B
                dst = sb + r * GRS + c * 16;
                int row = m0 + r;
                if (row >= M) { row = 0; sz = 0; }
                g = Ah + (size_t)row * FF + k0 + c * 8;
            } else {           // B: 128 rows x 8 cols of 16B
                dst = sb + G_ATILE + r * GRS + c * 16;
                g = Bh + (size_t)(n0 + r) * FF + k0 + c * 8;
            }
            asm volatile("cp.async.cg.shared.global [%0], [%1], 16, %2;"
                         :: "r"(dst), "l"(g), "r"(sz));
        }
        asm volatile("cp.async.commit_group;" ::: "memory");
    };

    float acc[4][4][4];
#pragma unroll
    for (int i = 0; i < 4; i++)
#pragma unroll
        for (int t = 0; t < 4; t++)
#pragma unroll
            for (int q = 0; q < 4; q++) acc[i][t][q] = 0.f;

    const int fr = lane & 15;
    const int fko = (lane >> 4) * 16;

    load_stage(0, 0);
    load_stage(1, 64);

#pragma unroll 1
    for (int ch = 0; ch < NCHUNK; ch++) {
        if (ch < NCHUNK - 1)
            asm volatile("cp.async.wait_group 1;" ::: "memory");
        else
            asm volatile("cp.async.wait_group 0;" ::: "memory");
        __syncthreads();
        if (ch + 2 < NCHUNK) load_stage((ch + 2) % NSTAGE, (ch + 2) * 64);

        const uint32_t sb = sbase + (ch % NSTAGE) * GSTG;
#pragma unroll
        for (int ks = 0; ks < 4; ks++) {
            unsigned ah[4][4], bh[2][4];
            const uint32_t ko = (uint32_t)(ks * 32 + fko);
#pragma unroll
            for (int i = 0; i < 4; i++) {
                uint32_t ra = sb + (uint32_t)((wm * 64 + i * 16 + fr) * GRS) + ko;
                ldsm4(ah[i], ra);
            }
#pragma unroll
            for (int j = 0; j < 2; j++) {
                uint32_t rb = sb + G_ATILE + (uint32_t)((wn * 32 + j * 16 + fr) * GRS) + ko;
                ldsm4(bh[j], rb);
            }
#pragma unroll
            for (int i = 0; i < 4; i++) {
#pragma unroll
                for (int j = 0; j < 2; j++) {
#pragma unroll
                    for (int s = 0; s < 2; s++) {
                        mma_f16(acc[i][j * 2 + s], ah[i], bh[j][s], bh[j][s + 2]);
                    }
                }
            }
        }
        __syncthreads();
    }

    // epilogue: stream = blockIdx.x / 6 (6 column tiles of 128 per 768-wide stream)
    const int str = blockIdx.x / 6;
    float* Cb = (str == 0) ? o0 : (str == 1) ? o1 : (str == 2) ? o2 : o3;
    const int nbase = (blockIdx.x % 6) * 128 + wn * 32;
#pragma unroll
    for (int i = 0; i < 4; i++) {
        const int r0 = m0 + wm * 64 + i * 16 + (lane >> 2);
#pragma unroll
        for (int t = 0; t < 4; t++) {
            const int col = nbase + t * 8 + (lane & 3) * 2;
            if (r0 < M)
                *(float2*)(Cb + (size_t)r0 * FF + col) =
                    make_float2(acc[i][t][0], acc[i][t][1]);
            if (r0 + 8 < M)
                *(float2*)(Cb + (size_t)(r0 + 8) * FF + col) =
                    make_float2(acc[i][t][2], acc[i][t][3]);
        }
    }
}

// ---------------- split-K small GEMM: C[M,N] += A[M,K] * B[K,N] -----------------
#define SGK 128
__global__ __launch_bounds__(256) void smallgemm(const float* __restrict__ A,
                                                 const float* __restrict__ B,
                                                 float* __restrict__ C,
                                                 int M, int N, int K) {
    __shared__ float As[32][68];
    __shared__ float Bs[32][64];
    const int tid = threadIdx.x;
    const int n0 = blockIdx.x * 64;
    const int k0 = blockIdx.y * SGK;
    const int m0 = blockIdx.z * 64;
    const int tx = tid & 15, ty = tid >> 4;
    float acc[4][4] = {};

    for (int kt = 0; kt < SGK; kt += 32) {
        __syncthreads();
#pragma unroll
        for (int i = 0; i < 2; i++) {
            int idx = tid + i * 256;
            int r = idx >> 3, c = (idx & 7) * 4;
            float4 v = (m0 + r < M)
                           ? *(const float4*)(A + (size_t)(m0 + r) * K + k0 + kt + c)
                           : make_float4(0.f, 0.f, 0.f, 0.f);
            As[c + 0][r] = v.x;
            As[c + 1][r] = v.y;
            As[c + 2][r] = v.z;
            As[c + 3][r] = v.w;
            int rb = idx >> 4, cb = (idx & 15) * 4;
            *(float4*)&Bs[rb][cb] =
                *(const float4*)(B + (size_t)(k0 + kt + rb) * N + n0 + cb);
        }
        __syncthreads();
#pragma unroll
        for (int kk = 0; kk < 32; kk++) {
            float a0 = As[kk][ty * 4 + 0], a1 = As[kk][ty * 4 + 1];
            float a2 = As[kk][ty * 4 + 2], a3 = As[kk][ty * 4 + 3];
            float4 b = *(float4*)&Bs[kk][tx * 4];
            acc[0][0] += a0 * b.x; acc[0][1] += a0 * b.y; acc[0][2] += a0 * b.z; acc[0][3] += a0 * b.w;
            acc[1][0] += a1 * b.x; acc[1][1] += a1 * b.y; acc[1][2] += a1 * b.z; acc[1][3] += a1 * b.w;
            acc[2][0] += a2 * b.x; acc[2][1] += a2 * b.y; acc[2][2] += a2 * b.z; acc[2][3] += a2 * b.w;
            acc[3][0] += a3 * b.x; acc[3][1] += a3 * b.y; acc[3][2] += a3 * b.z; acc[3][3] += a3 * b.w;
        }
    }
#pragma unroll
    for (int i = 0; i < 4; i++) {
        int r = m0 + ty * 4 + i;
        if (r < M)
            red_v4(C + (size_t)r * N + n0 + tx * 4, acc[i][0], acc[i][1], acc[i][2],
                   acc[i][3]);
    }
}

// ---------------- prep: convert entities to fp16 --------------------------------
__global__ void cvtA_kernel(const float4* __restrict__ in, uint2* __restrict__ hi,
                            int n4) {
    int i = blockIdx.x * blockDim.x + threadIdx.x;
    if (i >= n4) return;
    float4 v = in[i];
    hi[i] = make_uint2(cat_h(__float2half_rn(v.x), __float2half_rn(v.y)),
                       cat_h(__float2half_rn(v.z), __float2half_rn(v.w)));
}

// ---------------- prep: transpose + fp16 of fused mega weights -----------------
__global__ void wmegaT_kernel(const float* __restrict__ Wl, const float* __restrict__ Wr,
                              const float* __restrict__ P1, const float* __restrict__ P2,
                              __half* __restrict__ Bh) {
    __shared__ float t[32][33];
    const int k0 = blockIdx.x * 32;
    const int n0g = blockIdx.y * 32;
    const int sel = n0g / FF;
    const float* W = (sel == 0) ? Wl : (sel == 1) ? Wr : (sel == 2) ? P1 : P2;
    const int n0 = n0g - sel * FF;
    const int tx = threadIdx.x, ty = threadIdx.y;
#pragma unroll
    for (int i = 0; i < 4; i++)
        t[ty + i * 8][tx] = W[(size_t)(k0 + ty + i * 8) * FF + n0 + tx];
    __syncthreads();
#pragma unroll
    for (int i = 0; i < 4; i++)
        Bh[(size_t)(n0g + ty + i * 8) * FF + k0 + tx] = __float2half_rn(t[tx][ty + i * 8]);
}

// ---------------- fused injection attention + encoder-input assembly ----------
__global__ void combine2_kernel(float* __restrict__ hl,        // in: hl, out: gl
                                float* __restrict__ hs,        // in: hs, out: gr
                                const float* __restrict__ t1,
                                const float* __restrict__ t2,
                                const float* __restrict__ hqg,
                                const float* __restrict__ Gql,
                                const float* __restrict__ Gqr,
                                const int* __restrict__ batch,
                                const float* __restrict__ att) {
    int warp = (blockIdx.x * blockDim.x + threadIdx.x) >> 5;
    int lane = threadIdx.x & 31;
    if (warp >= NN) return;
    const int b = batch[warp];
    const float4* phl = (const float4*)(hl + (size_t)warp * FF);
    const float4* phs = (const float4*)(hs + (size_t)warp * FF);
    const float4* phq = (const float4*)(hqg + (size_t)b * FF);
    const float4* pat = (const float4*)att;

    float sq = 0.f, ss = 0.f;
#pragma unroll
    for (int i = 0; i < 6; i++) {
        int j = lane + i * 32;
        float4 l = phl[j], q = phq[j], s = phs[j], a = pat[j];
        sq += lrelu(l.x + q.x) * a.x + lrelu(l.y + q.y) * a.y +
              lrelu(l.z + q.z) * a.z + lrelu(l.w + q.w) * a.w;
        ss += lrelu(l.x + s.x) * a.x + lrelu(l.y + s.y) * a.y +
              lrelu(l.z + s.z) * a.z + lrelu(l.w + s.w) * a.w;
    }
#pragma unroll
    for (int o = 16; o > 0; o >>= 1) {
        sq += __shfl_xor_sync(0xFFFFFFFFu, sq, o);
        ss += __shfl_xor_sync(0xFFFFFFFFu, ss, o);
    }
    float m = fmaxf(sq, ss);
    float e0 = expf(sq - m), e1 = expf(ss - m);
    float inv = 1.f / (e0 + e1);
    float a0 = e0 * inv, a1 = e1 * inv;

    const float4* pt1 = (const float4*)(t1 + (size_t)warp * FF);
    const float4* pt2 = (const float4*)(t2 + (size_t)warp * FF);
    const float4* pgl = (const float4*)(Gql + (size_t)b * FF);
    const float4* pgr = (const float4*)(Gqr + (size_t)b * FF);
    float4* ogl = (float4*)(hl + (size_t)warp * FF);
    float4* ogr = (float4*)(hs + (size_t)warp * FF);
#pragma unroll
    for (int i = 0; i < 6; i++) {
        int j = lane + i * 32;
        float4 u = pt1[j], g = pgl[j];
        ogl[j] = make_float4(a0 * g.x + a1 * u.x, a0 * g.y + a1 * u.y,
                             a0 * g.z + a1 * u.z, a0 * g.w + a1 * u.w);
        float4 v = pt2[j], h = pgr[j];
        ogr[j] = make_float4(a0 * h.x + a1 * v.x, a0 * h.y + a1 * v.y,
                             a0 * h.z + a1 * v.z, a0 * h.w + a1 * v.w);
    }
}

// ---------------- edge logits (one warp per edge) -----------------------------
__global__ void edge_logit_kernel(const float* __restrict__ gl,
                                  const float* __restrict__ gr,
                                  const float* __restrict__ ge,
                                  const int* __restrict__ xcoo,
                                  const float* __restrict__ att,
                                  float* __restrict__ logit) {
    int warp = (blockIdx.x * blockDim.x + threadIdx.x) >> 5;
    int lane = threadIdx.x & 31;
    if (warp >= NE) return;
    int src = xcoo[warp * 3 + 0];
    int rel = xcoo[warp * 3 + 1];
    int tgt = xcoo[warp * 3 + 2];
    const float4* pt = (const float4*)(gl + (size_t)tgt * FF);
    const float4* ps = (const float4*)(gr + (size_t)src * FF);
    const float4* pe = (const float4*)(ge + (size_t)rel * FF);
    const float4* pa = (const float4*)att;
    float s = 0.f;
#pragma unroll
    for (int i = 0; i < 6; i++) {
        int j = lane + i * 32;
        float4 t = pt[j], r = ps[j], e = pe[j], a = pa[j];
        s += lrelu(t.x + r.x + e.x) * a.x + lrelu(t.y + r.y + e.y) * a.y +
             lrelu(t.z + r.z + e.z) * a.z + lrelu(t.w + r.w + e.w) * a.w;
    }
#pragma unroll
    for (int o = 16; o > 0; o >>= 1) s += __shfl_xor_sync(0xFFFFFFFFu, s, o);
    if (lane == 0) logit[warp] = s;
}

// ---------------- segment softmax over edges (tgt) ----------------------------
__global__ void edge_max_kernel(const int* __restrict__ xcoo,
                                const float* __restrict__ logit,
                                unsigned* __restrict__ nmax) {
    int e = blockIdx.x * blockDim.x + threadIdx.x;
    if (e < NE) atomicMax(&nmax[xcoo[e * 3 + 2]], f2ord(logit[e]));
}

__global__ void edge_sum_kernel(const int* __restrict__ xcoo,
                                const float* __restrict__ logit,
                                const unsigned* __restrict__ nmax,
                                float* __restrict__ nsum) {
    int e = blockIdx.x * blockDim.x + threadIdx.x;
    if (e < NE) {
        int t = xcoo[e * 3 + 2];
        atomicAdd(&nsum[t], expf(logit[e] - ord2f(nmax[t])));
    }
}

// ---------------- message scatter (one warp per edge, red.v4) -----------------
__global__ void message_kernel(const int* __restrict__ xcoo,
                               const float* __restrict__ logit,
                               const unsigned* __restrict__ nmax,
                               const float* __restrict__ nsum,
                               const float* __restrict__ gr,
                               float* __restrict__ acc) {
    int warp = (blockIdx.x * blockDim.x + threadIdx.x) >> 5;
    int lane = threadIdx.x & 31;
    if (warp >= NE) return;
    int src = xcoo[warp * 3 + 0];
    int tgt = xcoo[warp * 3 + 2];
    float alpha = expf(logit[warp] - ord2f(nmax[tgt])) / (nsum[tgt] + 1e-16f);
    const float4* ps = (const float4*)(gr + (size_t)src * FF);
    float* pd = acc + (size_t)tgt * FF;
#pragma unroll
    for (int i = 0; i < 6; i++) {
        int j = lane + i * 32;
        float4 v = ps[j];
        red_v4(pd + j * 4, alpha * v.x, alpha * v.y, alpha * v.z, alpha * v.w);
    }
}

// ---------------- elu + gate dot (one warp per node, in-place) ----------------
__global__ void node_post_kernel(float* __restrict__ emb,
                                 const float* __restrict__ gate_W,
                                 const float* __restrict__ gate_b,
                                 float* __restrict__ gate) {
    int warp = (blockIdx.x * blockDim.x + threadIdx.x) >> 5;
    int lane = threadIdx.x & 31;
    if (warp >= NN) return;
    float4* p = (float4*)(emb + (size_t)warp * FF);
    const float4* pw = (const float4*)gate_W;
    float s = 0.f;
#pragma unroll
    for (int i = 0; i < 6; i++) {
        int j = lane + i * 32;
        float4 v = p[j];
        v.x = v.x > 0.f ? v.x : expm1f(v.x);
        v.y = v.y > 0.f ? v.y : expm1f(v.y);
        v.z = v.z > 0.f ? v.z : expm1f(v.z);
        v.w = v.w > 0.f ? v.w : expm1f(v.w);
        p[j] = v;
        float4 w = pw[j];
        s += v.x * w.x + v.y * w.y + v.z * w.z + v.w * w.w;
    }
#pragma unroll
    for (int o = 16; o > 0; o >>= 1) s += __shfl_xor_sync(0xFFFFFFFFu, s, o);
    if (lane == 0) gate[warp] = s + gate_b[0];
}

// ---------------- graph softmax over nodes ------------------------------------
__global__ void graph_max_kernel(const float* __restrict__ gate,
                                 const int* __restrict__ batch,
                                 unsigned* __restrict__ gmax) {
    int n = blockIdx.x * blockDim.x + threadIdx.x;
    if (n < NN) atomicMax(&gmax[batch[n]], f2ord(gate[n]));
}

__global__ void graph_sum_kernel(float* __restrict__ gate,
                                 const int* __restrict__ batch,
                                 const unsigned* __restrict__ gmax,
                                 float* __restrict__ gsum) {
    int n = blockIdx.x * blockDim.x + threadIdx.x;
    if (n < NN) {
        float ex = expf(gate[n] - ord2f(gmax[batch[n]]));
        gate[n] = ex;
        atomicAdd(&gsum[batch[n]], ex);
    }
}

__global__ void gscale_kernel(float* __restrict__ gate,
                              const int* __restrict__ batch,
                              const float* __restrict__ gsum) {
    int n = blockIdx.x * blockDim.x + threadIdx.x;
    if (n < NN) gate[n] = gate[n] / (gsum[batch[n]] + 1e-16f);
}

// ---------------- pooled = segment_sum(g * emb, batch) (batch is sorted) ------
__global__ void pool_kernel(const float* __restrict__ emb,
                            const float* __restrict__ g,
                            const int* __restrict__ batch,
                            float* __restrict__ pool) {
    int f = blockIdx.y * 256 + threadIdx.x;
    int n0 = blockIdx.x * 1024;
    int n1 = min(n0 + 1024, NN);
    float acc = 0.f;
    int curb = batch[n0];
    for (int n = n0; n < n1; n++) {
        int b = batch[n];
        if (b != curb) {
            atomicAdd(&pool[(size_t)curb * FF + f], acc);
            acc = 0.f;
            curb = b;
        }
        acc += g[n] * emb[(size_t)n * FF + f];
    }
    atomicAdd(&pool[(size_t)curb * FF + f], acc);
}

// ---------------- init kernels ------------------------------------------------
__global__ void init_node_kernel(unsigned* nmax, float* nsum, unsigned* gmax,
                                 float* gsum, float* pool) {
    int i = blockIdx.x * blockDim.x + threadIdx.x;
    if (i < NN) {
        nmax[i] = ENC_NEG_INF;
        nsum[i] = 0.f;
    }
    if (i < NB) {
        gmax[i] = ENC_NEG_INF;
        gsum[i] = 0.f;
    }
    if (i < NB * FF) pool[i] = 0.f;
}

__global__ void zero_kernel(float4* p, int n4) {
    int i = blockIdx.x * blockDim.x + threadIdx.x;
    if (i < n4) p[i] = make_float4(0.f, 0.f, 0.f, 0.f);
}

// ---------------- launcher ------------------------------------------------------
extern "C" void kernel_launch(void* const* d_in, const int* in_sizes, int n_in,
                              void* d_out, int out_size) {
    const float* queries = (const float*)d_in[0];
    const float* entities = (const float*)d_in[1];
    const float* relations = (const float*)d_in[2];
    const int* xcoo = (const int*)d_in[3];
    const int* batch = (const int*)d_in[4];
    const float* inj_Wl = (const float*)d_in[5];
    const float* inj_Wr = (const float*)d_in[6];
    const float* inj_att = (const float*)d_in[7];
    const float* enc_Wl = (const float*)d_in[8];
    const float* enc_Wr = (const float*)d_in[9];
    const float* enc_We = (const float*)d_in[10];
    const float* enc_att = (const float*)d_in[11];
    /* d_in[12] enc_Wrel: dead code in reference */
    const float* gate_W = (const float*)d_in[13];
    const float* gate_b = (const float*)d_in[14];
    const float* vt_W = (const float*)d_in[15];
    float* out = (float*)d_out;

    float *big0, *big1, *big2, *big3, *P1, *P2, *hq, *Gql, *Gqr, *ge, *logit, *nsum,
        *gate, *gsum, *pool;
    __half *Ahf, *Bhf;
    unsigned *nmax, *gmax;
    cudaGetSymbolAddress((void**)&big0, g_big0);
    cudaGetSymbolAddress((void**)&big1, g_big1);
    cudaGetSymbolAddress((void**)&big2, g_big2);
    cudaGetSymbolAddress((void**)&big3, g_big3);
    cudaGetSymbolAddress((void**)&Ahf, g_Ahf);
    cudaGetSymbolAddress((void**)&Bhf, g_Bhf);
    cudaGetSymbolAddress((void**)&P1, g_P1);
    cudaGetSymbolAddress((void**)&P2, g_P2);
    cudaGetSymbolAddress((void**)&hq, g_hq);
    cudaGetSymbolAddress((void**)&Gql, g_Gql);
    cudaGetSymbolAddress((void**)&Gqr, g_Gqr);
    cudaGetSymbolAddress((void**)&ge, g_ge);
    cudaGetSymbolAddress((void**)&logit, g_logit);
    cudaGetSymbolAddress((void**)&nmax, g_nmax);
    cudaGetSymbolAddress((void**)&nsum, g_nsum);
    cudaGetSymbolAddress((void**)&gate, g_gate);
    cudaGetSymbolAddress((void**)&gmax, g_gmax);
    cudaGetSymbolAddress((void**)&gsum, g_gsum);
    cudaGetSymbolAddress((void**)&pool, g_pool);

    cudaFuncSetAttribute(gemm_mega, cudaFuncAttributeMaxDynamicSharedMemorySize,
                         NSTAGE * GSTG);

    // ---- prep: fp16 entities ----
    cvtA_kernel<<<(NN * FF / 4 + 255) / 256, 256>>>((const float4*)entities,
                                                    (uint2*)Ahf, NN * FF / 4);

    // ---- P1 = inj_Wr @ enc_Wl, P2 = inj_Wr @ enc_Wr (fp32 split-K) ----
    zero_kernel<<<(FF * FF / 4 + 255) / 256, 256>>>((float4*)P1, FF * FF / 4);
    zero_kernel<<<(FF * FF / 4 + 255) / 256, 256>>>((float4*)P2, FF * FF / 4);
    smallgemm<<<dim3(FF / 64, FF / SGK, FF / 64), 256>>>(inj_Wr, enc_Wl, P1, FF, FF, FF);
    smallgemm<<<dim3(FF / 64, FF / SGK, FF / 64), 256>>>(inj_Wr, enc_Wr, P2, FF, FF, FF);

    // ---- hq = queries @ inj_Wr; Gql = hq @ enc_Wl; Gqr = hq @ enc_Wr ----
    zero_kernel<<<(NB * FF / 4 + 255) / 256, 256>>>((float4*)hq, NB * FF / 4);
    smallgemm<<<dim3(FF / 64, FF / SGK, 1), 256>>>(queries, inj_Wr, hq, NB, FF, FF);
    zero_kernel<<<(NB * FF / 4 + 255) / 256, 256>>>((float4*)Gql, NB * FF / 4);
    zero_kernel<<<(NB * FF / 4 + 255) / 256, 256>>>((float4*)Gqr, NB * FF / 4);
    smallgemm<<<dim3(FF / 64, FF / SGK, 1), 256>>>(hq, enc_Wl, Gql, NB, FF, FF);
    smallgemm<<<dim3(FF / 64, FF / SGK, 1), 256>>>(hq, enc_Wr, Gqr, NB, FF, FF);

    // ---- ge = relations @ enc_We ----
    zero_kernel<<<(NRL * FF / 4 + 255) / 256, 256>>>((float4*)ge, NRL * FF / 4);
    smallgemm<<<dim3(FF / 64, FF / SGK, (NRL + 63) / 64), 256>>>(relations, enc_We, ge,
                                                                 NRL, FF, FF);

    // ---- fused mega weights [Wl | Wr | P1 | P2] -> Bt fp16 ----
    wmegaT_kernel<<<dim3(FF / 32, NMEGA / 32), dim3(32, 8)>>>(inj_Wl, inj_Wr, P1, P2,
                                                              Bhf);

    // ---- mega GEMM: fp16(E) @ Bt^T -> hl, hs, t1, t2 ----
    gemm_mega<<<dim3(NMEGA / 128, (NN + 127) / 128), 256, NSTAGE * GSTG>>>(
        Ahf, Bhf, big0, big1, big2, big3, NN);

    // ---- injection attention + encoder-input assembly ----
    combine2_kernel<<<(NN * 32 + 255) / 256, 256>>>(big0, big1, big2, big3, hq, Gql,
                                                    Gqr, batch, inj_att);

    edge_logit_kernel<<<(NE * 32 + 255) / 256, 256>>>(big0, big1, ge, xcoo, enc_att,
                                                      logit);

    init_node_kernel<<<(NN + 255) / 256, 256>>>(nmax, nsum, gmax, gsum, pool);
    zero_kernel<<<(NN * FF / 4 + 255) / 256, 256>>>((float4*)big2, NN * FF / 4);

    edge_max_kernel<<<(NE + 255) / 256, 256>>>(xcoo, logit, nmax);
    edge_sum_kernel<<<(NE + 255) / 256, 256>>>(xcoo, logit, nmax, nsum);
    message_kernel<<<(NE * 32 + 255) / 256, 256>>>(xcoo, logit, nmax, nsum, big1, big2);

    node_post_kernel<<<(NN * 32 + 255) / 256, 256>>>(big2, gate_W, gate_b, gate);

    graph_max_kernel<<<(NN + 255) / 256, 256>>>(gate, batch, gmax);
    graph_sum_kernel<<<(NN + 255) / 256, 256>>>(gate, batch, gmax, gsum);
    gscale_kernel<<<(NN + 255) / 256, 256>>>(gate, batch, gsum);

    pool_kernel<<<dim3((NN + 1023) / 1024, 3), 256>>>(big2, gate, batch, pool);

    // out = pooled @ vt_W  [64,768]x[768,2304]
    zero_kernel<<<(NB * FV / 4 + 255) / 256, 256>>>((float4*)out, NB * FV / 4);
    smallgemm<<<dim3(FV / 64, FF / SGK, 1), 256>>>(pool, vt_W, out, NB, FV, FF);
}